// round 1
// baseline (speedup 1.0000x reference)
#include <cuda_runtime.h>
#include <math.h>

// ---------------- problem constants ----------------
#define Bb   2
#define Ll   4096
#define Dd   1024
#define Hh   4
#define DKk  256
#define DVv  256
#define CSs  32
#define NCc  128          // L / CS
#define BL   (Bb*Ll)      // 8192
#define HD   1024         // H*DK = H*DV
#define GIN  1792
#define GHID 1024

// ---------------- scratch (device globals; no runtime alloc) ----------------
__device__ float g_xq[BL*HD];
__device__ float g_xk[BL*HD];
__device__ float g_xv[BL*HD];
__device__ float g_q [BL*HD];     // l2-normalized silu(conv(q)) , [b,l,h*256+d]
__device__ float g_k [BL*HD];
__device__ float g_v [BL*HD];     // silu(conv(v))
__device__ float g_u [Bb*Hh*Ll*DVv];  // chunk layout [bh][ci][i][d]
__device__ float g_w [Bb*Hh*Ll*DVv];
__device__ float g_attn[Bb*Hh*NCc*CSs*CSs];
__device__ float g_delta[BL*HD];  // [b,l,h*256+d]
__device__ float g_short[BL*HD];
__device__ float g_long [BL*HD];
__device__ float g_gin[BL*GIN];
__device__ float g_gh [BL*GHID];
__device__ float g_beta[BL*Hh];
__device__ float g_wgt [BL*4];
__device__ float g_ocomb[BL*HD];

// ---------------- helpers ----------------
__device__ __forceinline__ float siluf(float x){ return x / (1.f + expf(-x)); }
__device__ __forceinline__ float geluf(float x){ return 0.5f * x * (1.f + erff(x * 0.70710678118654752f)); }

// ---------------- SGEMM: C[M,N] = A[M,K] * B[N,K]^T (NT), optional gelu(bias) epilogue ----
template<bool EPI>
__global__ void __launch_bounds__(256) sgemm_nt(const float* __restrict__ A,
                                                const float* __restrict__ B,
                                                float* __restrict__ C,
                                                int M, int N, int K,
                                                const float* __restrict__ bias)
{
    __shared__ float As[2][8][128];
    __shared__ float Bs[2][8][128];
    const int tid = threadIdx.x;
    const int bm = blockIdx.y * 128;
    const int bn = blockIdx.x * 128;
    const int lr = tid >> 1;
    const int lc = (tid & 1) * 4;
    const float* Ab = A + (size_t)(bm + lr) * K + lc;
    const float* Bb2 = B + (size_t)(bn + lr) * K + lc;
    const int ty = tid >> 4;   // 0..15
    const int tx = tid & 15;   // 0..15

    float acc[8][8];
    #pragma unroll
    for (int i = 0; i < 8; i++)
        #pragma unroll
        for (int j = 0; j < 8; j++) acc[i][j] = 0.f;

    // prologue
    {
        float4 a4 = *(const float4*)Ab;
        float4 b4 = *(const float4*)Bb2;
        As[0][lc+0][lr]=a4.x; As[0][lc+1][lr]=a4.y; As[0][lc+2][lr]=a4.z; As[0][lc+3][lr]=a4.w;
        Bs[0][lc+0][lr]=b4.x; Bs[0][lc+1][lr]=b4.y; Bs[0][lc+2][lr]=b4.z; Bs[0][lc+3][lr]=b4.w;
    }
    __syncthreads();

    const int nk = K >> 3;
    for (int kt = 0; kt < nk; ++kt) {
        const int cur = kt & 1;
        float4 a4, b4;
        const bool more = (kt + 1 < nk);
        if (more) {
            a4 = *(const float4*)(Ab + (kt+1)*8);
            b4 = *(const float4*)(Bb2 + (kt+1)*8);
        }
        #pragma unroll
        for (int kk = 0; kk < 8; ++kk) {
            float ar[8], br[8];
            *(float4*)(ar)   = *(const float4*)&As[cur][kk][ty*8];
            *(float4*)(ar+4) = *(const float4*)&As[cur][kk][ty*8+4];
            *(float4*)(br)   = *(const float4*)&Bs[cur][kk][tx*8];
            *(float4*)(br+4) = *(const float4*)&Bs[cur][kk][tx*8+4];
            #pragma unroll
            for (int i = 0; i < 8; i++)
                #pragma unroll
                for (int j = 0; j < 8; j++)
                    acc[i][j] += ar[i] * br[j];
        }
        if (more) {
            const int nxt = cur ^ 1;
            As[nxt][lc+0][lr]=a4.x; As[nxt][lc+1][lr]=a4.y; As[nxt][lc+2][lr]=a4.z; As[nxt][lc+3][lr]=a4.w;
            Bs[nxt][lc+0][lr]=b4.x; Bs[nxt][lc+1][lr]=b4.y; Bs[nxt][lc+2][lr]=b4.z; Bs[nxt][lc+3][lr]=b4.w;
            __syncthreads();
        }
    }

    #pragma unroll
    for (int i = 0; i < 8; i++) {
        const int row = bm + ty*8 + i;
        float* crow = C + (size_t)row * N + bn + tx*8;
        #pragma unroll
        for (int j = 0; j < 8; j++) {
            float v = acc[i][j];
            if (EPI) { v += bias[bn + tx*8 + j]; v = geluf(v); }
            crow[j] = v;
        }
    }
}

// ---------------- beta = sigmoid(hs @ b_proj^T), [b,l,4] ----------------
__global__ void beta_kernel(const float* __restrict__ hs, const float* __restrict__ bw,
                            float* __restrict__ beta)
{
    const int row = blockIdx.x;
    const int warp = threadIdx.x >> 5, lane = threadIdx.x & 31;
    const float* x = hs + (size_t)row * Dd;
    const float* w = bw + warp * Dd;
    float s = 0.f;
    for (int i = lane; i < Dd; i += 32) s += x[i] * w[i];
    #pragma unroll
    for (int o = 16; o; o >>= 1) s += __shfl_xor_sync(0xffffffff, s, o);
    if (lane == 0) beta[row*4 + warp] = 1.f / (1.f + expf(-s));
}

// ---------------- causal conv(k=4) + silu + (q,k: per-head l2norm) ----------------
__global__ void conv_silu_norm(const float* __restrict__ XQ, const float* __restrict__ XK,
                               const float* __restrict__ XV,
                               const float* __restrict__ WQ, const float* __restrict__ WK,
                               const float* __restrict__ WV,
                               float* __restrict__ Qo, float* __restrict__ Ko,
                               float* __restrict__ Vo)
{
    const int row = blockIdx.x;
    const int b = row >> 12, l = row & (Ll-1);
    const int tid = threadIdx.x;
    const int lane = tid & 31;
    __shared__ float redq[4], redk[4];
    if (tid < 4) { redq[tid] = 0.f; redk[tid] = 0.f; }
    __syncthreads();

    float yq[4], yk[4];
    #pragma unroll
    for (int j = 0; j < 4; ++j) {
        const int c = tid + 256*j;
        float aq=0.f, ak=0.f, av=0.f;
        #pragma unroll
        for (int t = 0; t < 4; ++t) {
            const int ll = l - 3 + t;
            if (ll >= 0) {
                const size_t g = ((size_t)(b*Ll + ll))*HD + c;
                aq += XQ[g]*WQ[c*4+t];
                ak += XK[g]*WK[c*4+t];
                av += XV[g]*WV[c*4+t];
            }
        }
        aq = siluf(aq); ak = siluf(ak); av = siluf(av);
        Vo[(size_t)row*HD + c] = av;
        yq[j] = aq; yk[j] = ak;
        float vq = aq*aq, vk = ak*ak;
        #pragma unroll
        for (int o = 16; o; o >>= 1) {
            vq += __shfl_xor_sync(0xffffffff, vq, o);
            vk += __shfl_xor_sync(0xffffffff, vk, o);
        }
        if (lane == 0) { atomicAdd(&redq[j], vq); atomicAdd(&redk[j], vk); }
    }
    __syncthreads();
    #pragma unroll
    for (int j = 0; j < 4; ++j) {
        const int c = tid + 256*j;
        const float rq = rsqrtf(redq[j] + 1e-12f);
        const float rk = rsqrtf(redk[j] + 1e-12f);
        Qo[(size_t)row*HD + c] = yq[j]*rq;
        Ko[(size_t)row*HD + c] = yk[j]*rk;
    }
}

// ---------------- per-chunk precompute: A, Tinv, u, w, attn ----------------
#define PRE_SMEM ((3*32*257 + 1024 + 1024 + 32) * 4)
__global__ void precompute_kernel(const float* __restrict__ Qn, const float* __restrict__ Kn,
                                  const float* __restrict__ V,  const float* __restrict__ beta,
                                  float* __restrict__ U, float* __restrict__ W,
                                  float* __restrict__ Attn)
{
    extern __shared__ float sm[];
    float* sq = sm;                // 32*257
    float* sk = sq + 32*257;
    float* sv = sk + 32*257;
    float* Am = sv + 32*257;       // 32*32
    float* Ti = Am + 1024;         // 32*32
    float* sb = Ti + 1024;         // 32

    const int idx = blockIdx.x;
    const int bh = idx / NCc, ci = idx % NCc;
    const int b = bh >> 2, h = bh & 3;
    const int tid = threadIdx.x;

    for (int e = tid; e < 32*256; e += 256) {
        const int i = e >> 8, d = e & 255;
        const size_t g = ((size_t)(b*Ll + ci*CSs + i))*HD + h*256 + d;
        sq[i*257+d] = Qn[g];
        sk[i*257+d] = Kn[g];
        sv[i*257+d] = V[g];
    }
    if (tid < 32) sb[tid] = beta[(size_t)(b*Ll + ci*CSs + tid)*4 + h];
    __syncthreads();
    for (int e = tid; e < 32*256; e += 256) {
        const int i = e >> 8, d = e & 255;
        sv[i*257+d] *= sb[i];       // vb = v * beta
    }
    // A (strict lower of kb k^T) and attn (lower incl diag of q k^T)
    for (int p = tid; p < 1024; p += 256) {
        const int i = p >> 5, j = p & 31;
        const float* ki = sk + i*257;
        const float* kj = sk + j*257;
        const float* qi = sq + i*257;
        float dkk = 0.f, dqk = 0.f;
        #pragma unroll 8
        for (int d = 0; d < 256; ++d) {
            const float kv = kj[d];
            dkk += ki[d]*kv;
            dqk += qi[d]*kv;
        }
        Am[p] = (i > j) ? sb[i]*dkk : 0.f;
        Attn[(size_t)(bh*NCc + ci)*1024 + p] = (i >= j) ? dqk : 0.f;
    }
    __syncthreads();
    // Tinv = (I + A)^{-1}, forward substitution (warp 0)
    if (tid < 32) {
        const int j = tid;
        Ti[j] = (j == 0) ? 1.f : 0.f;
        for (int i2 = 1; i2 < 32; ++i2) {
            __syncwarp();
            float s = 0.f;
            for (int m = 0; m < i2; ++m) s += Am[i2*32+m]*Ti[m*32+j];
            Ti[i2*32+j] = ((i2 == j) ? 1.f : 0.f) - s;
        }
    }
    __syncthreads();
    // u = Tinv @ vb ; w = Tinv @ (beta*k)
    for (int e = tid; e < 32*256; e += 256) {
        const int i = e >> 8, d = e & 255;
        float uu = 0.f, ww = 0.f;
        #pragma unroll
        for (int m = 0; m < 32; ++m) {
            const float t = Ti[i*32+m];
            uu += t * sv[m*257+d];
            ww += t * sb[m] * sk[m*257+d];
        }
        const size_t gb = (size_t)(bh*NCc + ci)*8192 + i*256 + d;
        U[gb] = uu; W[gb] = ww;
    }
}

// ---------------- sequential scan over chunks, dv split into 16-col blocks --------
#define SCAN_SMEM ((256*17 + 3*32*256 + 512 + 512 + 1024) * 4)
__global__ void __launch_bounds__(256) scan_kernel(const float* __restrict__ Qn,
                                                   const float* __restrict__ Kn,
                                                   const float* __restrict__ U,
                                                   const float* __restrict__ W,
                                                   const float* __restrict__ Attn,
                                                   float* __restrict__ Out)
{
    extern __shared__ float sm[];
    float* sS  = sm;              // 256*17 (padded)
    float* sq  = sS + 256*17;     // 32*256
    float* sk  = sq + 8192;
    float* sw  = sk + 8192;
    float* su  = sw + 8192;       // 32*16
    float* sun = su + 512;        // 32*16
    float* sa  = sun + 512;       // 32*32

    const int idx = blockIdx.x;
    const int bh = idx >> 4, cb = idx & 15;
    const int b = bh >> 2, h = bh & 3;
    const int tid = threadIdx.x;

    for (int e = tid; e < 256*17; e += 256) sS[e] = 0.f;
    __syncthreads();

    const int c  = tid & 15;
    const int i2 = tid >> 4;        // 0..15
    const int uc = tid & 15;
    const int rb = (tid >> 4) * 16; // 0..240

    for (int ci = 0; ci < NCc; ++ci) {
        const size_t cbase = (size_t)(bh*NCc + ci);
        // loads
        for (int e = tid; e < 32*256; e += 256) {
            const int i = e >> 8, d = e & 255;
            const size_t g = ((size_t)(b*Ll + ci*CSs + i))*HD + h*256 + d;
            sq[e] = Qn[g];
            sk[e] = Kn[g];
            sw[e] = W[cbase*8192 + e];
        }
        for (int e = tid; e < 512; e += 256) {
            const int i = e >> 4, cc = e & 15;
            su[e] = U[cbase*8192 + i*256 + cb*16 + cc];
        }
        for (int e = tid; e < 1024; e += 256) sa[e] = Attn[cbase*1024 + e];
        __syncthreads();

        // u' = u - w @ S   (two rows per thread: i2, i2+16)
        {
            float a0 = su[i2*16 + c], a1 = su[(i2+16)*16 + c];
            const float* w0 = sw + i2*256;
            const float* w1 = w0 + 16*256;
            #pragma unroll 8
            for (int r = 0; r < 256; r += 4) {
                const float4 wa = *(const float4*)(w0 + r);
                const float4 wb = *(const float4*)(w1 + r);
                const float s0 = sS[(r+0)*17 + c];
                const float s1 = sS[(r+1)*17 + c];
                const float s2 = sS[(r+2)*17 + c];
                const float s3 = sS[(r+3)*17 + c];
                a0 -= wa.x*s0 + wa.y*s1 + wa.z*s2 + wa.w*s3;
                a1 -= wb.x*s0 + wb.y*s1 + wb.z*s2 + wb.w*s3;
            }
            sun[i2*16 + c] = a0;
            sun[(i2+16)*16 + c] = a1;
        }
        __syncthreads();

        // o = q @ S + attn @ u'
        {
            float o0 = 0.f, o1 = 0.f;
            const float* q0 = sq + i2*256;
            const float* q1 = q0 + 16*256;
            #pragma unroll 8
            for (int r = 0; r < 256; r += 4) {
                const float4 qa = *(const float4*)(q0 + r);
                const float4 qb = *(const float4*)(q1 + r);
                const float s0 = sS[(r+0)*17 + c];
                const float s1 = sS[(r+1)*17 + c];
                const float s2 = sS[(r+2)*17 + c];
                const float s3 = sS[(r+3)*17 + c];
                o0 += qa.x*s0 + qa.y*s1 + qa.z*s2 + qa.w*s3;
                o1 += qb.x*s0 + qb.y*s1 + qb.z*s2 + qb.w*s3;
            }
            #pragma unroll
            for (int j = 0; j < 32; ++j) {
                const float uu = sun[j*16 + c];
                o0 += sa[i2*32 + j] * uu;
                o1 += sa[(i2+16)*32 + j] * uu;
            }
            const size_t go = ((size_t)(b*Ll + ci*CSs + i2))*HD + h*256 + cb*16 + c;
            Out[go] = o0;
            Out[go + (size_t)16*HD] = o1;
        }
        __syncthreads();

        // S += k^T @ u'  (thread: column uc, rows rb..rb+15 in registers)
        {
            float accS[16];
            #pragma unroll
            for (int rr = 0; rr < 16; ++rr) accS[rr] = sS[(rb+rr)*17 + uc];
            #pragma unroll
            for (int i = 0; i < 32; ++i) {
                const float uu = sun[i*16 + uc];
                const float* kr = sk + i*256 + rb;
                #pragma unroll
                for (int rr = 0; rr < 16; rr += 4) {
                    const float4 kv = *(const float4*)(kr + rr);
                    accS[rr+0] += kv.x*uu;
                    accS[rr+1] += kv.y*uu;
                    accS[rr+2] += kv.z*uu;
                    accS[rr+3] += kv.w*uu;
                }
            }
            #pragma unroll
            for (int rr = 0; rr < 16; ++rr) sS[(rb+rr)*17 + uc] = accS[rr];
        }
        __syncthreads();
    }
}

// ---------------- FIR short/long + gate_in assembly ----------------
__global__ void fir_gatein_kernel(const float* __restrict__ hs, const float* __restrict__ V,
                                  const float* __restrict__ ws, const float* __restrict__ wl,
                                  const float* __restrict__ Dl,
                                  float* __restrict__ Sout, float* __restrict__ Lout,
                                  float* __restrict__ Gin)
{
    const int blk = blockIdx.x;
    const int b = blk / (Ll/8);
    const int l0 = (blk % (Ll/8)) * 8;
    const int tid = threadIdx.x;

    float smean[8], lmean[8], dmean[8];
    #pragma unroll
    for (int r = 0; r < 8; ++r) { smean[r]=0.f; lmean[r]=0.f; dmean[r]=0.f; }

    for (int j = 0; j < 4; ++j) {
        const int ch = tid + 256*j;
        float win[38];
        #pragma unroll
        for (int t = 0; t < 38; ++t) {
            const int l = l0 - 30 + t;
            win[t] = (l >= 0) ? V[((size_t)(b*Ll + l))*HD + ch] : 0.f;
        }
        float wlr[31];
        #pragma unroll
        for (int t = 0; t < 31; ++t) wlr[t] = wl[ch*31 + t];
        const float w0 = ws[ch*3+0], w1 = ws[ch*3+1], w2 = ws[ch*3+2];
        #pragma unroll
        for (int r = 0; r < 8; ++r) {
            float yl = 0.f;
            #pragma unroll
            for (int t = 0; t < 31; ++t) yl += win[r+t]*wlr[t];
            const float ysv = win[r+28]*w0 + win[r+29]*w1 + win[r+30]*w2;
            const size_t row = (size_t)(b*Ll + l0 + r);
            Sout[row*HD + ch] = ysv;
            Lout[row*HD + ch] = yl;
            smean[r] += ysv; lmean[r] += yl;
            dmean[r] += Dl[row*HD + ch];
        }
    }
    // gate_in rows
    for (int r = 0; r < 8; ++r) {
        const size_t row = (size_t)(b*Ll + l0 + r);
        float* grow = Gin + row*GIN;
        #pragma unroll
        for (int j = 0; j < 4; ++j) grow[tid + 256*j] = hs[row*HD + tid + 256*j];
        grow[1024 + tid] = smean[r]*0.25f;
        grow[1280 + tid] = lmean[r]*0.25f;
        grow[1536 + tid] = dmean[r]*0.25f;
    }
}

// ---------------- gate head 2 + softmax/floor -> weights [b,l,4] ----------------
__global__ void gate2_wgt(const float* __restrict__ GH2, const float* __restrict__ W2,
                          const float* __restrict__ b2, const float* __restrict__ ltemp,
                          float* __restrict__ Wgt)
{
    const int row = blockIdx.x;
    const int warp = threadIdx.x >> 5, lane = threadIdx.x & 31;
    __shared__ float lg[4];
    const float* x = GH2 + (size_t)row*GHID;
    const float* w = W2 + warp*GHID;
    float s = 0.f;
    for (int i = lane; i < GHID; i += 32) s += x[i]*w[i];
    #pragma unroll
    for (int o = 16; o; o >>= 1) s += __shfl_xor_sync(0xffffffff, s, o);
    if (lane == 0) lg[warp] = s + b2[warp];
    __syncthreads();
    if (threadIdx.x == 0) {
        const float t = log1pf(expf(ltemp[0])) + 1e-4f;
        float m = fmaxf(fmaxf(lg[0], lg[1]), fmaxf(lg[2], lg[3]));
        float e[4]; float se = 0.f;
        #pragma unroll
        for (int j = 0; j < 4; ++j) { e[j] = expf((lg[j]-m)/t); se += e[j]; }
        #pragma unroll
        for (int j = 0; j < 4; ++j) e[j] /= se;
        const float fl = 0.05f * e[3];
        e[0] = fmaxf(e[0], fl);
        e[1] = fmaxf(e[1], fl);
        const float s2 = e[0]+e[1]+e[2]+e[3];
        #pragma unroll
        for (int j = 0; j < 4; ++j) Wgt[row*4+j] = e[j]/s2;
    }
}

// ---------------- weighted combine + per-head RMSNorm ----------------
__global__ void combine_kernel(const float* __restrict__ Sh, const float* __restrict__ Lg,
                               const float* __restrict__ Dl, const float* __restrict__ V,
                               const float* __restrict__ Wgt, const float* __restrict__ onw,
                               float* __restrict__ O)
{
    const int row = blockIdx.x;
    const int tid = threadIdx.x, lane = tid & 31;
    __shared__ float red[4];
    if (tid < 4) red[tid] = 0.f;
    __syncthreads();
    const float w0 = Wgt[row*4+0], w1 = Wgt[row*4+1], w2 = Wgt[row*4+2], w3 = Wgt[row*4+3];
    float ov[4];
    #pragma unroll
    for (int j = 0; j < 4; ++j) {
        const size_t g = (size_t)row*HD + tid + 256*j;
        ov[j] = w0*Sh[g] + w1*Lg[g] + w2*Dl[g] + w3*V[g];
        float v = ov[j]*ov[j];
        #pragma unroll
        for (int o = 16; o; o >>= 1) v += __shfl_xor_sync(0xffffffff, v, o);
        if (lane == 0) atomicAdd(&red[j], v);
    }
    __syncthreads();
    #pragma unroll
    for (int j = 0; j < 4; ++j) {
        const float sc = rsqrtf(red[j]*(1.f/256.f) + 1e-5f) * onw[tid];
        O[(size_t)row*HD + tid + 256*j] = ov[j]*sc;
    }
}

// ---------------- launch ----------------
extern "C" void kernel_launch(void* const* d_in, const int* in_sizes, int n_in,
                              void* d_out, int out_size)
{
    const float* hs  = (const float*)d_in[0];
    const float* qw  = (const float*)d_in[1];
    const float* kw  = (const float*)d_in[2];
    const float* vw  = (const float*)d_in[3];
    const float* bw  = (const float*)d_in[4];
    const float* qcw = (const float*)d_in[5];
    const float* kcw = (const float*)d_in[6];
    const float* vcw = (const float*)d_in[7];
    const float* fsw = (const float*)d_in[8];
    const float* flw = (const float*)d_in[9];
    const float* w1  = (const float*)d_in[10];
    const float* b1  = (const float*)d_in[11];
    const float* w2  = (const float*)d_in[12];
    const float* b2  = (const float*)d_in[13];
    const float* lt  = (const float*)d_in[14];
    const float* onw = (const float*)d_in[15];
    const float* ow  = (const float*)d_in[16];
    float* out = (float*)d_out;

    float *xq,*xk,*xv,*q,*k,*v,*u,*w,*attn,*delta,*shrt,*lng,*gin,*gh,*beta,*wgt,*ocomb;
    cudaGetSymbolAddress((void**)&xq,   g_xq);
    cudaGetSymbolAddress((void**)&xk,   g_xk);
    cudaGetSymbolAddress((void**)&xv,   g_xv);
    cudaGetSymbolAddress((void**)&q,    g_q);
    cudaGetSymbolAddress((void**)&k,    g_k);
    cudaGetSymbolAddress((void**)&v,    g_v);
    cudaGetSymbolAddress((void**)&u,    g_u);
    cudaGetSymbolAddress((void**)&w,    g_w);
    cudaGetSymbolAddress((void**)&attn, g_attn);
    cudaGetSymbolAddress((void**)&delta,g_delta);
    cudaGetSymbolAddress((void**)&shrt, g_short);
    cudaGetSymbolAddress((void**)&lng,  g_long);
    cudaGetSymbolAddress((void**)&gin,  g_gin);
    cudaGetSymbolAddress((void**)&gh,   g_gh);
    cudaGetSymbolAddress((void**)&beta, g_beta);
    cudaGetSymbolAddress((void**)&wgt,  g_wgt);
    cudaGetSymbolAddress((void**)&ocomb,g_ocomb);

    cudaFuncSetAttribute(precompute_kernel, cudaFuncAttributeMaxDynamicSharedMemorySize, PRE_SMEM);
    cudaFuncSetAttribute(scan_kernel,       cudaFuncAttributeMaxDynamicSharedMemorySize, SCAN_SMEM);

    const dim3 gemmGrid(HD/128, BL/128);   // (8, 64)

    sgemm_nt<false><<<gemmGrid, 256>>>(hs, qw, xq, BL, HD, Dd, nullptr);
    sgemm_nt<false><<<gemmGrid, 256>>>(hs, kw, xk, BL, HD, Dd, nullptr);
    sgemm_nt<false><<<gemmGrid, 256>>>(hs, vw, xv, BL, HD, Dd, nullptr);
    beta_kernel<<<BL, 128>>>(hs, bw, beta);
    conv_silu_norm<<<BL, 256>>>(xq, xk, xv, qcw, kcw, vcw, q, k, v);
    precompute_kernel<<<Bb*Hh*NCc, 256, PRE_SMEM>>>(q, k, v, beta, u, w, attn);
    scan_kernel<<<Bb*Hh*16, 256, SCAN_SMEM>>>(q, k, u, w, attn, delta);
    fir_gatein_kernel<<<Bb*(Ll/8), 256>>>(hs, v, fsw, flw, delta, shrt, lng, gin);
    sgemm_nt<true><<<gemmGrid, 256>>>(gin, w1, gh, BL, GHID, GIN, b1);
    gate2_wgt<<<BL, 128>>>(gh, w2, b2, lt, wgt);
    combine_kernel<<<BL, 256>>>(shrt, lng, delta, v, wgt, onw, ocomb);
    sgemm_nt<false><<<gemmGrid, 256>>>(ocomb, ow, out, BL, Dd, HD, nullptr);
}

// round 2
// speedup vs baseline: 1.4672x; 1.4672x over previous
#include <cuda_runtime.h>
#include <cuda_bf16.h>
#include <math.h>

// ---------------- problem constants ----------------
#define Bb   2
#define Ll   4096
#define Dd   1024
#define Hh   4
#define DKk  256
#define DVv  256
#define CSs  32
#define NCc  128          // L / CS
#define BL   (Bb*Ll)      // 8192
#define HD   1024         // H*DK = H*DV
#define GIN  1792
#define GHID 1024

// ---------------- scratch (device globals; no runtime alloc) ----------------
__device__ float g_xq[BL*HD];
__device__ float g_xk[BL*HD];
__device__ float g_xv[BL*HD];
__device__ float g_q [BL*HD];
__device__ float g_k [BL*HD];
__device__ float g_v [BL*HD];
__device__ float g_u [Bb*Hh*Ll*DVv];
__device__ float g_w [Bb*Hh*Ll*DVv];
__device__ float g_attn[Bb*Hh*NCc*CSs*CSs];
__device__ float g_delta[BL*HD];
__device__ float g_short[BL*HD];
__device__ float g_long [BL*HD];
__device__ float g_gin[BL*GIN];
__device__ float g_gh [BL*GHID];
__device__ float g_beta[BL*Hh];
__device__ float g_wgt [BL*4];
__device__ float g_ocomb[BL*HD];

// bf16 hi/lo split buffers
__device__ __align__(16) __nv_bfloat16 g_hsH[BL*Dd];
__device__ __align__(16) __nv_bfloat16 g_hsL[BL*Dd];
__device__ __align__(16) __nv_bfloat16 g_ginH[BL*GIN];
__device__ __align__(16) __nv_bfloat16 g_ginL[BL*GIN];
__device__ __align__(16) __nv_bfloat16 g_ocH[BL*HD];
__device__ __align__(16) __nv_bfloat16 g_ocL[BL*HD];
// weights: qw(1M) kw(1M) vw(1M) w1(1792*1024) ow(1M)
#define WOFF_Q  0
#define WOFF_K  (1024*1024)
#define WOFF_V  (2*1024*1024)
#define WOFF_W1 (3*1024*1024)
#define WOFF_O  (3*1024*1024 + 1792*1024)
#define WTOT    (WOFF_O + 1024*1024)
__device__ __align__(16) __nv_bfloat16 g_wtH[WTOT];
__device__ __align__(16) __nv_bfloat16 g_wtL[WTOT];

// ---------------- helpers ----------------
__device__ __forceinline__ float siluf(float x){ return x / (1.f + expf(-x)); }
__device__ __forceinline__ float geluf(float x){ return 0.5f * x * (1.f + erff(x * 0.70710678118654752f)); }

__device__ __forceinline__ void ldsm4(unsigned* r, unsigned addr){
    asm volatile("ldmatrix.sync.aligned.m8n8.x4.shared.b16 {%0,%1,%2,%3}, [%4];"
        : "=r"(r[0]),"=r"(r[1]),"=r"(r[2]),"=r"(r[3]) : "r"(addr));
}
__device__ __forceinline__ void mma16816(float* c, const unsigned* a, const unsigned* b){
    asm volatile("mma.sync.aligned.m16n8k16.row.col.f32.bf16.bf16.f32 "
        "{%0,%1,%2,%3}, {%4,%5,%6,%7}, {%8,%9}, {%0,%1,%2,%3};"
        : "+f"(c[0]),"+f"(c[1]),"+f"(c[2]),"+f"(c[3])
        : "r"(a[0]),"r"(a[1]),"r"(a[2]),"r"(a[3]), "r"(b[0]),"r"(b[1]));
}

// ---------------- fp32 -> (hi,lo) bf16 split ----------------
__global__ void split_kernel(const float4* __restrict__ x, uint2* __restrict__ hi,
                             uint2* __restrict__ lo, int n4)
{
    int i = blockIdx.x*blockDim.x + threadIdx.x;
    if (i >= n4) return;
    float4 v = x[i];
    __nv_bfloat16 h0=__float2bfloat16(v.x), h1=__float2bfloat16(v.y),
                  h2=__float2bfloat16(v.z), h3=__float2bfloat16(v.w);
    __nv_bfloat16 l0=__float2bfloat16(v.x-__bfloat162float(h0));
    __nv_bfloat16 l1=__float2bfloat16(v.y-__bfloat162float(h1));
    __nv_bfloat16 l2=__float2bfloat16(v.z-__bfloat162float(h2));
    __nv_bfloat16 l3=__float2bfloat16(v.w-__bfloat162float(h3));
    __nv_bfloat162 hp0{h0,h1}, hp1{h2,h3}, lp0{l0,l1}, lp1{l2,l3};
    uint2 ho, loo;
    ho.x = *(unsigned*)&hp0; ho.y = *(unsigned*)&hp1;
    loo.x = *(unsigned*)&lp0; loo.y = *(unsigned*)&lp1;
    hi[i] = ho; lo[i] = loo;
}

// ---------------- bf16x3 split GEMM: C[M,N] = A[M,K]*B[N,K]^T (fp32-grade) ----------
// CTA 128x128, k-step 16, 8 warps (2x4), warp tile 64x32.
template<bool EPI>
__global__ void __launch_bounds__(256) hgemm_nt(const __nv_bfloat16* __restrict__ Ah,
                                                const __nv_bfloat16* __restrict__ Al,
                                                const __nv_bfloat16* __restrict__ Bh,
                                                const __nv_bfloat16* __restrict__ Bl,
                                                float* __restrict__ C,
                                                int M, int N, int K,
                                                const float* __restrict__ bias)
{
    __shared__ __align__(16) __nv_bfloat16 sm[4*128*24];  // Ah,Al,Bh,Bl planes
    const int PL = 128*24;
    __nv_bfloat16* sAh = sm;
    __nv_bfloat16* sAl = sm + PL;
    __nv_bfloat16* sBh = sm + 2*PL;
    __nv_bfloat16* sBl = sm + 3*PL;

    const int tid = threadIdx.x;
    const int bm = blockIdx.y*128, bn = blockIdx.x*128;
    const int warp = tid>>5, lane = tid&31;
    const int wm = warp>>2, wn = warp&3;

    float acc[4][4][4];
    #pragma unroll
    for (int i=0;i<4;i++) for(int j=0;j<4;j++) for(int r=0;r<4;r++) acc[i][j][r]=0.f;

    // gmem load: thread -> (row = tid>>1, 16B chunk = tid&1)
    const size_t aoff = (size_t)(bm + (tid>>1))*K + (tid&1)*8;
    const size_t boff = (size_t)(bn + (tid>>1))*K + (tid&1)*8;
    const int sto = (tid>>1)*24 + (tid&1)*8;

    // ldmatrix addresses (byte, shared space)
    unsigned base = (unsigned)__cvta_generic_to_shared(sm);
    // A: row = wm*64 + mt*16 + (lane&15), col = (lane>>4)*8
    const int arow = wm*64 + (lane&15);
    const int acol = (lane>>4)*8;
    // B: row = wn*32 + ng*16 + ((lane>>4)&1)*8 + (lane&7), col = ((lane>>3)&1)*8
    const int brow = wn*32 + ((lane>>4)&1)*8 + (lane&7);
    const int bcol = ((lane>>3)&1)*8;

    const int nk = K >> 4;
    uint4 rAh, rAl, rBh, rBl;
    rAh = *(const uint4*)(Ah + aoff);
    rAl = *(const uint4*)(Al + aoff);
    rBh = *(const uint4*)(Bh + boff);
    rBl = *(const uint4*)(Bl + boff);

    for (int kt = 0; kt < nk; ++kt) {
        __syncthreads();
        *(uint4*)(sAh + sto) = rAh;
        *(uint4*)(sAl + sto) = rAl;
        *(uint4*)(sBh + sto) = rBh;
        *(uint4*)(sBl + sto) = rBl;
        __syncthreads();
        if (kt + 1 < nk) {
            const size_t ka = aoff + (size_t)(kt+1)*16;
            const size_t kb = boff + (size_t)(kt+1)*16;
            rAh = *(const uint4*)(Ah + ka);
            rAl = *(const uint4*)(Al + ka);
            rBh = *(const uint4*)(Bh + kb);
            rBl = *(const uint4*)(Bl + kb);
        }
        // B fragments (4 n-tiles: bh[nt][2], bl[nt][2])
        unsigned bh[4][2], bl[4][2];
        #pragma unroll
        for (int ng = 0; ng < 2; ++ng) {
            unsigned r4[4];
            unsigned addr = base + 2u*(2*PL + (brow + ng*16)*24 + bcol);
            ldsm4(r4, addr);
            bh[2*ng][0]=r4[0]; bh[2*ng][1]=r4[1]; bh[2*ng+1][0]=r4[2]; bh[2*ng+1][1]=r4[3];
            addr = base + 2u*(3*PL + (brow + ng*16)*24 + bcol);
            ldsm4(r4, addr);
            bl[2*ng][0]=r4[0]; bl[2*ng][1]=r4[1]; bl[2*ng+1][0]=r4[2]; bl[2*ng+1][1]=r4[3];
        }
        #pragma unroll
        for (int mt = 0; mt < 4; ++mt) {
            unsigned ah[4], al[4];
            unsigned addr = base + 2u*((arow + mt*16)*24 + acol);
            ldsm4(ah, addr);
            addr = base + 2u*(PL + (arow + mt*16)*24 + acol);
            ldsm4(al, addr);
            #pragma unroll
            for (int nt = 0; nt < 4; ++nt) {
                mma16816(acc[mt][nt], ah, bh[nt]);
                mma16816(acc[mt][nt], ah, bl[nt]);
                mma16816(acc[mt][nt], al, bh[nt]);
            }
        }
    }

    // epilogue
    const int g = lane>>2, tig = lane&3;
    #pragma unroll
    for (int mt = 0; mt < 4; ++mt) {
        const int row0 = bm + wm*64 + mt*16 + g;
        #pragma unroll
        for (int nt = 0; nt < 4; ++nt) {
            const int col = bn + wn*32 + nt*8 + tig*2;
            float v0 = acc[mt][nt][0], v1 = acc[mt][nt][1];
            float v2 = acc[mt][nt][2], v3 = acc[mt][nt][3];
            if (EPI) {
                const float bz0 = bias[col], bz1 = bias[col+1];
                v0 = geluf(v0+bz0); v1 = geluf(v1+bz1);
                v2 = geluf(v2+bz0); v3 = geluf(v3+bz1);
            }
            *(float2*)(C + (size_t)row0*N + col)     = make_float2(v0, v1);
            *(float2*)(C + (size_t)(row0+8)*N + col) = make_float2(v2, v3);
        }
    }
}

// ---------------- beta = sigmoid(hs @ b_proj^T) ----------------
__global__ void beta_kernel(const float* __restrict__ hs, const float* __restrict__ bw,
                            float* __restrict__ beta)
{
    const int row = blockIdx.x;
    const int warp = threadIdx.x >> 5, lane = threadIdx.x & 31;
    const float* x = hs + (size_t)row * Dd;
    const float* w = bw + warp * Dd;
    float s = 0.f;
    for (int i = lane; i < Dd; i += 32) s += x[i] * w[i];
    #pragma unroll
    for (int o = 16; o; o >>= 1) s += __shfl_xor_sync(0xffffffff, s, o);
    if (lane == 0) beta[row*4 + warp] = 1.f / (1.f + expf(-s));
}

// ---------------- causal conv(k=4) + silu + (q,k: per-head l2norm) ----------------
__global__ void conv_silu_norm(const float* __restrict__ XQ, const float* __restrict__ XK,
                               const float* __restrict__ XV,
                               const float* __restrict__ WQ, const float* __restrict__ WK,
                               const float* __restrict__ WV,
                               float* __restrict__ Qo, float* __restrict__ Ko,
                               float* __restrict__ Vo)
{
    const int row = blockIdx.x;
    const int b = row >> 12, l = row & (Ll-1);
    const int tid = threadIdx.x;
    const int lane = tid & 31;
    __shared__ float redq[4], redk[4];
    if (tid < 4) { redq[tid] = 0.f; redk[tid] = 0.f; }
    __syncthreads();

    float yq[4], yk[4];
    #pragma unroll
    for (int j = 0; j < 4; ++j) {
        const int c = tid + 256*j;
        float aq=0.f, ak=0.f, av=0.f;
        #pragma unroll
        for (int t = 0; t < 4; ++t) {
            const int ll = l - 3 + t;
            if (ll >= 0) {
                const size_t g = ((size_t)(b*Ll + ll))*HD + c;
                aq += XQ[g]*WQ[c*4+t];
                ak += XK[g]*WK[c*4+t];
                av += XV[g]*WV[c*4+t];
            }
        }
        aq = siluf(aq); ak = siluf(ak); av = siluf(av);
        Vo[(size_t)row*HD + c] = av;
        yq[j] = aq; yk[j] = ak;
        float vq = aq*aq, vk = ak*ak;
        #pragma unroll
        for (int o = 16; o; o >>= 1) {
            vq += __shfl_xor_sync(0xffffffff, vq, o);
            vk += __shfl_xor_sync(0xffffffff, vk, o);
        }
        if (lane == 0) { atomicAdd(&redq[j], vq); atomicAdd(&redk[j], vk); }
    }
    __syncthreads();
    #pragma unroll
    for (int j = 0; j < 4; ++j) {
        const int c = tid + 256*j;
        const float rq = rsqrtf(redq[j] + 1e-12f);
        const float rk = rsqrtf(redk[j] + 1e-12f);
        Qo[(size_t)row*HD + c] = yq[j]*rq;
        Ko[(size_t)row*HD + c] = yk[j]*rk;
    }
}

// ---------------- per-chunk precompute: A, Tinv, u, w, attn ----------------
#define PRE_SMEM ((3*32*257 + 1024 + 1024 + 32) * 4)
__global__ void precompute_kernel(const float* __restrict__ Qn, const float* __restrict__ Kn,
                                  const float* __restrict__ V,  const float* __restrict__ beta,
                                  float* __restrict__ U, float* __restrict__ W,
                                  float* __restrict__ Attn)
{
    extern __shared__ float sm[];
    float* sq = sm;
    float* sk = sq + 32*257;
    float* sv = sk + 32*257;
    float* Am = sv + 32*257;
    float* Ti = Am + 1024;
    float* sb = Ti + 1024;

    const int idx = blockIdx.x;
    const int bh = idx / NCc, ci = idx % NCc;
    const int b = bh >> 2, h = bh & 3;
    const int tid = threadIdx.x;

    for (int e = tid; e < 32*256; e += 256) {
        const int i = e >> 8, d = e & 255;
        const size_t g = ((size_t)(b*Ll + ci*CSs + i))*HD + h*256 + d;
        sq[i*257+d] = Qn[g];
        sk[i*257+d] = Kn[g];
        sv[i*257+d] = V[g];
    }
    if (tid < 32) sb[tid] = beta[(size_t)(b*Ll + ci*CSs + tid)*4 + h];
    __syncthreads();
    for (int e = tid; e < 32*256; e += 256) {
        const int i = e >> 8, d = e & 255;
        sv[i*257+d] *= sb[i];
    }
    for (int p = tid; p < 1024; p += 256) {
        const int i = p >> 5, j = p & 31;
        const float* ki = sk + i*257;
        const float* kj = sk + j*257;
        const float* qi = sq + i*257;
        float dkk = 0.f, dqk = 0.f;
        #pragma unroll 8
        for (int d = 0; d < 256; ++d) {
            const float kv = kj[d];
            dkk += ki[d]*kv;
            dqk += qi[d]*kv;
        }
        Am[p] = (i > j) ? sb[i]*dkk : 0.f;
        Attn[(size_t)(bh*NCc + ci)*1024 + p] = (i >= j) ? dqk : 0.f;
    }
    __syncthreads();
    if (tid < 32) {
        const int j = tid;
        Ti[j] = (j == 0) ? 1.f : 0.f;
        for (int i2 = 1; i2 < 32; ++i2) {
            __syncwarp();
            float s = 0.f;
            for (int m = 0; m < i2; ++m) s += Am[i2*32+m]*Ti[m*32+j];
            Ti[i2*32+j] = ((i2 == j) ? 1.f : 0.f) - s;
        }
    }
    __syncthreads();
    for (int e = tid; e < 32*256; e += 256) {
        const int i = e >> 8, d = e & 255;
        float uu = 0.f, ww = 0.f;
        #pragma unroll
        for (int m = 0; m < 32; ++m) {
            const float t = Ti[i*32+m];
            uu += t * sv[m*257+d];
            ww += t * sb[m] * sk[m*257+d];
        }
        const size_t gb = (size_t)(bh*NCc + ci)*8192 + i*256 + d;
        U[gb] = uu; W[gb] = ww;
    }
}

// ---------------- sequential scan over chunks, dv split into 16-col blocks --------
#define SCAN_SMEM ((256*17 + 3*32*256 + 512 + 512 + 1024) * 4)
__global__ void __launch_bounds__(256) scan_kernel(const float* __restrict__ Qn,
                                                   const float* __restrict__ Kn,
                                                   const float* __restrict__ U,
                                                   const float* __restrict__ W,
                                                   const float* __restrict__ Attn,
                                                   float* __restrict__ Out)
{
    extern __shared__ float sm[];
    float* sS  = sm;
    float* sq  = sS + 256*17;
    float* sk  = sq + 8192;
    float* sw  = sk + 8192;
    float* su  = sw + 8192;
    float* sun = su + 512;
    float* sa  = sun + 512;

    const int idx = blockIdx.x;
    const int bh = idx >> 4, cb = idx & 15;
    const int b = bh >> 2, h = bh & 3;
    const int tid = threadIdx.x;

    for (int e = tid; e < 256*17; e += 256) sS[e] = 0.f;
    __syncthreads();

    const int c  = tid & 15;
    const int i2 = tid >> 4;
    const int uc = tid & 15;
    const int rb = (tid >> 4) * 16;

    for (int ci = 0; ci < NCc; ++ci) {
        const size_t cbase = (size_t)(bh*NCc + ci);
        for (int e = tid; e < 32*256; e += 256) {
            const int i = e >> 8, d = e & 255;
            const size_t g = ((size_t)(b*Ll + ci*CSs + i))*HD + h*256 + d;
            sq[e] = Qn[g];
            sk[e] = Kn[g];
            sw[e] = W[cbase*8192 + e];
        }
        for (int e = tid; e < 512; e += 256) {
            const int i = e >> 4, cc = e & 15;
            su[e] = U[cbase*8192 + i*256 + cb*16 + cc];
        }
        for (int e = tid; e < 1024; e += 256) sa[e] = Attn[cbase*1024 + e];
        __syncthreads();

        {
            float a0 = su[i2*16 + c], a1 = su[(i2+16)*16 + c];
            const float* w0 = sw + i2*256;
            const float* w1 = w0 + 16*256;
            #pragma unroll 8
            for (int r = 0; r < 256; r += 4) {
                const float4 wa = *(const float4*)(w0 + r);
                const float4 wb = *(const float4*)(w1 + r);
                const float s0 = sS[(r+0)*17 + c];
                const float s1 = sS[(r+1)*17 + c];
                const float s2 = sS[(r+2)*17 + c];
                const float s3 = sS[(r+3)*17 + c];
                a0 -= wa.x*s0 + wa.y*s1 + wa.z*s2 + wa.w*s3;
                a1 -= wb.x*s0 + wb.y*s1 + wb.z*s2 + wb.w*s3;
            }
            sun[i2*16 + c] = a0;
            sun[(i2+16)*16 + c] = a1;
        }
        __syncthreads();

        {
            float o0 = 0.f, o1 = 0.f;
            const float* q0 = sq + i2*256;
            const float* q1 = q0 + 16*256;
            #pragma unroll 8
            for (int r = 0; r < 256; r += 4) {
                const float4 qa = *(const float4*)(q0 + r);
                const float4 qb = *(const float4*)(q1 + r);
                const float s0 = sS[(r+0)*17 + c];
                const float s1 = sS[(r+1)*17 + c];
                const float s2 = sS[(r+2)*17 + c];
                const float s3 = sS[(r+3)*17 + c];
                o0 += qa.x*s0 + qa.y*s1 + qa.z*s2 + qa.w*s3;
                o1 += qb.x*s0 + qb.y*s1 + qb.z*s2 + qb.w*s3;
            }
            #pragma unroll
            for (int j = 0; j < 32; ++j) {
                const float uu = sun[j*16 + c];
                o0 += sa[i2*32 + j] * uu;
                o1 += sa[(i2+16)*32 + j] * uu;
            }
            const size_t go = ((size_t)(b*Ll + ci*CSs + i2))*HD + h*256 + cb*16 + c;
            Out[go] = o0;
            Out[go + (size_t)16*HD] = o1;
        }
        __syncthreads();

        {
            float accS[16];
            #pragma unroll
            for (int rr = 0; rr < 16; ++rr) accS[rr] = sS[(rb+rr)*17 + uc];
            #pragma unroll
            for (int i = 0; i < 32; ++i) {
                const float uu = sun[i*16 + uc];
                const float* kr = sk + i*256 + rb;
                #pragma unroll
                for (int rr = 0; rr < 16; rr += 4) {
                    const float4 kv = *(const float4*)(kr + rr);
                    accS[rr+0] += kv.x*uu;
                    accS[rr+1] += kv.y*uu;
                    accS[rr+2] += kv.z*uu;
                    accS[rr+3] += kv.w*uu;
                }
            }
            #pragma unroll
            for (int rr = 0; rr < 16; ++rr) sS[(rb+rr)*17 + uc] = accS[rr];
        }
        __syncthreads();
    }
}

// ---------------- FIR short/long + gate_in assembly ----------------
__global__ void fir_gatein_kernel(const float* __restrict__ hs, const float* __restrict__ V,
                                  const float* __restrict__ ws, const float* __restrict__ wl,
                                  const float* __restrict__ Dl,
                                  float* __restrict__ Sout, float* __restrict__ Lout,
                                  float* __restrict__ Gin)
{
    const int blk = blockIdx.x;
    const int b = blk / (Ll/8);
    const int l0 = (blk % (Ll/8)) * 8;
    const int tid = threadIdx.x;

    float smean[8], lmean[8], dmean[8];
    #pragma unroll
    for (int r = 0; r < 8; ++r) { smean[r]=0.f; lmean[r]=0.f; dmean[r]=0.f; }

    for (int j = 0; j < 4; ++j) {
        const int ch = tid + 256*j;
        float win[38];
        #pragma unroll
        for (int t = 0; t < 38; ++t) {
            const int l = l0 - 30 + t;
            win[t] = (l >= 0) ? V[((size_t)(b*Ll + l))*HD + ch] : 0.f;
        }
        float wlr[31];
        #pragma unroll
        for (int t = 0; t < 31; ++t) wlr[t] = wl[ch*31 + t];
        const float w0 = ws[ch*3+0], w1 = ws[ch*3+1], w2 = ws[ch*3+2];
        #pragma unroll
        for (int r = 0; r < 8; ++r) {
            float yl = 0.f;
            #pragma unroll
            for (int t = 0; t < 31; ++t) yl += win[r+t]*wlr[t];
            const float ysv = win[r+28]*w0 + win[r+29]*w1 + win[r+30]*w2;
            const size_t row = (size_t)(b*Ll + l0 + r);
            Sout[row*HD + ch] = ysv;
            Lout[row*HD + ch] = yl;
            smean[r] += ysv; lmean[r] += yl;
            dmean[r] += Dl[row*HD + ch];
        }
    }
    for (int r = 0; r < 8; ++r) {
        const size_t row = (size_t)(b*Ll + l0 + r);
        float* grow = Gin + row*GIN;
        #pragma unroll
        for (int j = 0; j < 4; ++j) grow[tid + 256*j] = hs[row*HD + tid + 256*j];
        grow[1024 + tid] = smean[r]*0.25f;
        grow[1280 + tid] = lmean[r]*0.25f;
        grow[1536 + tid] = dmean[r]*0.25f;
    }
}

// ---------------- gate head 2 + softmax/floor -> weights [b,l,4] ----------------
__global__ void gate2_wgt(const float* __restrict__ GH2, const float* __restrict__ W2,
                          const float* __restrict__ b2, const float* __restrict__ ltemp,
                          float* __restrict__ Wgt)
{
    const int row = blockIdx.x;
    const int warp = threadIdx.x >> 5, lane = threadIdx.x & 31;
    __shared__ float lg[4];
    const float* x = GH2 + (size_t)row*GHID;
    const float* w = W2 + warp*GHID;
    float s = 0.f;
    for (int i = lane; i < GHID; i += 32) s += x[i]*w[i];
    #pragma unroll
    for (int o = 16; o; o >>= 1) s += __shfl_xor_sync(0xffffffff, s, o);
    if (lane == 0) lg[warp] = s + b2[warp];
    __syncthreads();
    if (threadIdx.x == 0) {
        const float t = log1pf(expf(ltemp[0])) + 1e-4f;
        float m = fmaxf(fmaxf(lg[0], lg[1]), fmaxf(lg[2], lg[3]));
        float e[4]; float se = 0.f;
        #pragma unroll
        for (int j = 0; j < 4; ++j) { e[j] = expf((lg[j]-m)/t); se += e[j]; }
        #pragma unroll
        for (int j = 0; j < 4; ++j) e[j] /= se;
        const float fl = 0.05f * e[3];
        e[0] = fmaxf(e[0], fl);
        e[1] = fmaxf(e[1], fl);
        const float s2 = e[0]+e[1]+e[2]+e[3];
        #pragma unroll
        for (int j = 0; j < 4; ++j) Wgt[row*4+j] = e[j]/s2;
    }
}

// ---------------- weighted combine + per-head RMSNorm ----------------
__global__ void combine_kernel(const float* __restrict__ Sh, const float* __restrict__ Lg,
                               const float* __restrict__ Dl, const float* __restrict__ V,
                               const float* __restrict__ Wgt, const float* __restrict__ onw,
                               float* __restrict__ O)
{
    const int row = blockIdx.x;
    const int tid = threadIdx.x, lane = tid & 31;
    __shared__ float red[4];
    if (tid < 4) red[tid] = 0.f;
    __syncthreads();
    const float w0 = Wgt[row*4+0], w1 = Wgt[row*4+1], w2 = Wgt[row*4+2], w3 = Wgt[row*4+3];
    float ov[4];
    #pragma unroll
    for (int j = 0; j < 4; ++j) {
        const size_t g = (size_t)row*HD + tid + 256*j;
        ov[j] = w0*Sh[g] + w1*Lg[g] + w2*Dl[g] + w3*V[g];
        float v = ov[j]*ov[j];
        #pragma unroll
        for (int o = 16; o; o >>= 1) v += __shfl_xor_sync(0xffffffff, v, o);
        if (lane == 0) atomicAdd(&red[j], v);
    }
    __syncthreads();
    #pragma unroll
    for (int j = 0; j < 4; ++j) {
        const float sc = rsqrtf(red[j]*(1.f/256.f) + 1e-5f) * onw[tid];
        O[(size_t)row*HD + tid + 256*j] = ov[j]*sc;
    }
}

// ---------------- launch ----------------
static inline void split_launch(const float* x, __nv_bfloat16* hi, __nv_bfloat16* lo, size_t n)
{
    int n4 = (int)(n >> 2);
    split_kernel<<<(n4 + 255)/256, 256>>>((const float4*)x, (uint2*)hi, (uint2*)lo, n4);
}

extern "C" void kernel_launch(void* const* d_in, const int* in_sizes, int n_in,
                              void* d_out, int out_size)
{
    const float* hs  = (const float*)d_in[0];
    const float* qw  = (const float*)d_in[1];
    const float* kw  = (const float*)d_in[2];
    const float* vw  = (const float*)d_in[3];
    const float* bw  = (const float*)d_in[4];
    const float* qcw = (const float*)d_in[5];
    const float* kcw = (const float*)d_in[6];
    const float* vcw = (const float*)d_in[7];
    const float* fsw = (const float*)d_in[8];
    const float* flw = (const float*)d_in[9];
    const float* w1  = (const float*)d_in[10];
    const float* b1  = (const float*)d_in[11];
    const float* w2  = (const float*)d_in[12];
    const float* b2  = (const float*)d_in[13];
    const float* lt  = (const float*)d_in[14];
    const float* onw = (const float*)d_in[15];
    const float* ow  = (const float*)d_in[16];
    float* out = (float*)d_out;

    float *xq,*xk,*xv,*q,*k,*v,*u,*w,*attn,*delta,*shrt,*lng,*gin,*gh,*beta,*wgt,*ocomb;
    __nv_bfloat16 *hsH,*hsL,*ginH,*ginL,*ocH,*ocL,*wtH,*wtL;
    cudaGetSymbolAddress((void**)&xq,   g_xq);
    cudaGetSymbolAddress((void**)&xk,   g_xk);
    cudaGetSymbolAddress((void**)&xv,   g_xv);
    cudaGetSymbolAddress((void**)&q,    g_q);
    cudaGetSymbolAddress((void**)&k,    g_k);
    cudaGetSymbolAddress((void**)&v,    g_v);
    cudaGetSymbolAddress((void**)&u,    g_u);
    cudaGetSymbolAddress((void**)&w,    g_w);
    cudaGetSymbolAddress((void**)&attn, g_attn);
    cudaGetSymbolAddress((void**)&delta,g_delta);
    cudaGetSymbolAddress((void**)&shrt, g_short);
    cudaGetSymbolAddress((void**)&lng,  g_long);
    cudaGetSymbolAddress((void**)&gin,  g_gin);
    cudaGetSymbolAddress((void**)&gh,   g_gh);
    cudaGetSymbolAddress((void**)&beta, g_beta);
    cudaGetSymbolAddress((void**)&wgt,  g_wgt);
    cudaGetSymbolAddress((void**)&ocomb,g_ocomb);
    cudaGetSymbolAddress((void**)&hsH,  g_hsH);
    cudaGetSymbolAddress((void**)&hsL,  g_hsL);
    cudaGetSymbolAddress((void**)&ginH, g_ginH);
    cudaGetSymbolAddress((void**)&ginL, g_ginL);
    cudaGetSymbolAddress((void**)&ocH,  g_ocH);
    cudaGetSymbolAddress((void**)&ocL,  g_ocL);
    cudaGetSymbolAddress((void**)&wtH,  g_wtH);
    cudaGetSymbolAddress((void**)&wtL,  g_wtL);

    cudaFuncSetAttribute(precompute_kernel, cudaFuncAttributeMaxDynamicSharedMemorySize, PRE_SMEM);
    cudaFuncSetAttribute(scan_kernel,       cudaFuncAttributeMaxDynamicSharedMemorySize, SCAN_SMEM);

    // ---- splits (inputs + weights) ----
    split_launch(hs, hsH, hsL, (size_t)BL*Dd);
    split_launch(qw, wtH + WOFF_Q,  wtL + WOFF_Q,  (size_t)1024*1024);
    split_launch(kw, wtH + WOFF_K,  wtL + WOFF_K,  (size_t)1024*1024);
    split_launch(vw, wtH + WOFF_V,  wtL + WOFF_V,  (size_t)1024*1024);
    split_launch(w1, wtH + WOFF_W1, wtL + WOFF_W1, (size_t)GHID*GIN);
    split_launch(ow, wtH + WOFF_O,  wtL + WOFF_O,  (size_t)Dd*HD);

    const dim3 gemmGrid(HD/128, BL/128);   // (8, 64)

    hgemm_nt<false><<<gemmGrid, 256>>>(hsH, hsL, wtH+WOFF_Q, wtL+WOFF_Q, xq, BL, HD, Dd, nullptr);
    hgemm_nt<false><<<gemmGrid, 256>>>(hsH, hsL, wtH+WOFF_K, wtL+WOFF_K, xk, BL, HD, Dd, nullptr);
    hgemm_nt<false><<<gemmGrid, 256>>>(hsH, hsL, wtH+WOFF_V, wtL+WOFF_V, xv, BL, HD, Dd, nullptr);
    beta_kernel<<<BL, 128>>>(hs, bw, beta);
    conv_silu_norm<<<BL, 256>>>(xq, xk, xv, qcw, kcw, vcw, q, k, v);
    precompute_kernel<<<Bb*Hh*NCc, 256, PRE_SMEM>>>(q, k, v, beta, u, w, attn);
    scan_kernel<<<Bb*Hh*16, 256, SCAN_SMEM>>>(q, k, u, w, attn, delta);
    fir_gatein_kernel<<<Bb*(Ll/8), 256>>>(hs, v, fsw, flw, delta, shrt, lng, gin);
    split_launch(gin, ginH, ginL, (size_t)BL*GIN);
    hgemm_nt<true><<<gemmGrid, 256>>>(ginH, ginL, wtH+WOFF_W1, wtL+WOFF_W1, gh, BL, GHID, GIN, b1);
    gate2_wgt<<<BL, 128>>>(gh, w2, b2, lt, wgt);
    combine_kernel<<<BL, 256>>>(shrt, lng, delta, v, wgt, onw, ocomb);
    split_launch(ocomb, ocH, ocL, (size_t)BL*HD);
    hgemm_nt<false><<<gemmGrid, 256>>>(ocH, ocL, wtH+WOFF_O, wtL+WOFF_O, out, BL, Dd, HD, nullptr);
}

// round 3
// speedup vs baseline: 1.4808x; 1.0093x over previous
#include <cuda_runtime.h>
#include <cuda_bf16.h>
#include <math.h>

// ---------------- problem constants ----------------
#define Bb   2
#define Ll   4096
#define Dd   1024
#define Hh   4
#define DKk  256
#define DVv  256
#define CSs  32
#define NCc  128          // L / CS
#define BL   (Bb*Ll)      // 8192
#define HD   1024         // H*DK = H*DV
#define GIN  1792
#define GHID 1024

// ---------------- scratch (device globals; no runtime alloc) ----------------
__device__ float g_xq[BL*HD];
__device__ float g_xk[BL*HD];
__device__ float g_xv[BL*HD];
__device__ float g_q [BL*HD];
__device__ float g_k [BL*HD];
__device__ float g_v [BL*HD];
__device__ float g_u [Bb*Hh*Ll*DVv];
__device__ float g_w [Bb*Hh*Ll*DVv];
__device__ float g_attn[Bb*Hh*NCc*CSs*CSs];
__device__ float g_delta[BL*HD];
__device__ float g_short[BL*HD];
__device__ float g_long [BL*HD];
__device__ float g_gin[BL*GIN];
__device__ float g_gh [BL*GHID];
__device__ float g_beta[BL*Hh];
__device__ float g_wgt [BL*4];
__device__ float g_ocomb[BL*HD];

// bf16 hi/lo split buffers
__device__ __align__(16) __nv_bfloat16 g_hsH[BL*Dd];
__device__ __align__(16) __nv_bfloat16 g_hsL[BL*Dd];
__device__ __align__(16) __nv_bfloat16 g_ginH[BL*GIN];
__device__ __align__(16) __nv_bfloat16 g_ginL[BL*GIN];
__device__ __align__(16) __nv_bfloat16 g_ocH[BL*HD];
__device__ __align__(16) __nv_bfloat16 g_ocL[BL*HD];
// weights: qw(1M) kw(1M) vw(1M) w1(1792*1024) ow(1M)
#define WOFF_Q  0
#define WOFF_K  (1024*1024)
#define WOFF_V  (2*1024*1024)
#define WOFF_W1 (3*1024*1024)
#define WOFF_O  (3*1024*1024 + 1792*1024)
#define WTOT    (WOFF_O + 1024*1024)
__device__ __align__(16) __nv_bfloat16 g_wtH[WTOT];
__device__ __align__(16) __nv_bfloat16 g_wtL[WTOT];

// ---------------- helpers ----------------
__device__ __forceinline__ float siluf(float x){ return x / (1.f + expf(-x)); }
__device__ __forceinline__ float geluf(float x){ return 0.5f * x * (1.f + erff(x * 0.70710678118654752f)); }

__device__ __forceinline__ void ldsm4(unsigned* r, unsigned addr){
    asm volatile("ldmatrix.sync.aligned.m8n8.x4.shared.b16 {%0,%1,%2,%3}, [%4];"
        : "=r"(r[0]),"=r"(r[1]),"=r"(r[2]),"=r"(r[3]) : "r"(addr));
}
__device__ __forceinline__ void mma16816(float* c, const unsigned* a, const unsigned* b){
    asm volatile("mma.sync.aligned.m16n8k16.row.col.f32.bf16.bf16.f32 "
        "{%0,%1,%2,%3}, {%4,%5,%6,%7}, {%8,%9}, {%0,%1,%2,%3};"
        : "+f"(c[0]),"+f"(c[1]),"+f"(c[2]),"+f"(c[3])
        : "r"(a[0]),"r"(a[1]),"r"(a[2]),"r"(a[3]), "r"(b[0]),"r"(b[1]));
}

// ---------------- fp32 -> (hi,lo) bf16 split ----------------
__global__ void split_kernel(const float4* __restrict__ x, uint2* __restrict__ hi,
                             uint2* __restrict__ lo, int n4)
{
    int i = blockIdx.x*blockDim.x + threadIdx.x;
    if (i >= n4) return;
    float4 v = x[i];
    __nv_bfloat16 h0=__float2bfloat16(v.x), h1=__float2bfloat16(v.y),
                  h2=__float2bfloat16(v.z), h3=__float2bfloat16(v.w);
    __nv_bfloat16 l0=__float2bfloat16(v.x-__bfloat162float(h0));
    __nv_bfloat16 l1=__float2bfloat16(v.y-__bfloat162float(h1));
    __nv_bfloat16 l2=__float2bfloat16(v.z-__bfloat162float(h2));
    __nv_bfloat16 l3=__float2bfloat16(v.w-__bfloat162float(h3));
    __nv_bfloat162 hp0{h0,h1}, hp1{h2,h3}, lp0{l0,l1}, lp1{l2,l3};
    uint2 ho, loo;
    ho.x = *(unsigned*)&hp0; ho.y = *(unsigned*)&hp1;
    loo.x = *(unsigned*)&lp0; loo.y = *(unsigned*)&lp1;
    hi[i] = ho; lo[i] = loo;
}

// ---------------- bf16x3 split GEMM: C[M,N] = A[M,K]*B[N,K]^T (fp32-grade) ----------
// CTA 128x128, k-step 16, 8 warps (2x4), warp tile 64x32.
template<bool EPI>
__global__ void __launch_bounds__(256) hgemm_nt(const __nv_bfloat16* __restrict__ Ah,
                                                const __nv_bfloat16* __restrict__ Al,
                                                const __nv_bfloat16* __restrict__ Bh,
                                                const __nv_bfloat16* __restrict__ Bl,
                                                float* __restrict__ C,
                                                int M, int N, int K,
                                                const float* __restrict__ bias)
{
    __shared__ __align__(16) __nv_bfloat16 sm[4*128*24];  // Ah,Al,Bh,Bl planes
    const int PL = 128*24;
    __nv_bfloat16* sAh = sm;
    __nv_bfloat16* sAl = sm + PL;
    __nv_bfloat16* sBh = sm + 2*PL;
    __nv_bfloat16* sBl = sm + 3*PL;

    const int tid = threadIdx.x;
    const int bm = blockIdx.y*128, bn = blockIdx.x*128;
    const int warp = tid>>5, lane = tid&31;
    const int wm = warp>>2, wn = warp&3;

    float acc[4][4][4];
    #pragma unroll
    for (int i=0;i<4;i++) for(int j=0;j<4;j++) for(int r=0;r<4;r++) acc[i][j][r]=0.f;

    // gmem load: thread -> (row = tid>>1, 16B chunk = tid&1)
    const size_t aoff = (size_t)(bm + (tid>>1))*K + (tid&1)*8;
    const size_t boff = (size_t)(bn + (tid>>1))*K + (tid&1)*8;
    const int sto = (tid>>1)*24 + (tid&1)*8;

    // ldmatrix addresses (byte, shared space)
    unsigned base = (unsigned)__cvta_generic_to_shared(sm);
    // A: row = wm*64 + mt*16 + (lane&15), col = (lane>>4)*8
    const int arow = wm*64 + (lane&15);
    const int acol = (lane>>4)*8;
    // B: row = wn*32 + ng*16 + ((lane>>4)&1)*8 + (lane&7), col = ((lane>>3)&1)*8
    const int brow = wn*32 + ((lane>>4)&1)*8 + (lane&7);
    const int bcol = ((lane>>3)&1)*8;

    const int nk = K >> 4;
    uint4 rAh, rAl, rBh, rBl;
    rAh = *(const uint4*)(Ah + aoff);
    rAl = *(const uint4*)(Al + aoff);
    rBh = *(const uint4*)(Bh + boff);
    rBl = *(const uint4*)(Bl + boff);

    for (int kt = 0; kt < nk; ++kt) {
        __syncthreads();
        *(uint4*)(sAh + sto) = rAh;
        *(uint4*)(sAl + sto) = rAl;
        *(uint4*)(sBh + sto) = rBh;
        *(uint4*)(sBl + sto) = rBl;
        __syncthreads();
        if (kt + 1 < nk) {
            const size_t ka = aoff + (size_t)(kt+1)*16;
            const size_t kb = boff + (size_t)(kt+1)*16;
            rAh = *(const uint4*)(Ah + ka);
            rAl = *(const uint4*)(Al + ka);
            rBh = *(const uint4*)(Bh + kb);
            rBl = *(const uint4*)(Bl + kb);
        }
        // B fragments (4 n-tiles: bh[nt][2], bl[nt][2])
        unsigned bh[4][2], bl[4][2];
        #pragma unroll
        for (int ng = 0; ng < 2; ++ng) {
            unsigned r4[4];
            unsigned addr = base + 2u*(2*PL + (brow + ng*16)*24 + bcol);
            ldsm4(r4, addr);
            bh[2*ng][0]=r4[0]; bh[2*ng][1]=r4[1]; bh[2*ng+1][0]=r4[2]; bh[2*ng+1][1]=r4[3];
            addr = base + 2u*(3*PL + (brow + ng*16)*24 + bcol);
            ldsm4(r4, addr);
            bl[2*ng][0]=r4[0]; bl[2*ng][1]=r4[1]; bl[2*ng+1][0]=r4[2]; bl[2*ng+1][1]=r4[3];
        }
        #pragma unroll
        for (int mt = 0; mt < 4; ++mt) {
            unsigned ah[4], al[4];
            unsigned addr = base + 2u*((arow + mt*16)*24 + acol);
            ldsm4(ah, addr);
            addr = base + 2u*(PL + (arow + mt*16)*24 + acol);
            ldsm4(al, addr);
            #pragma unroll
            for (int nt = 0; nt < 4; ++nt) {
                mma16816(acc[mt][nt], ah, bh[nt]);
                mma16816(acc[mt][nt], ah, bl[nt]);
                mma16816(acc[mt][nt], al, bh[nt]);
            }
        }
    }

    // epilogue
    const int g = lane>>2, tig = lane&3;
    #pragma unroll
    for (int mt = 0; mt < 4; ++mt) {
        const int row0 = bm + wm*64 + mt*16 + g;
        #pragma unroll
        for (int nt = 0; nt < 4; ++nt) {
            const int col = bn + wn*32 + nt*8 + tig*2;
            float v0 = acc[mt][nt][0], v1 = acc[mt][nt][1];
            float v2 = acc[mt][nt][2], v3 = acc[mt][nt][3];
            if (EPI) {
                const float bz0 = bias[col], bz1 = bias[col+1];
                v0 = geluf(v0+bz0); v1 = geluf(v1+bz1);
                v2 = geluf(v2+bz0); v3 = geluf(v3+bz1);
            }
            *(float2*)(C + (size_t)row0*N + col)     = make_float2(v0, v1);
            *(float2*)(C + (size_t)(row0+8)*N + col) = make_float2(v2, v3);
        }
    }
}

// ---------------- beta = sigmoid(hs @ b_proj^T) ----------------
__global__ void beta_kernel(const float* __restrict__ hs, const float* __restrict__ bw,
                            float* __restrict__ beta)
{
    const int row = blockIdx.x;
    const int warp = threadIdx.x >> 5, lane = threadIdx.x & 31;
    const float* x = hs + (size_t)row * Dd;
    const float* w = bw + warp * Dd;
    float s = 0.f;
    for (int i = lane; i < Dd; i += 32) s += x[i] * w[i];
    #pragma unroll
    for (int o = 16; o; o >>= 1) s += __shfl_xor_sync(0xffffffff, s, o);
    if (lane == 0) beta[row*4 + warp] = 1.f / (1.f + expf(-s));
}

// ---------------- causal conv(k=4) + silu + (q,k: per-head l2norm) ----------------
__global__ void conv_silu_norm(const float* __restrict__ XQ, const float* __restrict__ XK,
                               const float* __restrict__ XV,
                               const float* __restrict__ WQ, const float* __restrict__ WK,
                               const float* __restrict__ WV,
                               float* __restrict__ Qo, float* __restrict__ Ko,
                               float* __restrict__ Vo)
{
    const int row = blockIdx.x;
    const int b = row >> 12, l = row & (Ll-1);
    const int tid = threadIdx.x;
    const int lane = tid & 31;
    __shared__ float redq[4], redk[4];
    if (tid < 4) { redq[tid] = 0.f; redk[tid] = 0.f; }
    __syncthreads();

    float yq[4], yk[4];
    #pragma unroll
    for (int j = 0; j < 4; ++j) {
        const int c = tid + 256*j;
        float aq=0.f, ak=0.f, av=0.f;
        #pragma unroll
        for (int t = 0; t < 4; ++t) {
            const int ll = l - 3 + t;
            if (ll >= 0) {
                const size_t g = ((size_t)(b*Ll + ll))*HD + c;
                aq += XQ[g]*WQ[c*4+t];
                ak += XK[g]*WK[c*4+t];
                av += XV[g]*WV[c*4+t];
            }
        }
        aq = siluf(aq); ak = siluf(ak); av = siluf(av);
        Vo[(size_t)row*HD + c] = av;
        yq[j] = aq; yk[j] = ak;
        float vq = aq*aq, vk = ak*ak;
        #pragma unroll
        for (int o = 16; o; o >>= 1) {
            vq += __shfl_xor_sync(0xffffffff, vq, o);
            vk += __shfl_xor_sync(0xffffffff, vk, o);
        }
        if (lane == 0) { atomicAdd(&redq[j], vq); atomicAdd(&redk[j], vk); }
    }
    __syncthreads();
    #pragma unroll
    for (int j = 0; j < 4; ++j) {
        const int c = tid + 256*j;
        const float rq = rsqrtf(redq[j] + 1e-12f);
        const float rk = rsqrtf(redk[j] + 1e-12f);
        Qo[(size_t)row*HD + c] = yq[j]*rq;
        Ko[(size_t)row*HD + c] = yk[j]*rk;
    }
}

// ---------------- per-chunk precompute: A, Tinv, u, w, attn ----------------
#define PRE_SMEM ((3*32*257 + 1024 + 1024 + 32) * 4)
__global__ void precompute_kernel(const float* __restrict__ Qn, const float* __restrict__ Kn,
                                  const float* __restrict__ V,  const float* __restrict__ beta,
                                  float* __restrict__ U, float* __restrict__ W,
                                  float* __restrict__ Attn)
{
    extern __shared__ float sm[];
    float* sq = sm;
    float* sk = sq + 32*257;
    float* sv = sk + 32*257;
    float* Am = sv + 32*257;
    float* Ti = Am + 1024;
    float* sb = Ti + 1024;

    const int idx = blockIdx.x;
    const int bh = idx / NCc, ci = idx % NCc;
    const int b = bh >> 2, h = bh & 3;
    const int tid = threadIdx.x;

    for (int e = tid; e < 32*256; e += 256) {
        const int i = e >> 8, d = e & 255;
        const size_t g = ((size_t)(b*Ll + ci*CSs + i))*HD + h*256 + d;
        sq[i*257+d] = Qn[g];
        sk[i*257+d] = Kn[g];
        sv[i*257+d] = V[g];
    }
    if (tid < 32) sb[tid] = beta[(size_t)(b*Ll + ci*CSs + tid)*4 + h];
    __syncthreads();
    for (int e = tid; e < 32*256; e += 256) {
        const int i = e >> 8, d = e & 255;
        sv[i*257+d] *= sb[i];
    }
    for (int p = tid; p < 1024; p += 256) {
        const int i = p >> 5, j = p & 31;
        const float* ki = sk + i*257;
        const float* kj = sk + j*257;
        const float* qi = sq + i*257;
        float dkk = 0.f, dqk = 0.f;
        #pragma unroll 8
        for (int d = 0; d < 256; ++d) {
            const float kv = kj[d];
            dkk += ki[d]*kv;
            dqk += qi[d]*kv;
        }
        Am[p] = (i > j) ? sb[i]*dkk : 0.f;
        Attn[(size_t)(bh*NCc + ci)*1024 + p] = (i >= j) ? dqk : 0.f;
    }
    __syncthreads();
    if (tid < 32) {
        const int j = tid;
        Ti[j] = (j == 0) ? 1.f : 0.f;
        for (int i2 = 1; i2 < 32; ++i2) {
            __syncwarp();
            float s = 0.f;
            for (int m = 0; m < i2; ++m) s += Am[i2*32+m]*Ti[m*32+j];
            Ti[i2*32+j] = ((i2 == j) ? 1.f : 0.f) - s;
        }
    }
    __syncthreads();
    for (int e = tid; e < 32*256; e += 256) {
        const int i = e >> 8, d = e & 255;
        float uu = 0.f, ww = 0.f;
        #pragma unroll
        for (int m = 0; m < 32; ++m) {
            const float t = Ti[i*32+m];
            uu += t * sv[m*257+d];
            ww += t * sb[m] * sk[m*257+d];
        }
        const size_t gb = (size_t)(bh*NCc + ci)*8192 + i*256 + d;
        U[gb] = uu; W[gb] = ww;
    }
}

// ---------------- sequential scan over chunks, dv split into 16-col blocks --------
#define SCAN_SMEM ((256*17 + 3*32*256 + 512 + 512 + 1024) * 4)
__global__ void __launch_bounds__(256) scan_kernel(const float* __restrict__ Qn,
                                                   const float* __restrict__ Kn,
                                                   const float* __restrict__ U,
                                                   const float* __restrict__ W,
                                                   const float* __restrict__ Attn,
                                                   float* __restrict__ Out)
{
    extern __shared__ float sm[];
    float* sS  = sm;
    float* sq  = sS + 256*17;
    float* sk  = sq + 8192;
    float* sw  = sk + 8192;
    float* su  = sw + 8192;
    float* sun = su + 512;
    float* sa  = sun + 512;

    const int idx = blockIdx.x;
    const int bh = idx >> 4, cb = idx & 15;
    const int b = bh >> 2, h = bh & 3;
    const int tid = threadIdx.x;

    for (int e = tid; e < 256*17; e += 256) sS[e] = 0.f;
    __syncthreads();

    const int c  = tid & 15;
    const int i2 = tid >> 4;
    const int uc = tid & 15;
    const int rb = (tid >> 4) * 16;

    for (int ci = 0; ci < NCc; ++ci) {
        const size_t cbase = (size_t)(bh*NCc + ci);
        for (int e = tid; e < 32*256; e += 256) {
            const int i = e >> 8, d = e & 255;
            const size_t g = ((size_t)(b*Ll + ci*CSs + i))*HD + h*256 + d;
            sq[e] = Qn[g];
            sk[e] = Kn[g];
            sw[e] = W[cbase*8192 + e];
        }
        for (int e = tid; e < 512; e += 256) {
            const int i = e >> 4, cc = e & 15;
            su[e] = U[cbase*8192 + i*256 + cb*16 + cc];
        }
        for (int e = tid; e < 1024; e += 256) sa[e] = Attn[cbase*1024 + e];
        __syncthreads();

        {
            float a0 = su[i2*16 + c], a1 = su[(i2+16)*16 + c];
            const float* w0 = sw + i2*256;
            const float* w1 = w0 + 16*256;
            #pragma unroll 8
            for (int r = 0; r < 256; r += 4) {
                const float4 wa = *(const float4*)(w0 + r);
                const float4 wb = *(const float4*)(w1 + r);
                const float s0 = sS[(r+0)*17 + c];
                const float s1 = sS[(r+1)*17 + c];
                const float s2 = sS[(r+2)*17 + c];
                const float s3 = sS[(r+3)*17 + c];
                a0 -= wa.x*s0 + wa.y*s1 + wa.z*s2 + wa.w*s3;
                a1 -= wb.x*s0 + wb.y*s1 + wb.z*s2 + wb.w*s3;
            }
            sun[i2*16 + c] = a0;
            sun[(i2+16)*16 + c] = a1;
        }
        __syncthreads();

        {
            float o0 = 0.f, o1 = 0.f;
            const float* q0 = sq + i2*256;
            const float* q1 = q0 + 16*256;
            #pragma unroll 8
            for (int r = 0; r < 256; r += 4) {
                const float4 qa = *(const float4*)(q0 + r);
                const float4 qb = *(const float4*)(q1 + r);
                const float s0 = sS[(r+0)*17 + c];
                const float s1 = sS[(r+1)*17 + c];
                const float s2 = sS[(r+2)*17 + c];
                const float s3 = sS[(r+3)*17 + c];
                o0 += qa.x*s0 + qa.y*s1 + qa.z*s2 + qa.w*s3;
                o1 += qb.x*s0 + qb.y*s1 + qb.z*s2 + qb.w*s3;
            }
            #pragma unroll
            for (int j = 0; j < 32; ++j) {
                const float uu = sun[j*16 + c];
                o0 += sa[i2*32 + j] * uu;
                o1 += sa[(i2+16)*32 + j] * uu;
            }
            const size_t go = ((size_t)(b*Ll + ci*CSs + i2))*HD + h*256 + cb*16 + c;
            Out[go] = o0;
            Out[go + (size_t)16*HD] = o1;
        }
        __syncthreads();

        {
            float accS[16];
            #pragma unroll
            for (int rr = 0; rr < 16; ++rr) accS[rr] = sS[(rb+rr)*17 + uc];
            #pragma unroll
            for (int i = 0; i < 32; ++i) {
                const float uu = sun[i*16 + uc];
                const float* kr = sk + i*256 + rb;
                #pragma unroll
                for (int rr = 0; rr < 16; rr += 4) {
                    const float4 kv = *(const float4*)(kr + rr);
                    accS[rr+0] += kv.x*uu;
                    accS[rr+1] += kv.y*uu;
                    accS[rr+2] += kv.z*uu;
                    accS[rr+3] += kv.w*uu;
                }
            }
            #pragma unroll
            for (int rr = 0; rr < 16; ++rr) sS[(rb+rr)*17 + uc] = accS[rr];
        }
        __syncthreads();
    }
}

// ---------------- FIR short/long + gate_in assembly ----------------
__global__ void fir_gatein_kernel(const float* __restrict__ hs, const float* __restrict__ V,
                                  const float* __restrict__ ws, const float* __restrict__ wl,
                                  const float* __restrict__ Dl,
                                  float* __restrict__ Sout, float* __restrict__ Lout,
                                  float* __restrict__ Gin)
{
    const int blk = blockIdx.x;
    const int b = blk / (Ll/8);
    const int l0 = (blk % (Ll/8)) * 8;
    const int tid = threadIdx.x;

    float smean[8], lmean[8], dmean[8];
    #pragma unroll
    for (int r = 0; r < 8; ++r) { smean[r]=0.f; lmean[r]=0.f; dmean[r]=0.f; }

    for (int j = 0; j < 4; ++j) {
        const int ch = tid + 256*j;
        float win[38];
        #pragma unroll
        for (int t = 0; t < 38; ++t) {
            const int l = l0 - 30 + t;
            win[t] = (l >= 0) ? V[((size_t)(b*Ll + l))*HD + ch] : 0.f;
        }
        float wlr[31];
        #pragma unroll
        for (int t = 0; t < 31; ++t) wlr[t] = wl[ch*31 + t];
        const float w0 = ws[ch*3+0], w1 = ws[ch*3+1], w2 = ws[ch*3+2];
        #pragma unroll
        for (int r = 0; r < 8; ++r) {
            float yl = 0.f;
            #pragma unroll
            for (int t = 0; t < 31; ++t) yl += win[r+t]*wlr[t];
            const float ysv = win[r+28]*w0 + win[r+29]*w1 + win[r+30]*w2;
            const size_t row = (size_t)(b*Ll + l0 + r);
            Sout[row*HD + ch] = ysv;
            Lout[row*HD + ch] = yl;
            smean[r] += ysv; lmean[r] += yl;
            dmean[r] += Dl[row*HD + ch];
        }
    }
    for (int r = 0; r < 8; ++r) {
        const size_t row = (size_t)(b*Ll + l0 + r);
        float* grow = Gin + row*GIN;
        #pragma unroll
        for (int j = 0; j < 4; ++j) grow[tid + 256*j] = hs[row*HD + tid + 256*j];
        grow[1024 + tid] = smean[r]*0.25f;
        grow[1280 + tid] = lmean[r]*0.25f;
        grow[1536 + tid] = dmean[r]*0.25f;
    }
}

// ---------------- gate head 2 + softmax/floor -> weights [b,l,4] ----------------
__global__ void gate2_wgt(const float* __restrict__ GH2, const float* __restrict__ W2,
                          const float* __restrict__ b2, const float* __restrict__ ltemp,
                          float* __restrict__ Wgt)
{
    const int row = blockIdx.x;
    const int warp = threadIdx.x >> 5, lane = threadIdx.x & 31;
    __shared__ float lg[4];
    const float* x = GH2 + (size_t)row*GHID;
    const float* w = W2 + warp*GHID;
    float s = 0.f;
    for (int i = lane; i < GHID; i += 32) s += x[i]*w[i];
    #pragma unroll
    for (int o = 16; o; o >>= 1) s += __shfl_xor_sync(0xffffffff, s, o);
    if (lane == 0) lg[warp] = s + b2[warp];
    __syncthreads();
    if (threadIdx.x == 0) {
        const float t = log1pf(expf(ltemp[0])) + 1e-4f;
        float m = fmaxf(fmaxf(lg[0], lg[1]), fmaxf(lg[2], lg[3]));
        float e[4]; float se = 0.f;
        #pragma unroll
        for (int j = 0; j < 4; ++j) { e[j] = expf((lg[j]-m)/t); se += e[j]; }
        #pragma unroll
        for (int j = 0; j < 4; ++j) e[j] /= se;
        const float fl = 0.05f * e[3];
        e[0] = fmaxf(e[0], fl);
        e[1] = fmaxf(e[1], fl);
        const float s2 = e[0]+e[1]+e[2]+e[3];
        #pragma unroll
        for (int j = 0; j < 4; ++j) Wgt[row*4+j] = e[j]/s2;
    }
}

// ---------------- weighted combine + per-head RMSNorm ----------------
__global__ void combine_kernel(const float* __restrict__ Sh, const float* __restrict__ Lg,
                               const float* __restrict__ Dl, const float* __restrict__ V,
                               const float* __restrict__ Wgt, const float* __restrict__ onw,
                               float* __restrict__ O)
{
    const int row = blockIdx.x;
    const int tid = threadIdx.x, lane = tid & 31;
    __shared__ float red[4];
    if (tid < 4) red[tid] = 0.f;
    __syncthreads();
    const float w0 = Wgt[row*4+0], w1 = Wgt[row*4+1], w2 = Wgt[row*4+2], w3 = Wgt[row*4+3];
    float ov[4];
    #pragma unroll
    for (int j = 0; j < 4; ++j) {
        const size_t g = (size_t)row*HD + tid + 256*j;
        ov[j] = w0*Sh[g] + w1*Lg[g] + w2*Dl[g] + w3*V[g];
        float v = ov[j]*ov[j];
        #pragma unroll
        for (int o = 16; o; o >>= 1) v += __shfl_xor_sync(0xffffffff, v, o);
        if (lane == 0) atomicAdd(&red[j], v);
    }
    __syncthreads();
    #pragma unroll
    for (int j = 0; j < 4; ++j) {
        const float sc = rsqrtf(red[j]*(1.f/256.f) + 1e-5f) * onw[tid];
        O[(size_t)row*HD + tid + 256*j] = ov[j]*sc;
    }
}

// ---------------- launch ----------------
static inline void split_launch(const float* x, __nv_bfloat16* hi, __nv_bfloat16* lo, size_t n)
{
    int n4 = (int)(n >> 2);
    split_kernel<<<(n4 + 255)/256, 256>>>((const float4*)x, (uint2*)hi, (uint2*)lo, n4);
}

extern "C" void kernel_launch(void* const* d_in, const int* in_sizes, int n_in,
                              void* d_out, int out_size)
{
    const float* hs  = (const float*)d_in[0];
    const float* qw  = (const float*)d_in[1];
    const float* kw  = (const float*)d_in[2];
    const float* vw  = (const float*)d_in[3];
    const float* bw  = (const float*)d_in[4];
    const float* qcw = (const float*)d_in[5];
    const float* kcw = (const float*)d_in[6];
    const float* vcw = (const float*)d_in[7];
    const float* fsw = (const float*)d_in[8];
    const float* flw = (const float*)d_in[9];
    const float* w1  = (const float*)d_in[10];
    const float* b1  = (const float*)d_in[11];
    const float* w2  = (const float*)d_in[12];
    const float* b2  = (const float*)d_in[13];
    const float* lt  = (const float*)d_in[14];
    const float* onw = (const float*)d_in[15];
    const float* ow  = (const float*)d_in[16];
    float* out = (float*)d_out;

    float *xq,*xk,*xv,*q,*k,*v,*u,*w,*attn,*delta,*shrt,*lng,*gin,*gh,*beta,*wgt,*ocomb;
    __nv_bfloat16 *hsH,*hsL,*ginH,*ginL,*ocH,*ocL,*wtH,*wtL;
    cudaGetSymbolAddress((void**)&xq,   g_xq);
    cudaGetSymbolAddress((void**)&xk,   g_xk);
    cudaGetSymbolAddress((void**)&xv,   g_xv);
    cudaGetSymbolAddress((void**)&q,    g_q);
    cudaGetSymbolAddress((void**)&k,    g_k);
    cudaGetSymbolAddress((void**)&v,    g_v);
    cudaGetSymbolAddress((void**)&u,    g_u);
    cudaGetSymbolAddress((void**)&w,    g_w);
    cudaGetSymbolAddress((void**)&attn, g_attn);
    cudaGetSymbolAddress((void**)&delta,g_delta);
    cudaGetSymbolAddress((void**)&shrt, g_short);
    cudaGetSymbolAddress((void**)&lng,  g_long);
    cudaGetSymbolAddress((void**)&gin,  g_gin);
    cudaGetSymbolAddress((void**)&gh,   g_gh);
    cudaGetSymbolAddress((void**)&beta, g_beta);
    cudaGetSymbolAddress((void**)&wgt,  g_wgt);
    cudaGetSymbolAddress((void**)&ocomb,g_ocomb);
    cudaGetSymbolAddress((void**)&hsH,  g_hsH);
    cudaGetSymbolAddress((void**)&hsL,  g_hsL);
    cudaGetSymbolAddress((void**)&ginH, g_ginH);
    cudaGetSymbolAddress((void**)&ginL, g_ginL);
    cudaGetSymbolAddress((void**)&ocH,  g_ocH);
    cudaGetSymbolAddress((void**)&ocL,  g_ocL);
    cudaGetSymbolAddress((void**)&wtH,  g_wtH);
    cudaGetSymbolAddress((void**)&wtL,  g_wtL);

    cudaFuncSetAttribute(precompute_kernel, cudaFuncAttributeMaxDynamicSharedMemorySize, PRE_SMEM);
    cudaFuncSetAttribute(scan_kernel,       cudaFuncAttributeMaxDynamicSharedMemorySize, SCAN_SMEM);

    // ---- splits (inputs + weights) ----
    split_launch(hs, hsH, hsL, (size_t)BL*Dd);
    split_launch(qw, wtH + WOFF_Q,  wtL + WOFF_Q,  (size_t)1024*1024);
    split_launch(kw, wtH + WOFF_K,  wtL + WOFF_K,  (size_t)1024*1024);
    split_launch(vw, wtH + WOFF_V,  wtL + WOFF_V,  (size_t)1024*1024);
    split_launch(w1, wtH + WOFF_W1, wtL + WOFF_W1, (size_t)GHID*GIN);
    split_launch(ow, wtH + WOFF_O,  wtL + WOFF_O,  (size_t)Dd*HD);

    const dim3 gemmGrid(HD/128, BL/128);   // (8, 64)

    hgemm_nt<false><<<gemmGrid, 256>>>(hsH, hsL, wtH+WOFF_Q, wtL+WOFF_Q, xq, BL, HD, Dd, nullptr);
    hgemm_nt<false><<<gemmGrid, 256>>>(hsH, hsL, wtH+WOFF_K, wtL+WOFF_K, xk, BL, HD, Dd, nullptr);
    hgemm_nt<false><<<gemmGrid, 256>>>(hsH, hsL, wtH+WOFF_V, wtL+WOFF_V, xv, BL, HD, Dd, nullptr);
    beta_kernel<<<BL, 128>>>(hs, bw, beta);
    conv_silu_norm<<<BL, 256>>>(xq, xk, xv, qcw, kcw, vcw, q, k, v);
    precompute_kernel<<<Bb*Hh*NCc, 256, PRE_SMEM>>>(q, k, v, beta, u, w, attn);
    scan_kernel<<<Bb*Hh*16, 256, SCAN_SMEM>>>(q, k, u, w, attn, delta);
    fir_gatein_kernel<<<Bb*(Ll/8), 256>>>(hs, v, fsw, flw, delta, shrt, lng, gin);
    split_launch(gin, ginH, ginL, (size_t)BL*GIN);
    hgemm_nt<true><<<gemmGrid, 256>>>(ginH, ginL, wtH+WOFF_W1, wtL+WOFF_W1, gh, BL, GHID, GIN, b1);
    gate2_wgt<<<BL, 128>>>(gh, w2, b2, lt, wgt);
    combine_kernel<<<BL, 256>>>(shrt, lng, delta, v, wgt, onw, ocomb);
    split_launch(ocomb, ocH, ocL, (size_t)BL*HD);
    hgemm_nt<false><<<gemmGrid, 256>>>(ocH, ocL, wtH+WOFF_O, wtL+WOFF_O, out, BL, Dd, HD, nullptr);
}

// round 4
// speedup vs baseline: 2.7750x; 1.8739x over previous
#include <cuda_runtime.h>
#include <cuda_bf16.h>
#include <math.h>

#define Bb   2
#define Ll   4096
#define Dd   1024
#define Hh   4
#define CSs  32
#define NCc  128
#define BL   (Bb*Ll)
#define HD   1024
#define GIN  1792
#define GHID 1024
#define CH8  (8*NCc*8192)

// ---------------- scratch ----------------
__device__ float g_xq[BL*HD];
__device__ float g_xk[BL*HD];
__device__ float g_xv[BL*HD];
__device__ float g_q [BL*HD];
__device__ float g_k [BL*HD];
__device__ float g_v [BL*HD];
__device__ float g_u [CH8];
__device__ float g_delta[BL*HD];
__device__ float g_short[BL*HD];
__device__ float g_long [BL*HD];
__device__ float g_gin[BL*GIN];
__device__ float g_gh [BL*GHID];
__device__ float g_beta[BL*Hh];
__device__ float g_wgt [BL*4];
__device__ float g_ocomb[BL*HD];

__device__ __align__(16) __nv_bfloat16 g_hsH[BL*Dd];
__device__ __align__(16) __nv_bfloat16 g_hsL[BL*Dd];
__device__ __align__(16) __nv_bfloat16 g_ginH[BL*GIN];
__device__ __align__(16) __nv_bfloat16 g_ginL[BL*GIN];
__device__ __align__(16) __nv_bfloat16 g_ocH[BL*HD];
__device__ __align__(16) __nv_bfloat16 g_ocL[BL*HD];
#define WOFF_Q  0
#define WOFF_K  (1024*1024)
#define WOFF_V  (2*1024*1024)
#define WOFF_W1 (3*1024*1024)
#define WOFF_O  (3*1024*1024 + 1792*1024)
#define WTOT    (WOFF_O + 1024*1024)
__device__ __align__(16) __nv_bfloat16 g_wtH[WTOT];
__device__ __align__(16) __nv_bfloat16 g_wtL[WTOT];

// scan operand planes
__device__ __align__(16) __nv_bfloat16 g_qh[CH8], g_ql[CH8], g_wh[CH8], g_wl[CH8], g_kh[CH8], g_kl[CH8];
__device__ __align__(16) __nv_bfloat16 g_ah[8*NCc*1024], g_al[8*NCc*1024];

// ---------------- helpers ----------------
__device__ __forceinline__ float siluf(float x){ return x / (1.f + expf(-x)); }
__device__ __forceinline__ float geluf(float x){ return 0.5f * x * (1.f + erff(x * 0.70710678118654752f)); }
__device__ __forceinline__ void ldsm4(unsigned* r, unsigned addr){
    asm volatile("ldmatrix.sync.aligned.m8n8.x4.shared.b16 {%0,%1,%2,%3}, [%4];"
        : "=r"(r[0]),"=r"(r[1]),"=r"(r[2]),"=r"(r[3]) : "r"(addr));
}
__device__ __forceinline__ void ldsm2(unsigned* r, unsigned addr){
    asm volatile("ldmatrix.sync.aligned.m8n8.x2.shared.b16 {%0,%1}, [%2];"
        : "=r"(r[0]),"=r"(r[1]) : "r"(addr));
}
__device__ __forceinline__ void mma16816(float* c, const unsigned* a, const unsigned* b){
    asm volatile("mma.sync.aligned.m16n8k16.row.col.f32.bf16.bf16.f32 "
        "{%0,%1,%2,%3}, {%4,%5,%6,%7}, {%8,%9}, {%0,%1,%2,%3};"
        : "+f"(c[0]),"+f"(c[1]),"+f"(c[2]),"+f"(c[3])
        : "r"(a[0]),"r"(a[1]),"r"(a[2]),"r"(a[3]), "r"(b[0]),"r"(b[1]));
}
__device__ __forceinline__ void cpa16(unsigned d, const void* s){
    asm volatile("cp.async.cg.shared.global [%0],[%1],16;\n" :: "r"(d), "l"(s));
}
#define CP_COMMIT() asm volatile("cp.async.commit_group;\n")
#define CP_WAIT0()  asm volatile("cp.async.wait_group 0;\n")
__device__ __forceinline__ unsigned pack2(float a, float b){
    __nv_bfloat162 t; t.x=__float2bfloat16(a); t.y=__float2bfloat16(b);
    return *(unsigned*)&t;
}
__device__ __forceinline__ float res1(float v){ return v - __bfloat162float(__float2bfloat16(v)); }
__device__ __forceinline__ void split1(float v, __nv_bfloat16& h, __nv_bfloat16& l){
    h = __float2bfloat16(v); l = __float2bfloat16(v - __bfloat162float(h));
}

// ---------------- fp32 -> (hi,lo) bf16 split ----------------
__global__ void split_kernel(const float4* __restrict__ x, uint2* __restrict__ hi,
                             uint2* __restrict__ lo, int n4)
{
    int i = blockIdx.x*blockDim.x + threadIdx.x;
    if (i >= n4) return;
    float4 v = x[i];
    uint2 ho, loo;
    ho.x = pack2(v.x, v.y);  ho.y = pack2(v.z, v.w);
    loo.x = pack2(res1(v.x), res1(v.y)); loo.y = pack2(res1(v.z), res1(v.w));
    hi[i] = ho; lo[i] = loo;
}

// ---------------- bf16x3 split GEMM (unchanged, validated) ----------
template<bool EPI>
__global__ void __launch_bounds__(256) hgemm_nt(const __nv_bfloat16* __restrict__ Ah,
                                                const __nv_bfloat16* __restrict__ Al,
                                                const __nv_bfloat16* __restrict__ Bh,
                                                const __nv_bfloat16* __restrict__ Bl,
                                                float* __restrict__ C,
                                                int M, int N, int K,
                                                const float* __restrict__ bias)
{
    __shared__ __align__(16) __nv_bfloat16 sm[4*128*24];
    const int PL = 128*24;
    const int tid = threadIdx.x;
    const int bm = blockIdx.y*128, bn = blockIdx.x*128;
    const int warp = tid>>5, lane = tid&31;
    const int wm = warp>>2, wn = warp&3;
    float acc[4][4][4];
    #pragma unroll
    for (int i=0;i<4;i++) for(int j=0;j<4;j++) for(int r=0;r<4;r++) acc[i][j][r]=0.f;
    const size_t aoff = (size_t)(bm + (tid>>1))*K + (tid&1)*8;
    const size_t boff = (size_t)(bn + (tid>>1))*K + (tid&1)*8;
    const int sto = (tid>>1)*24 + (tid&1)*8;
    unsigned base = (unsigned)__cvta_generic_to_shared(sm);
    const int arow = wm*64 + (lane&15);
    const int acol = (lane>>4)*8;
    const int brow = wn*32 + ((lane>>4)&1)*8 + (lane&7);
    const int bcol = ((lane>>3)&1)*8;
    const int nk = K >> 4;
    uint4 rAh = *(const uint4*)(Ah + aoff);
    uint4 rAl = *(const uint4*)(Al + aoff);
    uint4 rBh = *(const uint4*)(Bh + boff);
    uint4 rBl = *(const uint4*)(Bl + boff);
    for (int kt = 0; kt < nk; ++kt) {
        __syncthreads();
        *(uint4*)(sm + sto) = rAh;
        *(uint4*)(sm + PL + sto) = rAl;
        *(uint4*)(sm + 2*PL + sto) = rBh;
        *(uint4*)(sm + 3*PL + sto) = rBl;
        __syncthreads();
        if (kt + 1 < nk) {
            const size_t ka = aoff + (size_t)(kt+1)*16;
            const size_t kb = boff + (size_t)(kt+1)*16;
            rAh = *(const uint4*)(Ah + ka); rAl = *(const uint4*)(Al + ka);
            rBh = *(const uint4*)(Bh + kb); rBl = *(const uint4*)(Bl + kb);
        }
        unsigned bh[4][2], bl[4][2];
        #pragma unroll
        for (int ng = 0; ng < 2; ++ng) {
            unsigned r4[4];
            ldsm4(r4, base + 2u*(2*PL + (brow + ng*16)*24 + bcol));
            bh[2*ng][0]=r4[0]; bh[2*ng][1]=r4[1]; bh[2*ng+1][0]=r4[2]; bh[2*ng+1][1]=r4[3];
            ldsm4(r4, base + 2u*(3*PL + (brow + ng*16)*24 + bcol));
            bl[2*ng][0]=r4[0]; bl[2*ng][1]=r4[1]; bl[2*ng+1][0]=r4[2]; bl[2*ng+1][1]=r4[3];
        }
        #pragma unroll
        for (int mt = 0; mt < 4; ++mt) {
            unsigned ah[4], al[4];
            ldsm4(ah, base + 2u*((arow + mt*16)*24 + acol));
            ldsm4(al, base + 2u*(PL + (arow + mt*16)*24 + acol));
            #pragma unroll
            for (int nt = 0; nt < 4; ++nt) {
                mma16816(acc[mt][nt], ah, bh[nt]);
                mma16816(acc[mt][nt], ah, bl[nt]);
                mma16816(acc[mt][nt], al, bh[nt]);
            }
        }
    }
    const int g = lane>>2, tig = lane&3;
    #pragma unroll
    for (int mt = 0; mt < 4; ++mt) {
        const int row0 = bm + wm*64 + mt*16 + g;
        #pragma unroll
        for (int nt = 0; nt < 4; ++nt) {
            const int col = bn + wn*32 + nt*8 + tig*2;
            float v0 = acc[mt][nt][0], v1 = acc[mt][nt][1];
            float v2 = acc[mt][nt][2], v3 = acc[mt][nt][3];
            if (EPI) {
                const float bz0 = bias[col], bz1 = bias[col+1];
                v0 = geluf(v0+bz0); v1 = geluf(v1+bz1);
                v2 = geluf(v2+bz0); v3 = geluf(v3+bz1);
            }
            *(float2*)(C + (size_t)row0*N + col)     = make_float2(v0, v1);
            *(float2*)(C + (size_t)(row0+8)*N + col) = make_float2(v2, v3);
        }
    }
}

// ---------------- beta ----------------
__global__ void beta_kernel(const float* __restrict__ hs, const float* __restrict__ bw,
                            float* __restrict__ beta)
{
    const int row = blockIdx.x;
    const int warp = threadIdx.x >> 5, lane = threadIdx.x & 31;
    const float* x = hs + (size_t)row * Dd;
    const float* w = bw + warp * Dd;
    float s = 0.f;
    for (int i = lane; i < Dd; i += 32) s += x[i] * w[i];
    #pragma unroll
    for (int o = 16; o; o >>= 1) s += __shfl_xor_sync(0xffffffff, s, o);
    if (lane == 0) beta[row*4 + warp] = 1.f / (1.f + expf(-s));
}

// ---------------- conv + silu + l2norm ----------------
__global__ void conv_silu_norm(const float* __restrict__ XQ, const float* __restrict__ XK,
                               const float* __restrict__ XV,
                               const float* __restrict__ WQ, const float* __restrict__ WK,
                               const float* __restrict__ WV,
                               float* __restrict__ Qo, float* __restrict__ Ko,
                               float* __restrict__ Vo)
{
    const int row = blockIdx.x;
    const int b = row >> 12, l = row & (Ll-1);
    const int tid = threadIdx.x;
    const int lane = tid & 31;
    __shared__ float redq[4], redk[4];
    if (tid < 4) { redq[tid] = 0.f; redk[tid] = 0.f; }
    __syncthreads();
    float yq[4], yk[4];
    #pragma unroll
    for (int j = 0; j < 4; ++j) {
        const int c = tid + 256*j;
        float aq=0.f, ak=0.f, av=0.f;
        #pragma unroll
        for (int t = 0; t < 4; ++t) {
            const int ll = l - 3 + t;
            if (ll >= 0) {
                const size_t g = ((size_t)(b*Ll + ll))*HD + c;
                aq += XQ[g]*WQ[c*4+t];
                ak += XK[g]*WK[c*4+t];
                av += XV[g]*WV[c*4+t];
            }
        }
        aq = siluf(aq); ak = siluf(ak); av = siluf(av);
        Vo[(size_t)row*HD + c] = av;
        yq[j] = aq; yk[j] = ak;
        float vq = aq*aq, vk = ak*ak;
        #pragma unroll
        for (int o = 16; o; o >>= 1) {
            vq += __shfl_xor_sync(0xffffffff, vq, o);
            vk += __shfl_xor_sync(0xffffffff, vk, o);
        }
        if (lane == 0) { atomicAdd(&redq[j], vq); atomicAdd(&redk[j], vk); }
    }
    __syncthreads();
    #pragma unroll
    for (int j = 0; j < 4; ++j) {
        const int c = tid + 256*j;
        Qo[(size_t)row*HD + c] = yq[j]*rsqrtf(redq[j] + 1e-12f);
        Ko[(size_t)row*HD + c] = yk[j]*rsqrtf(redk[j] + 1e-12f);
    }
}

// ---------------- precompute: emits bf16 hi/lo operand planes ----------------
#define PRE_SMEM ((3*32*257 + 1024 + 1024 + 32) * 4)
__global__ void precompute_kernel(const float* __restrict__ Qn, const float* __restrict__ Kn,
                                  const float* __restrict__ V,  const float* __restrict__ beta,
                                  float* __restrict__ U,
                                  __nv_bfloat16* __restrict__ QH, __nv_bfloat16* __restrict__ QL,
                                  __nv_bfloat16* __restrict__ WH, __nv_bfloat16* __restrict__ WL,
                                  __nv_bfloat16* __restrict__ KH, __nv_bfloat16* __restrict__ KL,
                                  __nv_bfloat16* __restrict__ AH, __nv_bfloat16* __restrict__ AL)
{
    extern __shared__ float sm[];
    float* sq = sm;
    float* sk = sq + 32*257;
    float* sv = sk + 32*257;
    float* Am = sv + 32*257;
    float* Ti = Am + 1024;
    float* sb = Ti + 1024;
    const int idx = blockIdx.x;
    const int bh = idx / NCc, ci = idx % NCc;
    const int b = bh >> 2, h = bh & 3;
    const int tid = threadIdx.x;
    const size_t cb8 = (size_t)idx*8192;
    const size_t cb1 = (size_t)idx*1024;

    for (int e = tid; e < 8192; e += 256) {
        const int i = e >> 8, d = e & 255;
        const size_t g = ((size_t)(b*Ll + ci*CSs + i))*HD + h*256 + d;
        sq[i*257+d] = Qn[g];
        sk[i*257+d] = Kn[g];
        sv[i*257+d] = V[g];
    }
    if (tid < 32) sb[tid] = beta[(size_t)(b*Ll + ci*CSs + tid)*4 + h];
    __syncthreads();
    for (int e = tid; e < 8192; e += 256) {
        const int i = e >> 8, d = e & 255;
        sv[i*257+d] *= sb[i];
        __nv_bfloat16 hh, ll;
        split1(sq[i*257+d], hh, ll);
        QH[cb8+e] = hh; QL[cb8+e] = ll;
    }
    for (int e = tid; e < 8192; e += 256) {
        const int d = e >> 5, t = e & 31;
        __nv_bfloat16 hh, ll;
        split1(-sk[t*257+d], hh, ll);
        KH[cb8+e] = hh; KL[cb8+e] = ll;
    }
    for (int p = tid; p < 1024; p += 256) {
        const int i = p >> 5, j = p & 31;
        const float* ki = sk + i*257;
        const float* kj = sk + j*257;
        const float* qi = sq + i*257;
        float dkk = 0.f, dqk = 0.f;
        #pragma unroll 8
        for (int d = 0; d < 256; ++d) {
            const float kv = kj[d];
            dkk += ki[d]*kv;
            dqk += qi[d]*kv;
        }
        Am[p] = (i > j) ? sb[i]*dkk : 0.f;
        __nv_bfloat16 hh, ll;
        split1((i >= j) ? dqk : 0.f, hh, ll);
        AH[cb1+p] = hh; AL[cb1+p] = ll;
    }
    __syncthreads();
    if (tid < 32) {
        const int j = tid;
        Ti[j] = (j == 0) ? 1.f : 0.f;
        for (int i2 = 1; i2 < 32; ++i2) {
            __syncwarp();
            float s = 0.f;
            for (int m = 0; m < i2; ++m) s += Am[i2*32+m]*Ti[m*32+j];
            Ti[i2*32+j] = ((i2 == j) ? 1.f : 0.f) - s;
        }
    }
    __syncthreads();
    for (int e = tid; e < 8192; e += 256) {
        const int i = e >> 8, d = e & 255;
        float uu = 0.f, ww = 0.f;
        #pragma unroll
        for (int m = 0; m < 32; ++m) {
            const float t = Ti[i*32+m];
            uu += t * sv[m*257+d];
            ww += t * sb[m] * sk[m*257+d];
        }
        U[cb8+e] = uu;
        __nv_bfloat16 hh, ll;
        split1(ww, hh, ll);
        WH[cb8+e] = hh; WL[cb8+e] = ll;
    }
}

// ---------------- tensor-core delta scan ----------------
// stage: qh(0) ql(16384) wh(32768) wl(49152) ath(65536,2560) atl(68096,2560) u(70656,2048)
#define STGSZ  72704
#define OFF_KT 145408
#define OFF_UB 210944
#define SC_SMEM 227840

__global__ void __launch_bounds__(128) scan_mma(
    const __nv_bfloat16* __restrict__ QHp, const __nv_bfloat16* __restrict__ QLp,
    const __nv_bfloat16* __restrict__ WHp, const __nv_bfloat16* __restrict__ WLp,
    const __nv_bfloat16* __restrict__ KHp, const __nv_bfloat16* __restrict__ KLp,
    const __nv_bfloat16* __restrict__ AHp, const __nv_bfloat16* __restrict__ ALp,
    const float* __restrict__ Ug, float* __restrict__ Out)
{
    extern __shared__ char smraw[];
    const unsigned smb = (unsigned)__cvta_generic_to_shared(smraw);
    float* ub = (float*)(smraw + OFF_UB);   // [c 16][w 4][t 66]
    const int tid = threadIdx.x, warp = tid>>5, lane = tid&31;
    const int bh = blockIdx.x>>4, cb = blockIdx.x&15;
    const int b = bh>>2, h = bh&3;
    const int g = lane>>2, qp = (lane&3)*2;
    const int brow16 = ((lane>>4)&1)*8 + (lane&7);
    const int bcol8 = ((lane>>3)&1)*8;

    float P[8][4];
    #pragma unroll
    for (int i=0;i<8;++i)
        #pragma unroll
        for (int r=0;r<4;++r) P[i][r]=0.f;

    auto issue = [&](int ci, int stg){
        const size_t b8 = (size_t)(bh*NCc + ci)*8192;
        const size_t b1 = (size_t)(bh*NCc + ci)*1024;
        const unsigned sb = smb + stg*STGSZ;
        const __nv_bfloat16* srcs[4] = {QHp+b8, QLp+b8, WHp+b8, WLp+b8};
        #pragma unroll
        for (int pl = 0; pl < 4; ++pl){
            const unsigned dsb = sb + pl*16384;
            for (int e = tid; e < 1024; e += 128){
                int row = e>>5, c = e&31;
                cpa16(dsb + row*512 + ((c^(row&7))<<4), srcs[pl] + row*256 + c*8);
            }
        }
        const unsigned kb2 = smb + OFF_KT + stg*32768;
        for (int e = tid; e < 1024; e += 128){
            int row = e>>2, c = e&3;
            cpa16(kb2 + row*64 + c*16, KHp + b8 + row*32 + c*8);
            cpa16(kb2 + 16384 + row*64 + c*16, KLp + b8 + row*32 + c*8);
        }
        {
            int row = tid>>2, c = tid&3;
            cpa16(sb + 65536 + row*80 + c*16, AHp + b1 + row*32 + c*8);
            cpa16(sb + 68096 + row*80 + c*16, ALp + b1 + row*32 + c*8);
            cpa16(sb + 70656 + row*64 + c*16, Ug + b8 + (size_t)row*256 + cb*16 + c*4);
        }
    };

    issue(0, 0); CP_COMMIT();

    for (int ci = 0; ci < NCc; ++ci) {
        const int stg = ci & 1;
        const unsigned sb = smb + stg*STGSZ;
        const unsigned kb = smb + OFF_KT + stg*32768;
        CP_WAIT0();
        __syncthreads();

        // ---- phase 1: [u'part | oSpart] = P @ [w | q]^T over this warp's d-slice
        float accW[4][4], accQ[4][4];
        #pragma unroll
        for (int i=0;i<4;++i)
            #pragma unroll
            for (int r=0;r<4;++r){ accW[i][r]=0.f; accQ[i][r]=0.f; }
        #pragma unroll
        for (int kt = 0; kt < 4; ++kt) {
            unsigned Ah[4], Al[4];
            const float* p0 = P[2*kt]; const float* p1 = P[2*kt+1];
            Ah[0]=pack2(p0[0],p0[1]); Ah[1]=pack2(p0[2],p0[3]);
            Ah[2]=pack2(p1[0],p1[1]); Ah[3]=pack2(p1[2],p1[3]);
            Al[0]=pack2(res1(p0[0]),res1(p0[1])); Al[1]=pack2(res1(p0[2]),res1(p0[3]));
            Al[2]=pack2(res1(p1[0]),res1(p1[1])); Al[3]=pack2(res1(p1[2]),res1(p1[3]));
            const int dcol = warp*64 + kt*16 + bcol8;
            unsigned bwh[4][2], bwl[4][2], bqh[4][2], bql[4][2];
            #pragma unroll
            for (int ng = 0; ng < 2; ++ng) {
                const int row = ng*16 + brow16;
                const unsigned off = row*512 + ((((unsigned)(dcol>>3))^(row&7))<<4);
                unsigned r4[4];
                ldsm4(r4, sb + 32768 + off);
                bwh[2*ng][0]=r4[0]; bwh[2*ng][1]=r4[1]; bwh[2*ng+1][0]=r4[2]; bwh[2*ng+1][1]=r4[3];
                ldsm4(r4, sb + 49152 + off);
                bwl[2*ng][0]=r4[0]; bwl[2*ng][1]=r4[1]; bwl[2*ng+1][0]=r4[2]; bwl[2*ng+1][1]=r4[3];
                ldsm4(r4, sb + off);
                bqh[2*ng][0]=r4[0]; bqh[2*ng][1]=r4[1]; bqh[2*ng+1][0]=r4[2]; bqh[2*ng+1][1]=r4[3];
                ldsm4(r4, sb + 16384 + off);
                bql[2*ng][0]=r4[0]; bql[2*ng][1]=r4[1]; bql[2*ng+1][0]=r4[2]; bql[2*ng+1][1]=r4[3];
            }
            #pragma unroll
            for (int nt = 0; nt < 4; ++nt) {
                mma16816(accW[nt], Ah, bwh[nt]);
                mma16816(accW[nt], Al, bwh[nt]);
                mma16816(accW[nt], Ah, bwl[nt]);
                mma16816(accQ[nt], Ah, bqh[nt]);
                mma16816(accQ[nt], Al, bqh[nt]);
                mma16816(accQ[nt], Ah, bql[nt]);
            }
        }
        #pragma unroll
        for (int nt = 0; nt < 4; ++nt)
            #pragma unroll
            for (int r = 0; r < 4; ++r) {
                int c = g + ((r>>1)<<3), t = nt*8 + qp + (r&1);
                ub[(c*4+warp)*66 + t] = accW[nt][r];
                ub[(c*4+warp)*66 + 32 + t] = accQ[nt][r];
            }
        if (ci + 1 < NCc) { issue(ci+1, stg^1); CP_COMMIT(); }
        __syncthreads();

        // ---- reduce: u'T = u^T + sum_w partials ; build A fragments hi/lo
        const float* su = (const float*)(smraw + stg*STGSZ + 70656);
        unsigned UH[2][4], UL[2][4];
        #pragma unroll
        for (int kt = 0; kt < 2; ++kt) {
            float v[8];
            #pragma unroll
            for (int p = 0; p < 8; ++p) {
                const int c = g + (((p>>1)&1)<<3);
                const int t = kt*16 + qp + (p&1) + ((p>>2)<<3);
                const int bi = (c*4)*66 + t;
                v[p] = su[t*16 + c] + ub[bi] + ub[bi+66] + ub[bi+132] + ub[bi+198];
            }
            UH[kt][0]=pack2(v[0],v[1]); UH[kt][1]=pack2(v[2],v[3]);
            UH[kt][2]=pack2(v[4],v[5]); UH[kt][3]=pack2(v[6],v[7]);
            UL[kt][0]=pack2(res1(v[0]),res1(v[1])); UL[kt][1]=pack2(res1(v[2]),res1(v[3]));
            UL[kt][2]=pack2(res1(v[4]),res1(v[5])); UL[kt][3]=pack2(res1(v[6]),res1(v[7]));
        }
        // o init = (q@S)^T = -sum_w oSpart
        float oc[4];
        const int i0 = warp*8 + qp;
        #pragma unroll
        for (int r = 0; r < 4; ++r) {
            const int c = g + ((r>>1)<<3), t = 32 + i0 + (r&1) - qp + qp; // t = 32 + warp*8 + qp + (r&1)
            const int bi = (c*4)*66 + 32 + i0 + (r&1);
            oc[r] = -(ub[bi] + ub[bi+66] + ub[bi+132] + ub[bi+198]);
            (void)t;
        }

        // ---- phase 2: o += (attn @ u')^T ; store
        #pragma unroll
        for (int kt = 0; kt < 2; ++kt) {
            unsigned bh2[2], bl2[2];
            const unsigned aoff = (warp*8 + (lane&7))*80 + (kt*16 + bcol8)*2;
            ldsm2(bh2, sb + 65536 + aoff);
            ldsm2(bl2, sb + 68096 + aoff);
            mma16816(oc, UH[kt], bh2);
            mma16816(oc, UL[kt], bh2);
            mma16816(oc, UH[kt], bl2);
        }
        {
            const size_t base = ((size_t)(b*Ll + ci*CSs + i0))*HD + h*256 + cb*16;
            Out[base + g]          = oc[0];
            Out[base + HD + g]     = oc[1];
            Out[base + g + 8]      = oc[2];
            Out[base + HD + g + 8] = oc[3];
        }

        // ---- phase 3: P += u'^T @ (-k^T slice)
        #pragma unroll
        for (int kt = 0; kt < 2; ++kt) {
            #pragma unroll
            for (int np = 0; np < 4; ++np) {
                unsigned bh4[4], bl4[4];
                const unsigned off = (warp*64 + np*16 + brow16)*64 + (kt*16 + bcol8)*2;
                ldsm4(bh4, kb + off);
                ldsm4(bl4, kb + 16384 + off);
                mma16816(P[2*np],   UH[kt], bh4);
                mma16816(P[2*np],   UL[kt], bh4);
                mma16816(P[2*np],   UH[kt], bl4);
                mma16816(P[2*np+1], UH[kt], bh4+2);
                mma16816(P[2*np+1], UL[kt], bh4+2);
                mma16816(P[2*np+1], UH[kt], bl4+2);
            }
        }
    }
}

// ---------------- FIR short/long + gate_in ----------------
__global__ void fir_gatein_kernel(const float* __restrict__ hs, const float* __restrict__ V,
                                  const float* __restrict__ ws, const float* __restrict__ wl,
                                  const float* __restrict__ Dl,
                                  float* __restrict__ Sout, float* __restrict__ Lout,
                                  float* __restrict__ Gin)
{
    const int blk = blockIdx.x;
    const int b = blk / (Ll/8);
    const int l0 = (blk % (Ll/8)) * 8;
    const int tid = threadIdx.x;
    float smean[8], lmean[8], dmean[8];
    #pragma unroll
    for (int r = 0; r < 8; ++r) { smean[r]=0.f; lmean[r]=0.f; dmean[r]=0.f; }
    for (int j = 0; j < 4; ++j) {
        const int ch = tid + 256*j;
        float win[38];
        #pragma unroll
        for (int t = 0; t < 38; ++t) {
            const int l = l0 - 30 + t;
            win[t] = (l >= 0) ? V[((size_t)(b*Ll + l))*HD + ch] : 0.f;
        }
        float wlr[31];
        #pragma unroll
        for (int t = 0; t < 31; ++t) wlr[t] = wl[ch*31 + t];
        const float w0 = ws[ch*3+0], w1 = ws[ch*3+1], w2 = ws[ch*3+2];
        #pragma unroll
        for (int r = 0; r < 8; ++r) {
            float yl = 0.f;
            #pragma unroll
            for (int t = 0; t < 31; ++t) yl += win[r+t]*wlr[t];
            const float ysv = win[r+28]*w0 + win[r+29]*w1 + win[r+30]*w2;
            const size_t row = (size_t)(b*Ll + l0 + r);
            Sout[row*HD + ch] = ysv;
            Lout[row*HD + ch] = yl;
            smean[r] += ysv; lmean[r] += yl;
            dmean[r] += Dl[row*HD + ch];
        }
    }
    for (int r = 0; r < 8; ++r) {
        const size_t row = (size_t)(b*Ll + l0 + r);
        float* grow = Gin + row*GIN;
        #pragma unroll
        for (int j = 0; j < 4; ++j) grow[tid + 256*j] = hs[row*HD + tid + 256*j];
        grow[1024 + tid] = smean[r]*0.25f;
        grow[1280 + tid] = lmean[r]*0.25f;
        grow[1536 + tid] = dmean[r]*0.25f;
    }
}

// ---------------- gate head 2 ----------------
__global__ void gate2_wgt(const float* __restrict__ GH2, const float* __restrict__ W2,
                          const float* __restrict__ b2, const float* __restrict__ ltemp,
                          float* __restrict__ Wgt)
{
    const int row = blockIdx.x;
    const int warp = threadIdx.x >> 5, lane = threadIdx.x & 31;
    __shared__ float lg[4];
    const float* x = GH2 + (size_t)row*GHID;
    const float* w = W2 + warp*GHID;
    float s = 0.f;
    for (int i = lane; i < GHID; i += 32) s += x[i]*w[i];
    #pragma unroll
    for (int o = 16; o; o >>= 1) s += __shfl_xor_sync(0xffffffff, s, o);
    if (lane == 0) lg[warp] = s + b2[warp];
    __syncthreads();
    if (threadIdx.x == 0) {
        const float t = log1pf(expf(ltemp[0])) + 1e-4f;
        float m = fmaxf(fmaxf(lg[0], lg[1]), fmaxf(lg[2], lg[3]));
        float e[4]; float se = 0.f;
        #pragma unroll
        for (int j = 0; j < 4; ++j) { e[j] = expf((lg[j]-m)/t); se += e[j]; }
        #pragma unroll
        for (int j = 0; j < 4; ++j) e[j] /= se;
        const float fl = 0.05f * e[3];
        e[0] = fmaxf(e[0], fl);
        e[1] = fmaxf(e[1], fl);
        const float s2 = e[0]+e[1]+e[2]+e[3];
        #pragma unroll
        for (int j = 0; j < 4; ++j) Wgt[row*4+j] = e[j]/s2;
    }
}

// ---------------- combine + RMSNorm ----------------
__global__ void combine_kernel(const float* __restrict__ Sh, const float* __restrict__ Lg,
                               const float* __restrict__ Dl, const float* __restrict__ V,
                               const float* __restrict__ Wgt, const float* __restrict__ onw,
                               float* __restrict__ O)
{
    const int row = blockIdx.x;
    const int tid = threadIdx.x, lane = tid & 31;
    __shared__ float red[4];
    if (tid < 4) red[tid] = 0.f;
    __syncthreads();
    const float w0 = Wgt[row*4+0], w1 = Wgt[row*4+1], w2 = Wgt[row*4+2], w3 = Wgt[row*4+3];
    float ov[4];
    #pragma unroll
    for (int j = 0; j < 4; ++j) {
        const size_t g = (size_t)row*HD + tid + 256*j;
        ov[j] = w0*Sh[g] + w1*Lg[g] + w2*Dl[g] + w3*V[g];
        float v = ov[j]*ov[j];
        #pragma unroll
        for (int o = 16; o; o >>= 1) v += __shfl_xor_sync(0xffffffff, v, o);
        if (lane == 0) atomicAdd(&red[j], v);
    }
    __syncthreads();
    #pragma unroll
    for (int j = 0; j < 4; ++j) {
        const float sc = rsqrtf(red[j]*(1.f/256.f) + 1e-5f) * onw[tid];
        O[(size_t)row*HD + tid + 256*j] = ov[j]*sc;
    }
}

// ---------------- launch ----------------
static inline void split_launch(const float* x, __nv_bfloat16* hi, __nv_bfloat16* lo, size_t n)
{
    int n4 = (int)(n >> 2);
    split_kernel<<<(n4 + 255)/256, 256>>>((const float4*)x, (uint2*)hi, (uint2*)lo, n4);
}

extern "C" void kernel_launch(void* const* d_in, const int* in_sizes, int n_in,
                              void* d_out, int out_size)
{
    const float* hs  = (const float*)d_in[0];
    const float* qw  = (const float*)d_in[1];
    const float* kw  = (const float*)d_in[2];
    const float* vw  = (const float*)d_in[3];
    const float* bw  = (const float*)d_in[4];
    const float* qcw = (const float*)d_in[5];
    const float* kcw = (const float*)d_in[6];
    const float* vcw = (const float*)d_in[7];
    const float* fsw = (const float*)d_in[8];
    const float* flw = (const float*)d_in[9];
    const float* w1  = (const float*)d_in[10];
    const float* b1  = (const float*)d_in[11];
    const float* w2  = (const float*)d_in[12];
    const float* b2  = (const float*)d_in[13];
    const float* lt  = (const float*)d_in[14];
    const float* onw = (const float*)d_in[15];
    const float* ow  = (const float*)d_in[16];
    float* out = (float*)d_out;

    float *xq,*xk,*xv,*q,*k,*v,*u,*delta,*shrt,*lng,*gin,*gh,*beta,*wgt,*ocomb;
    __nv_bfloat16 *hsH,*hsL,*ginH,*ginL,*ocH,*ocL,*wtH,*wtL;
    __nv_bfloat16 *qh,*ql,*wh,*wlp,*kh,*kl,*ah,*al;
    cudaGetSymbolAddress((void**)&xq,   g_xq);
    cudaGetSymbolAddress((void**)&xk,   g_xk);
    cudaGetSymbolAddress((void**)&xv,   g_xv);
    cudaGetSymbolAddress((void**)&q,    g_q);
    cudaGetSymbolAddress((void**)&k,    g_k);
    cudaGetSymbolAddress((void**)&v,    g_v);
    cudaGetSymbolAddress((void**)&u,    g_u);
    cudaGetSymbolAddress((void**)&delta,g_delta);
    cudaGetSymbolAddress((void**)&shrt, g_short);
    cudaGetSymbolAddress((void**)&lng,  g_long);
    cudaGetSymbolAddress((void**)&gin,  g_gin);
    cudaGetSymbolAddress((void**)&gh,   g_gh);
    cudaGetSymbolAddress((void**)&beta, g_beta);
    cudaGetSymbolAddress((void**)&wgt,  g_wgt);
    cudaGetSymbolAddress((void**)&ocomb,g_ocomb);
    cudaGetSymbolAddress((void**)&hsH,  g_hsH);
    cudaGetSymbolAddress((void**)&hsL,  g_hsL);
    cudaGetSymbolAddress((void**)&ginH, g_ginH);
    cudaGetSymbolAddress((void**)&ginL, g_ginL);
    cudaGetSymbolAddress((void**)&ocH,  g_ocH);
    cudaGetSymbolAddress((void**)&ocL,  g_ocL);
    cudaGetSymbolAddress((void**)&wtH,  g_wtH);
    cudaGetSymbolAddress((void**)&wtL,  g_wtL);
    cudaGetSymbolAddress((void**)&qh,   g_qh);
    cudaGetSymbolAddress((void**)&ql,   g_ql);
    cudaGetSymbolAddress((void**)&wh,   g_wh);
    cudaGetSymbolAddress((void**)&wlp,  g_wl);
    cudaGetSymbolAddress((void**)&kh,   g_kh);
    cudaGetSymbolAddress((void**)&kl,   g_kl);
    cudaGetSymbolAddress((void**)&ah,   g_ah);
    cudaGetSymbolAddress((void**)&al,   g_al);

    cudaFuncSetAttribute(precompute_kernel, cudaFuncAttributeMaxDynamicSharedMemorySize, PRE_SMEM);
    cudaFuncSetAttribute(scan_mma, cudaFuncAttributeMaxDynamicSharedMemorySize, SC_SMEM);

    split_launch(hs, hsH, hsL, (size_t)BL*Dd);
    split_launch(qw, wtH + WOFF_Q,  wtL + WOFF_Q,  (size_t)1024*1024);
    split_launch(kw, wtH + WOFF_K,  wtL + WOFF_K,  (size_t)1024*1024);
    split_launch(vw, wtH + WOFF_V,  wtL + WOFF_V,  (size_t)1024*1024);
    split_launch(w1, wtH + WOFF_W1, wtL + WOFF_W1, (size_t)GHID*GIN);
    split_launch(ow, wtH + WOFF_O,  wtL + WOFF_O,  (size_t)Dd*HD);

    const dim3 gemmGrid(HD/128, BL/128);

    hgemm_nt<false><<<gemmGrid, 256>>>(hsH, hsL, wtH+WOFF_Q, wtL+WOFF_Q, xq, BL, HD, Dd, nullptr);
    hgemm_nt<false><<<gemmGrid, 256>>>(hsH, hsL, wtH+WOFF_K, wtL+WOFF_K, xk, BL, HD, Dd, nullptr);
    hgemm_nt<false><<<gemmGrid, 256>>>(hsH, hsL, wtH+WOFF_V, wtL+WOFF_V, xv, BL, HD, Dd, nullptr);
    beta_kernel<<<BL, 128>>>(hs, bw, beta);
    conv_silu_norm<<<BL, 256>>>(xq, xk, xv, qcw, kcw, vcw, q, k, v);
    precompute_kernel<<<8*NCc, 256, PRE_SMEM>>>(q, k, v, beta, u,
                                                qh, ql, wh, wlp, kh, kl, ah, al);
    scan_mma<<<128, 128, SC_SMEM>>>(qh, ql, wh, wlp, kh, kl, ah, al, u, delta);
    fir_gatein_kernel<<<Bb*(Ll/8), 256>>>(hs, v, fsw, flw, delta, shrt, lng, gin);
    split_launch(gin, ginH, ginL, (size_t)BL*GIN);
    hgemm_nt<true><<<gemmGrid, 256>>>(ginH, ginL, wtH+WOFF_W1, wtL+WOFF_W1, gh, BL, GHID, GIN, b1);
    gate2_wgt<<<BL, 128>>>(gh, w2, b2, lt, wgt);
    combine_kernel<<<BL, 256>>>(shrt, lng, delta, v, wgt, onw, ocomb);
    split_launch(ocomb, ocH, ocL, (size_t)BL*HD);
    hgemm_nt<false><<<gemmGrid, 256>>>(ocH, ocL, wtH+WOFF_O, wtL+WOFF_O, out, BL, Dd, HD, nullptr);
}

// round 5
// speedup vs baseline: 2.9394x; 1.0593x over previous
#include <cuda_runtime.h>
#include <cuda_bf16.h>
#include <math.h>

#define Bb   2
#define Ll   4096
#define Dd   1024
#define Hh   4
#define CSs  32
#define NCc  128
#define BL   (Bb*Ll)
#define HD   1024
#define GIN  1792
#define GHID 1024
#define CH8  (8*NCc*8192)

// ---------------- scratch ----------------
__device__ float g_xqkv[BL*3072];
__device__ float g_q [BL*HD];
__device__ float g_k [BL*HD];
__device__ float g_v [BL*HD];
__device__ float g_u [CH8];
__device__ float g_delta[BL*HD];
__device__ float g_short[BL*HD];
__device__ float g_long [BL*HD];
__device__ float g_gin[BL*GIN];
__device__ float g_gh [BL*GHID];
__device__ float g_beta[BL*Hh];
__device__ float g_wgt [BL*4];
__device__ float g_ocomb[BL*HD];

__device__ __align__(16) __nv_bfloat16 g_hsH[BL*Dd];
__device__ __align__(16) __nv_bfloat16 g_hsL[BL*Dd];
__device__ __align__(16) __nv_bfloat16 g_ginH[BL*GIN];
__device__ __align__(16) __nv_bfloat16 g_ginL[BL*GIN];
__device__ __align__(16) __nv_bfloat16 g_ocH[BL*HD];
__device__ __align__(16) __nv_bfloat16 g_ocL[BL*HD];
#define WOFF_Q  0
#define WOFF_K  (1024*1024)
#define WOFF_V  (2*1024*1024)
#define WOFF_W1 (3*1024*1024)
#define WOFF_O  (3*1024*1024 + 1792*1024)
#define WTOT    (WOFF_O + 1024*1024)
__device__ __align__(16) __nv_bfloat16 g_wtH[WTOT];
__device__ __align__(16) __nv_bfloat16 g_wtL[WTOT];

// scan operand planes
__device__ __align__(16) __nv_bfloat16 g_qh[CH8], g_ql[CH8], g_wh[CH8], g_wl[CH8], g_kh[CH8], g_kl[CH8];
__device__ __align__(16) __nv_bfloat16 g_ah[8*NCc*1024], g_al[8*NCc*1024];

// ---------------- helpers ----------------
__device__ __forceinline__ float siluf(float x){ return x / (1.f + expf(-x)); }
__device__ __forceinline__ float geluf(float x){ return 0.5f * x * (1.f + erff(x * 0.70710678118654752f)); }
__device__ __forceinline__ void ldsm4(unsigned* r, unsigned addr){
    asm volatile("ldmatrix.sync.aligned.m8n8.x4.shared.b16 {%0,%1,%2,%3}, [%4];"
        : "=r"(r[0]),"=r"(r[1]),"=r"(r[2]),"=r"(r[3]) : "r"(addr));
}
__device__ __forceinline__ void ldsm4t(unsigned* r, unsigned addr){
    asm volatile("ldmatrix.sync.aligned.m8n8.x4.trans.shared.b16 {%0,%1,%2,%3}, [%4];"
        : "=r"(r[0]),"=r"(r[1]),"=r"(r[2]),"=r"(r[3]) : "r"(addr));
}
__device__ __forceinline__ void ldsm2(unsigned* r, unsigned addr){
    asm volatile("ldmatrix.sync.aligned.m8n8.x2.shared.b16 {%0,%1}, [%2];"
        : "=r"(r[0]),"=r"(r[1]) : "r"(addr));
}
__device__ __forceinline__ void mma16816(float* c, const unsigned* a, const unsigned* b){
    asm volatile("mma.sync.aligned.m16n8k16.row.col.f32.bf16.bf16.f32 "
        "{%0,%1,%2,%3}, {%4,%5,%6,%7}, {%8,%9}, {%0,%1,%2,%3};"
        : "+f"(c[0]),"+f"(c[1]),"+f"(c[2]),"+f"(c[3])
        : "r"(a[0]),"r"(a[1]),"r"(a[2]),"r"(a[3]), "r"(b[0]),"r"(b[1]));
}
__device__ __forceinline__ void cpa16(unsigned d, const void* s){
    asm volatile("cp.async.cg.shared.global [%0],[%1],16;\n" :: "r"(d), "l"(s));
}
#define CP_COMMIT() asm volatile("cp.async.commit_group;\n")
#define CP_WAIT0()  asm volatile("cp.async.wait_group 0;\n")
__device__ __forceinline__ unsigned pack2(float a, float b){
    __nv_bfloat162 t; t.x=__float2bfloat16(a); t.y=__float2bfloat16(b);
    return *(unsigned*)&t;
}
__device__ __forceinline__ float res1(float v){ return v - __bfloat162float(__float2bfloat16(v)); }
__device__ __forceinline__ void split1(float v, __nv_bfloat16& h, __nv_bfloat16& l){
    h = __float2bfloat16(v); l = __float2bfloat16(v - __bfloat162float(h));
}

// ---------------- fp32 -> (hi,lo) bf16 split ----------------
__global__ void split_kernel(const float4* __restrict__ x, uint2* __restrict__ hi,
                             uint2* __restrict__ lo, int n4)
{
    int i = blockIdx.x*blockDim.x + threadIdx.x;
    if (i >= n4) return;
    float4 v = x[i];
    uint2 ho, loo;
    ho.x = pack2(v.x, v.y);  ho.y = pack2(v.z, v.w);
    loo.x = pack2(res1(v.x), res1(v.y)); loo.y = pack2(res1(v.z), res1(v.w));
    hi[i] = ho; lo[i] = loo;
}

// ---------------- bf16x3 split GEMM, double-buffered ----------
template<bool EPI>
__global__ void __launch_bounds__(256) hgemm_nt(const __nv_bfloat16* __restrict__ Ah,
                                                const __nv_bfloat16* __restrict__ Al,
                                                const __nv_bfloat16* __restrict__ Bh,
                                                const __nv_bfloat16* __restrict__ Bl,
                                                float* __restrict__ C,
                                                int M, int N, int K,
                                                const float* __restrict__ bias)
{
    __shared__ __align__(16) __nv_bfloat16 sm[2][4*128*24];
    const int PL = 128*24;
    const int tid = threadIdx.x;
    const int bm = blockIdx.y*128, bn = blockIdx.x*128;
    const int warp = tid>>5, lane = tid&31;
    const int wm = warp>>2, wn = warp&3;
    float acc[4][4][4];
    #pragma unroll
    for (int i=0;i<4;i++) for(int j=0;j<4;j++) for(int r=0;r<4;r++) acc[i][j][r]=0.f;
    const size_t aoff = (size_t)(bm + (tid>>1))*K + (tid&1)*8;
    const size_t boff = (size_t)(bn + (tid>>1))*K + (tid&1)*8;
    const int sto = (tid>>1)*24 + (tid&1)*8;
    unsigned base = (unsigned)__cvta_generic_to_shared(&sm[0][0]);
    const int arow = wm*64 + (lane&15);
    const int acol = (lane>>4)*8;
    const int brow = wn*32 + ((lane>>4)&1)*8 + (lane&7);
    const int bcol = ((lane>>3)&1)*8;
    const int nk = K >> 4;
    {
        uint4 rAh = *(const uint4*)(Ah + aoff);
        uint4 rAl = *(const uint4*)(Al + aoff);
        uint4 rBh = *(const uint4*)(Bh + boff);
        uint4 rBl = *(const uint4*)(Bl + boff);
        *(uint4*)(&sm[0][0] + sto) = rAh;
        *(uint4*)(&sm[0][0] + PL + sto) = rAl;
        *(uint4*)(&sm[0][0] + 2*PL + sto) = rBh;
        *(uint4*)(&sm[0][0] + 3*PL + sto) = rBl;
    }
    __syncthreads();
    for (int kt = 0; kt < nk; ++kt) {
        const int cur = kt & 1;
        const unsigned sb = base + (unsigned)cur*(8*PL);
        uint4 nAh, nAl, nBh, nBl;
        const bool more = (kt + 1 < nk);
        if (more) {
            const size_t ka = aoff + (size_t)(kt+1)*16;
            const size_t kb = boff + (size_t)(kt+1)*16;
            nAh = *(const uint4*)(Ah + ka); nAl = *(const uint4*)(Al + ka);
            nBh = *(const uint4*)(Bh + kb); nBl = *(const uint4*)(Bl + kb);
        }
        unsigned bh[4][2], bl[4][2];
        #pragma unroll
        for (int ng = 0; ng < 2; ++ng) {
            unsigned r4[4];
            ldsm4(r4, sb + 2u*(2*PL + (brow + ng*16)*24 + bcol));
            bh[2*ng][0]=r4[0]; bh[2*ng][1]=r4[1]; bh[2*ng+1][0]=r4[2]; bh[2*ng+1][1]=r4[3];
            ldsm4(r4, sb + 2u*(3*PL + (brow + ng*16)*24 + bcol));
            bl[2*ng][0]=r4[0]; bl[2*ng][1]=r4[1]; bl[2*ng+1][0]=r4[2]; bl[2*ng+1][1]=r4[3];
        }
        #pragma unroll
        for (int mt = 0; mt < 4; ++mt) {
            unsigned ah[4], al[4];
            ldsm4(ah, sb + 2u*((arow + mt*16)*24 + acol));
            ldsm4(al, sb + 2u*(PL + (arow + mt*16)*24 + acol));
            #pragma unroll
            for (int nt = 0; nt < 4; ++nt) {
                mma16816(acc[mt][nt], ah, bh[nt]);
                mma16816(acc[mt][nt], ah, bl[nt]);
                mma16816(acc[mt][nt], al, bh[nt]);
            }
        }
        if (more) {
            __nv_bfloat16* d = &sm[cur^1][0];
            *(uint4*)(d + sto) = nAh;
            *(uint4*)(d + PL + sto) = nAl;
            *(uint4*)(d + 2*PL + sto) = nBh;
            *(uint4*)(d + 3*PL + sto) = nBl;
            __syncthreads();
        }
    }
    const int g = lane>>2, tig = lane&3;
    #pragma unroll
    for (int mt = 0; mt < 4; ++mt) {
        const int row0 = bm + wm*64 + mt*16 + g;
        #pragma unroll
        for (int nt = 0; nt < 4; ++nt) {
            const int col = bn + wn*32 + nt*8 + tig*2;
            float v0 = acc[mt][nt][0], v1 = acc[mt][nt][1];
            float v2 = acc[mt][nt][2], v3 = acc[mt][nt][3];
            if (EPI) {
                const float bz0 = bias[col], bz1 = bias[col+1];
                v0 = geluf(v0+bz0); v1 = geluf(v1+bz1);
                v2 = geluf(v2+bz0); v3 = geluf(v3+bz1);
            }
            *(float2*)(C + (size_t)row0*N + col)     = make_float2(v0, v1);
            *(float2*)(C + (size_t)(row0+8)*N + col) = make_float2(v2, v3);
        }
    }
}

// ---------------- beta ----------------
__global__ void beta_kernel(const float* __restrict__ hs, const float* __restrict__ bw,
                            float* __restrict__ beta)
{
    const int row = blockIdx.x;
    const int warp = threadIdx.x >> 5, lane = threadIdx.x & 31;
    const float* x = hs + (size_t)row * Dd;
    const float* w = bw + warp * Dd;
    float s = 0.f;
    for (int i = lane; i < Dd; i += 32) s += x[i] * w[i];
    #pragma unroll
    for (int o = 16; o; o >>= 1) s += __shfl_xor_sync(0xffffffff, s, o);
    if (lane == 0) beta[row*4 + warp] = 1.f / (1.f + expf(-s));
}

// ---------------- conv + silu + l2norm (reads fused xqkv) ----------------
__global__ void conv_silu_norm(const float* __restrict__ XQKV,
                               const float* __restrict__ WQ, const float* __restrict__ WK,
                               const float* __restrict__ WV,
                               float* __restrict__ Qo, float* __restrict__ Ko,
                               float* __restrict__ Vo)
{
    const int row = blockIdx.x;
    const int b = row >> 12, l = row & (Ll-1);
    const int tid = threadIdx.x;
    const int lane = tid & 31;
    __shared__ float redq[4], redk[4];
    if (tid < 4) { redq[tid] = 0.f; redk[tid] = 0.f; }
    __syncthreads();
    float yq[4], yk[4];
    #pragma unroll
    for (int j = 0; j < 4; ++j) {
        const int c = tid + 256*j;
        float aq=0.f, ak=0.f, av=0.f;
        #pragma unroll
        for (int t = 0; t < 4; ++t) {
            const int ll = l - 3 + t;
            if (ll >= 0) {
                const size_t g3 = ((size_t)(b*Ll + ll))*3072;
                aq += XQKV[g3 + c]*WQ[c*4+t];
                ak += XQKV[g3 + 1024 + c]*WK[c*4+t];
                av += XQKV[g3 + 2048 + c]*WV[c*4+t];
            }
        }
        aq = siluf(aq); ak = siluf(ak); av = siluf(av);
        Vo[(size_t)row*HD + c] = av;
        yq[j] = aq; yk[j] = ak;
        float vq = aq*aq, vk = ak*ak;
        #pragma unroll
        for (int o = 16; o; o >>= 1) {
            vq += __shfl_xor_sync(0xffffffff, vq, o);
            vk += __shfl_xor_sync(0xffffffff, vk, o);
        }
        if (lane == 0) { atomicAdd(&redq[j], vq); atomicAdd(&redk[j], vk); }
    }
    __syncthreads();
    #pragma unroll
    for (int j = 0; j < 4; ++j) {
        const int c = tid + 256*j;
        Qo[(size_t)row*HD + c] = yq[j]*rsqrtf(redq[j] + 1e-12f);
        Ko[(size_t)row*HD + c] = yk[j]*rsqrtf(redk[j] + 1e-12f);
    }
}

// ---------------- precompute (tensor-core version) ----------------
// smem byte offsets; bf16 planes 32 rows x 264 (pad) cols
#define PPLN 16896
#define OQH 0
#define OQL 16896
#define OKH 33792
#define OKL 50688
#define OVH 67584
#define OVL 84480
#define OBH 101376
#define OBL 118272
#define OTH 135168
#define OTL 137728
#define OAM 140288
#define OTI 144512
#define OSB 148736
#define PRE_SMEM 148992

__global__ void __launch_bounds__(256) precompute_kernel(
    const float* __restrict__ Qn, const float* __restrict__ Kn,
    const float* __restrict__ V,  const float* __restrict__ beta,
    float* __restrict__ U,
    __nv_bfloat16* __restrict__ QH, __nv_bfloat16* __restrict__ QL,
    __nv_bfloat16* __restrict__ WH, __nv_bfloat16* __restrict__ WL,
    __nv_bfloat16* __restrict__ KH, __nv_bfloat16* __restrict__ KL,
    __nv_bfloat16* __restrict__ AH, __nv_bfloat16* __restrict__ AL)
{
    extern __shared__ char smraw[];
    const unsigned smb = (unsigned)__cvta_generic_to_shared(smraw);
    float* Amp = (float*)(smraw + OAM);
    float* Tip = (float*)(smraw + OTI);
    float* sbp = (float*)(smraw + OSB);
    const int idx = blockIdx.x;
    const int bh = idx >> 7, ci = idx & 127;
    const int b = bh >> 2, h = bh & 3;
    const int tid = threadIdx.x, warp = tid>>5, lane = tid&31;
    const int g = lane>>2, qp = (lane&3)*2;
    const size_t cb8 = (size_t)idx*8192;
    const size_t cb1 = (size_t)idx*1024;

    if (tid < 32) sbp[tid] = beta[(size_t)(b*Ll + ci*CSs + tid)*4 + h];
    __syncthreads();

    // load + split into planes
    for (int e = tid; e < 8192; e += 256) {
        const int i = e >> 8, d = e & 255;
        const size_t gg = ((size_t)(b*Ll + ci*CSs + i))*HD + h*256 + d;
        const float qv = Qn[gg], kv = Kn[gg], vv = V[gg];
        const float bi = sbp[i];
        __nv_bfloat16 hh, ll;
        split1(qv, hh, ll);
        *(__nv_bfloat16*)(smraw + OQH + (i*264+d)*2) = hh;
        *(__nv_bfloat16*)(smraw + OQL + (i*264+d)*2) = ll;
        QH[cb8+e] = hh; QL[cb8+e] = ll;
        split1(kv, hh, ll);
        *(__nv_bfloat16*)(smraw + OKH + (i*264+d)*2) = hh;
        *(__nv_bfloat16*)(smraw + OKL + (i*264+d)*2) = ll;
        split1(vv*bi, hh, ll);
        *(__nv_bfloat16*)(smraw + OVH + (i*264+d)*2) = hh;
        *(__nv_bfloat16*)(smraw + OVL + (i*264+d)*2) = ll;
        split1(kv*bi, hh, ll);
        *(__nv_bfloat16*)(smraw + OBH + (i*264+d)*2) = hh;
        *(__nv_bfloat16*)(smraw + OBL + (i*264+d)*2) = ll;
    }
    __syncthreads();

    // gram matrices: QK = q@k^T, KK = k@k^T  (warp w: m-tile w>>2, n-tile w&3)
    {
        const int mt = warp>>2, ntw = warp&3;
        float qk[4] = {0,0,0,0}, kk[4] = {0,0,0,0};
        const unsigned arow_off = (mt*16 + (lane&15))*528 + ((lane>>4)*8)*2;
        const unsigned brow_off = (ntw*8 + (lane&7))*528 + (((lane>>3)&1)*8)*2;
        #pragma unroll
        for (int kt = 0; kt < 16; ++kt) {
            const unsigned kb2 = kt*32;
            unsigned aq[4], aql[4], ak4[4], akl[4], b2h[2], b2l[2];
            ldsm4(aq,  smb + OQH + arow_off + kb2);
            ldsm4(aql, smb + OQL + arow_off + kb2);
            ldsm4(ak4, smb + OKH + arow_off + kb2);
            ldsm4(akl, smb + OKL + arow_off + kb2);
            ldsm2(b2h, smb + OKH + brow_off + kb2);
            ldsm2(b2l, smb + OKL + brow_off + kb2);
            mma16816(qk, aq, b2h);  mma16816(qk, aql, b2h); mma16816(qk, aq, b2l);
            mma16816(kk, ak4, b2h); mma16816(kk, akl, b2h); mma16816(kk, ak4, b2l);
        }
        const int i0 = mt*16 + g, j0 = ntw*8 + qp;
        #pragma unroll
        for (int r = 0; r < 4; ++r) {
            const int i = i0 + (r>>1)*8, j = j0 + (r&1);
            Amp[i*33+j] = (i > j) ? sbp[i]*kk[r] : 0.f;
            const float av = (i >= j) ? qk[r] : 0.f;
            __nv_bfloat16 hh, ll;
            split1(av, hh, ll);
            AH[cb1 + i*32 + j] = hh; AL[cb1 + i*32 + j] = ll;
        }
    }
    // -k^T planes to gmem [d][t]
    for (int e = tid; e < 8192; e += 256) {
        const int d = e >> 5, t = e & 31;
        unsigned short hv = *(unsigned short*)(smraw + OKH + (t*264+d)*2) ^ 0x8000u;
        unsigned short lv = *(unsigned short*)(smraw + OKL + (t*264+d)*2) ^ 0x8000u;
        KH[cb8+e] = *(__nv_bfloat16*)&hv;
        KL[cb8+e] = *(__nv_bfloat16*)&lv;
    }
    __syncthreads();

    // Tinv = (I+A)^{-1} forward substitution (warp 0)
    if (tid < 32) {
        const int j = tid;
        Tip[j] = (j == 0) ? 1.f : 0.f;
        for (int i2 = 1; i2 < 32; ++i2) {
            __syncwarp();
            float s = 0.f;
            for (int m = 0; m < i2; ++m) s += Amp[i2*33+m]*Tip[m*33+j];
            Tip[i2*33+j] = ((i2 == j) ? 1.f : 0.f) - s;
        }
    }
    __syncthreads();
    for (int e = tid; e < 1024; e += 256) {
        const int i = e >> 5, j = e & 31;
        __nv_bfloat16 hh, ll;
        split1(Tip[i*33+j], hh, ll);
        *(__nv_bfloat16*)(smraw + OTH + (i*40+j)*2) = hh;
        *(__nv_bfloat16*)(smraw + OTL + (i*40+j)*2) = ll;
    }
    __syncthreads();

    // u = Tinv@vb, w = Tinv@bk via mma with trans-B
    {
        const int mt = warp>>2;
        unsigned TiH[2][4], TiL[2][4];
        #pragma unroll
        for (int kt = 0; kt < 2; ++kt) {
            const unsigned ao = (mt*16 + (lane&15))*80 + (kt*16 + (lane>>4)*8)*2;
            ldsm4(TiH[kt], smb + OTH + ao);
            ldsm4(TiL[kt], smb + OTL + ao);
        }
        const int i0 = mt*16 + g;
        #pragma unroll
        for (int ng = 0; ng < 4; ++ng) {
            const int n0 = (warp&3)*64 + ng*16;
            float aU[2][4], aW[2][4];
            #pragma unroll
            for (int t2 = 0; t2 < 2; ++t2)
                #pragma unroll
                for (int r = 0; r < 4; ++r) { aU[t2][r]=0.f; aW[t2][r]=0.f; }
            #pragma unroll
            for (int kt = 0; kt < 2; ++kt) {
                const unsigned brow = kt*16 + (lane&7) + ((lane>>3)&1)*8;
                const unsigned bcol = n0 + ((lane>>4)&1)*8;
                const unsigned bo = brow*528 + bcol*2;
                unsigned bvh[4], bvl[4], bbh[4], bbl[4];
                ldsm4t(bvh, smb + OVH + bo);
                ldsm4t(bvl, smb + OVL + bo);
                ldsm4t(bbh, smb + OBH + bo);
                ldsm4t(bbl, smb + OBL + bo);
                #pragma unroll
                for (int nt = 0; nt < 2; ++nt) {
                    mma16816(aU[nt], TiH[kt], bvh+2*nt);
                    mma16816(aU[nt], TiL[kt], bvh+2*nt);
                    mma16816(aU[nt], TiH[kt], bvl+2*nt);
                    mma16816(aW[nt], TiH[kt], bbh+2*nt);
                    mma16816(aW[nt], TiL[kt], bbh+2*nt);
                    mma16816(aW[nt], TiH[kt], bbl+2*nt);
                }
            }
            #pragma unroll
            for (int nt = 0; nt < 2; ++nt)
                #pragma unroll
                for (int r = 0; r < 4; ++r) {
                    const int i = i0 + (r>>1)*8;
                    const int d = n0 + nt*8 + qp + (r&1);
                    U[cb8 + i*256 + d] = aU[nt][r];
                    __nv_bfloat16 hh, ll;
                    split1(aW[nt][r], hh, ll);
                    WH[cb8 + i*256 + d] = hh;
                    WL[cb8 + i*256 + d] = ll;
                }
        }
    }
}

// ---------------- tensor-core delta scan (unchanged from R4) ----------------
#define STGSZ  72704
#define OFF_KT 145408
#define OFF_UB 210944
#define SC_SMEM 227840

__global__ void __launch_bounds__(128) scan_mma(
    const __nv_bfloat16* __restrict__ QHp, const __nv_bfloat16* __restrict__ QLp,
    const __nv_bfloat16* __restrict__ WHp, const __nv_bfloat16* __restrict__ WLp,
    const __nv_bfloat16* __restrict__ KHp, const __nv_bfloat16* __restrict__ KLp,
    const __nv_bfloat16* __restrict__ AHp, const __nv_bfloat16* __restrict__ ALp,
    const float* __restrict__ Ug, float* __restrict__ Out)
{
    extern __shared__ char smraw[];
    const unsigned smb = (unsigned)__cvta_generic_to_shared(smraw);
    float* ub = (float*)(smraw + OFF_UB);
    const int tid = threadIdx.x, warp = tid>>5, lane = tid&31;
    const int bh = blockIdx.x>>4, cb = blockIdx.x&15;
    const int b = bh>>2, h = bh&3;
    const int g = lane>>2, qp = (lane&3)*2;
    const int brow16 = ((lane>>4)&1)*8 + (lane&7);
    const int bcol8 = ((lane>>3)&1)*8;

    float P[8][4];
    #pragma unroll
    for (int i=0;i<8;++i)
        #pragma unroll
        for (int r=0;r<4;++r) P[i][r]=0.f;

    auto issue = [&](int ci, int stg){
        const size_t b8 = (size_t)(bh*NCc + ci)*8192;
        const size_t b1 = (size_t)(bh*NCc + ci)*1024;
        const unsigned sb = smb + stg*STGSZ;
        const __nv_bfloat16* srcs[4] = {QHp+b8, QLp+b8, WHp+b8, WLp+b8};
        #pragma unroll
        for (int pl = 0; pl < 4; ++pl){
            const unsigned dsb = sb + pl*16384;
            for (int e = tid; e < 1024; e += 128){
                int row = e>>5, c = e&31;
                cpa16(dsb + row*512 + ((c^(row&7))<<4), srcs[pl] + row*256 + c*8);
            }
        }
        const unsigned kb2 = smb + OFF_KT + stg*32768;
        for (int e = tid; e < 1024; e += 128){
            int row = e>>2, c = e&3;
            cpa16(kb2 + row*64 + c*16, KHp + b8 + row*32 + c*8);
            cpa16(kb2 + 16384 + row*64 + c*16, KLp + b8 + row*32 + c*8);
        }
        {
            int row = tid>>2, c = tid&3;
            cpa16(sb + 65536 + row*80 + c*16, AHp + b1 + row*32 + c*8);
            cpa16(sb + 68096 + row*80 + c*16, ALp + b1 + row*32 + c*8);
            cpa16(sb + 70656 + row*64 + c*16, Ug + b8 + (size_t)row*256 + cb*16 + c*4);
        }
    };

    issue(0, 0); CP_COMMIT();

    for (int ci = 0; ci < NCc; ++ci) {
        const int stg = ci & 1;
        const unsigned sb = smb + stg*STGSZ;
        const unsigned kb = smb + OFF_KT + stg*32768;
        CP_WAIT0();
        __syncthreads();

        float accW[4][4], accQ[4][4];
        #pragma unroll
        for (int i=0;i<4;++i)
            #pragma unroll
            for (int r=0;r<4;++r){ accW[i][r]=0.f; accQ[i][r]=0.f; }
        #pragma unroll
        for (int kt = 0; kt < 4; ++kt) {
            unsigned Ah[4], Al[4];
            const float* p0 = P[2*kt]; const float* p1 = P[2*kt+1];
            Ah[0]=pack2(p0[0],p0[1]); Ah[1]=pack2(p0[2],p0[3]);
            Ah[2]=pack2(p1[0],p1[1]); Ah[3]=pack2(p1[2],p1[3]);
            Al[0]=pack2(res1(p0[0]),res1(p0[1])); Al[1]=pack2(res1(p0[2]),res1(p0[3]));
            Al[2]=pack2(res1(p1[0]),res1(p1[1])); Al[3]=pack2(res1(p1[2]),res1(p1[3]));
            const int dcol = warp*64 + kt*16 + bcol8;
            unsigned bwh[4][2], bwl[4][2], bqh[4][2], bql[4][2];
            #pragma unroll
            for (int ng = 0; ng < 2; ++ng) {
                const int row = ng*16 + brow16;
                const unsigned off = row*512 + ((((unsigned)(dcol>>3))^(row&7))<<4);
                unsigned r4[4];
                ldsm4(r4, sb + 32768 + off);
                bwh[2*ng][0]=r4[0]; bwh[2*ng][1]=r4[1]; bwh[2*ng+1][0]=r4[2]; bwh[2*ng+1][1]=r4[3];
                ldsm4(r4, sb + 49152 + off);
                bwl[2*ng][0]=r4[0]; bwl[2*ng][1]=r4[1]; bwl[2*ng+1][0]=r4[2]; bwl[2*ng+1][1]=r4[3];
                ldsm4(r4, sb + off);
                bqh[2*ng][0]=r4[0]; bqh[2*ng][1]=r4[1]; bqh[2*ng+1][0]=r4[2]; bqh[2*ng+1][1]=r4[3];
                ldsm4(r4, sb + 16384 + off);
                bql[2*ng][0]=r4[0]; bql[2*ng][1]=r4[1]; bql[2*ng+1][0]=r4[2]; bql[2*ng+1][1]=r4[3];
            }
            #pragma unroll
            for (int nt = 0; nt < 4; ++nt) {
                mma16816(accW[nt], Ah, bwh[nt]);
                mma16816(accW[nt], Al, bwh[nt]);
                mma16816(accW[nt], Ah, bwl[nt]);
                mma16816(accQ[nt], Ah, bqh[nt]);
                mma16816(accQ[nt], Al, bqh[nt]);
                mma16816(accQ[nt], Ah, bql[nt]);
            }
        }
        #pragma unroll
        for (int nt = 0; nt < 4; ++nt)
            #pragma unroll
            for (int r = 0; r < 4; ++r) {
                int c = g + ((r>>1)<<3), t = nt*8 + qp + (r&1);
                ub[(c*4+warp)*66 + t] = accW[nt][r];
                ub[(c*4+warp)*66 + 32 + t] = accQ[nt][r];
            }
        if (ci + 1 < NCc) { issue(ci+1, stg^1); CP_COMMIT(); }
        __syncthreads();

        const float* su = (const float*)(smraw + stg*STGSZ + 70656);
        unsigned UH[2][4], UL[2][4];
        #pragma unroll
        for (int kt = 0; kt < 2; ++kt) {
            float v[8];
            #pragma unroll
            for (int p = 0; p < 8; ++p) {
                const int c = g + (((p>>1)&1)<<3);
                const int t = kt*16 + qp + (p&1) + ((p>>2)<<3);
                const int bi = (c*4)*66 + t;
                v[p] = su[t*16 + c] + ub[bi] + ub[bi+66] + ub[bi+132] + ub[bi+198];
            }
            UH[kt][0]=pack2(v[0],v[1]); UH[kt][1]=pack2(v[2],v[3]);
            UH[kt][2]=pack2(v[4],v[5]); UH[kt][3]=pack2(v[6],v[7]);
            UL[kt][0]=pack2(res1(v[0]),res1(v[1])); UL[kt][1]=pack2(res1(v[2]),res1(v[3]));
            UL[kt][2]=pack2(res1(v[4]),res1(v[5])); UL[kt][3]=pack2(res1(v[6]),res1(v[7]));
        }
        float oc[4];
        const int i0 = warp*8 + qp;
        #pragma unroll
        for (int r = 0; r < 4; ++r) {
            const int c = g + ((r>>1)<<3);
            const int bi = (c*4)*66 + 32 + i0 + (r&1);
            oc[r] = -(ub[bi] + ub[bi+66] + ub[bi+132] + ub[bi+198]);
        }

        #pragma unroll
        for (int kt = 0; kt < 2; ++kt) {
            unsigned bh2[2], bl2[2];
            const unsigned aoff = (warp*8 + (lane&7))*80 + (kt*16 + bcol8)*2;
            ldsm2(bh2, sb + 65536 + aoff);
            ldsm2(bl2, sb + 68096 + aoff);
            mma16816(oc, UH[kt], bh2);
            mma16816(oc, UL[kt], bh2);
            mma16816(oc, UH[kt], bl2);
        }
        {
            const size_t base = ((size_t)(b*Ll + ci*CSs + i0))*HD + h*256 + cb*16;
            Out[base + g]          = oc[0];
            Out[base + HD + g]     = oc[1];
            Out[base + g + 8]      = oc[2];
            Out[base + HD + g + 8] = oc[3];
        }

        #pragma unroll
        for (int kt = 0; kt < 2; ++kt) {
            #pragma unroll
            for (int np = 0; np < 4; ++np) {
                unsigned bh4[4], bl4[4];
                const unsigned off = (warp*64 + np*16 + brow16)*64 + (kt*16 + bcol8)*2;
                ldsm4(bh4, kb + off);
                ldsm4(bl4, kb + 16384 + off);
                mma16816(P[2*np],   UH[kt], bh4);
                mma16816(P[2*np],   UL[kt], bh4);
                mma16816(P[2*np],   UH[kt], bl4);
                mma16816(P[2*np+1], UH[kt], bh4+2);
                mma16816(P[2*np+1], UL[kt], bh4+2);
                mma16816(P[2*np+1], UH[kt], bl4+2);
            }
        }
    }
}

// ---------------- FIR short/long + gate_in ----------------
__global__ void fir_gatein_kernel(const float* __restrict__ hs, const float* __restrict__ V,
                                  const float* __restrict__ ws, const float* __restrict__ wl,
                                  const float* __restrict__ Dl,
                                  float* __restrict__ Sout, float* __restrict__ Lout,
                                  float* __restrict__ Gin)
{
    const int blk = blockIdx.x;
    const int b = blk / (Ll/8);
    const int l0 = (blk % (Ll/8)) * 8;
    const int tid = threadIdx.x;
    float smean[8], lmean[8], dmean[8];
    #pragma unroll
    for (int r = 0; r < 8; ++r) { smean[r]=0.f; lmean[r]=0.f; dmean[r]=0.f; }
    for (int j = 0; j < 4; ++j) {
        const int ch = tid + 256*j;
        float win[38];
        #pragma unroll
        for (int t = 0; t < 38; ++t) {
            const int l = l0 - 30 + t;
            win[t] = (l >= 0) ? V[((size_t)(b*Ll + l))*HD + ch] : 0.f;
        }
        float wlr[31];
        #pragma unroll
        for (int t = 0; t < 31; ++t) wlr[t] = wl[ch*31 + t];
        const float w0 = ws[ch*3+0], w1 = ws[ch*3+1], w2 = ws[ch*3+2];
        #pragma unroll
        for (int r = 0; r < 8; ++r) {
            float yl = 0.f;
            #pragma unroll
            for (int t = 0; t < 31; ++t) yl += win[r+t]*wlr[t];
            const float ysv = win[r+28]*w0 + win[r+29]*w1 + win[r+30]*w2;
            const size_t row = (size_t)(b*Ll + l0 + r);
            Sout[row*HD + ch] = ysv;
            Lout[row*HD + ch] = yl;
            smean[r] += ysv; lmean[r] += yl;
            dmean[r] += Dl[row*HD + ch];
        }
    }
    for (int r = 0; r < 8; ++r) {
        const size_t row = (size_t)(b*Ll + l0 + r);
        float* grow = Gin + row*GIN;
        #pragma unroll
        for (int j = 0; j < 4; ++j) grow[tid + 256*j] = hs[row*HD + tid + 256*j];
        grow[1024 + tid] = smean[r]*0.25f;
        grow[1280 + tid] = lmean[r]*0.25f;
        grow[1536 + tid] = dmean[r]*0.25f;
    }
}

// ---------------- gate head 2 ----------------
__global__ void gate2_wgt(const float* __restrict__ GH2, const float* __restrict__ W2,
                          const float* __restrict__ b2, const float* __restrict__ ltemp,
                          float* __restrict__ Wgt)
{
    const int row = blockIdx.x;
    const int warp = threadIdx.x >> 5, lane = threadIdx.x & 31;
    __shared__ float lg[4];
    const float* x = GH2 + (size_t)row*GHID;
    const float* w = W2 + warp*GHID;
    float s = 0.f;
    for (int i = lane; i < GHID; i += 32) s += x[i]*w[i];
    #pragma unroll
    for (int o = 16; o; o >>= 1) s += __shfl_xor_sync(0xffffffff, s, o);
    if (lane == 0) lg[warp] = s + b2[warp];
    __syncthreads();
    if (threadIdx.x == 0) {
        const float t = log1pf(expf(ltemp[0])) + 1e-4f;
        float m = fmaxf(fmaxf(lg[0], lg[1]), fmaxf(lg[2], lg[3]));
        float e[4]; float se = 0.f;
        #pragma unroll
        for (int j = 0; j < 4; ++j) { e[j] = expf((lg[j]-m)/t); se += e[j]; }
        #pragma unroll
        for (int j = 0; j < 4; ++j) e[j] /= se;
        const float fl = 0.05f * e[3];
        e[0] = fmaxf(e[0], fl);
        e[1] = fmaxf(e[1], fl);
        const float s2 = e[0]+e[1]+e[2]+e[3];
        #pragma unroll
        for (int j = 0; j < 4; ++j) Wgt[row*4+j] = e[j]/s2;
    }
}

// ---------------- combine + RMSNorm ----------------
__global__ void combine_kernel(const float* __restrict__ Sh, const float* __restrict__ Lg,
                               const float* __restrict__ Dl, const float* __restrict__ V,
                               const float* __restrict__ Wgt, const float* __restrict__ onw,
                               float* __restrict__ O)
{
    const int row = blockIdx.x;
    const int tid = threadIdx.x, lane = tid & 31;
    __shared__ float red[4];
    if (tid < 4) red[tid] = 0.f;
    __syncthreads();
    const float w0 = Wgt[row*4+0], w1 = Wgt[row*4+1], w2 = Wgt[row*4+2], w3 = Wgt[row*4+3];
    float ov[4];
    #pragma unroll
    for (int j = 0; j < 4; ++j) {
        const size_t g = (size_t)row*HD + tid + 256*j;
        ov[j] = w0*Sh[g] + w1*Lg[g] + w2*Dl[g] + w3*V[g];
        float v = ov[j]*ov[j];
        #pragma unroll
        for (int o = 16; o; o >>= 1) v += __shfl_xor_sync(0xffffffff, v, o);
        if (lane == 0) atomicAdd(&red[j], v);
    }
    __syncthreads();
    #pragma unroll
    for (int j = 0; j < 4; ++j) {
        const float sc = rsqrtf(red[j]*(1.f/256.f) + 1e-5f) * onw[tid];
        O[(size_t)row*HD + tid + 256*j] = ov[j]*sc;
    }
}

// ---------------- launch ----------------
static inline void split_launch(const float* x, __nv_bfloat16* hi, __nv_bfloat16* lo, size_t n)
{
    int n4 = (int)(n >> 2);
    split_kernel<<<(n4 + 255)/256, 256>>>((const float4*)x, (uint2*)hi, (uint2*)lo, n4);
}

extern "C" void kernel_launch(void* const* d_in, const int* in_sizes, int n_in,
                              void* d_out, int out_size)
{
    const float* hs  = (const float*)d_in[0];
    const float* qw  = (const float*)d_in[1];
    const float* kw  = (const float*)d_in[2];
    const float* vw  = (const float*)d_in[3];
    const float* bw  = (const float*)d_in[4];
    const float* qcw = (const float*)d_in[5];
    const float* kcw = (const float*)d_in[6];
    const float* vcw = (const float*)d_in[7];
    const float* fsw = (const float*)d_in[8];
    const float* flw = (const float*)d_in[9];
    const float* w1  = (const float*)d_in[10];
    const float* b1  = (const float*)d_in[11];
    const float* w2  = (const float*)d_in[12];
    const float* b2  = (const float*)d_in[13];
    const float* lt  = (const float*)d_in[14];
    const float* onw = (const float*)d_in[15];
    const float* ow  = (const float*)d_in[16];
    float* out = (float*)d_out;

    float *xqkv,*q,*k,*v,*u,*delta,*shrt,*lng,*gin,*gh,*beta,*wgt,*ocomb;
    __nv_bfloat16 *hsH,*hsL,*ginH,*ginL,*ocH,*ocL,*wtH,*wtL;
    __nv_bfloat16 *qh,*ql,*wh,*wlp,*kh,*kl,*ah,*al;
    cudaGetSymbolAddress((void**)&xqkv, g_xqkv);
    cudaGetSymbolAddress((void**)&q,    g_q);
    cudaGetSymbolAddress((void**)&k,    g_k);
    cudaGetSymbolAddress((void**)&v,    g_v);
    cudaGetSymbolAddress((void**)&u,    g_u);
    cudaGetSymbolAddress((void**)&delta,g_delta);
    cudaGetSymbolAddress((void**)&shrt, g_short);
    cudaGetSymbolAddress((void**)&lng,  g_long);
    cudaGetSymbolAddress((void**)&gin,  g_gin);
    cudaGetSymbolAddress((void**)&gh,   g_gh);
    cudaGetSymbolAddress((void**)&beta, g_beta);
    cudaGetSymbolAddress((void**)&wgt,  g_wgt);
    cudaGetSymbolAddress((void**)&ocomb,g_ocomb);
    cudaGetSymbolAddress((void**)&hsH,  g_hsH);
    cudaGetSymbolAddress((void**)&hsL,  g_hsL);
    cudaGetSymbolAddress((void**)&ginH, g_ginH);
    cudaGetSymbolAddress((void**)&ginL, g_ginL);
    cudaGetSymbolAddress((void**)&ocH,  g_ocH);
    cudaGetSymbolAddress((void**)&ocL,  g_ocL);
    cudaGetSymbolAddress((void**)&wtH,  g_wtH);
    cudaGetSymbolAddress((void**)&wtL,  g_wtL);
    cudaGetSymbolAddress((void**)&qh,   g_qh);
    cudaGetSymbolAddress((void**)&ql,   g_ql);
    cudaGetSymbolAddress((void**)&wh,   g_wh);
    cudaGetSymbolAddress((void**)&wlp,  g_wl);
    cudaGetSymbolAddress((void**)&kh,   g_kh);
    cudaGetSymbolAddress((void**)&kl,   g_kl);
    cudaGetSymbolAddress((void**)&ah,   g_ah);
    cudaGetSymbolAddress((void**)&al,   g_al);

    cudaFuncSetAttribute(precompute_kernel, cudaFuncAttributeMaxDynamicSharedMemorySize, PRE_SMEM);
    cudaFuncSetAttribute(scan_mma, cudaFuncAttributeMaxDynamicSharedMemorySize, SC_SMEM);

    split_launch(hs, hsH, hsL, (size_t)BL*Dd);
    split_launch(qw, wtH + WOFF_Q,  wtL + WOFF_Q,  (size_t)1024*1024);
    split_launch(kw, wtH + WOFF_K,  wtL + WOFF_K,  (size_t)1024*1024);
    split_launch(vw, wtH + WOFF_V,  wtL + WOFF_V,  (size_t)1024*1024);
    split_launch(w1, wtH + WOFF_W1, wtL + WOFF_W1, (size_t)GHID*GIN);
    split_launch(ow, wtH + WOFF_O,  wtL + WOFF_O,  (size_t)Dd*HD);

    // fused q/k/v projection: C[8192,3072]
    hgemm_nt<false><<<dim3(3072/128, BL/128), 256>>>(hsH, hsL, wtH+WOFF_Q, wtL+WOFF_Q,
                                                     xqkv, BL, 3072, Dd, nullptr);
    beta_kernel<<<BL, 128>>>(hs, bw, beta);
    conv_silu_norm<<<BL, 256>>>(xqkv, qcw, kcw, vcw, q, k, v);
    precompute_kernel<<<8*NCc, 256, PRE_SMEM>>>(q, k, v, beta, u,
                                                qh, ql, wh, wlp, kh, kl, ah, al);
    scan_mma<<<128, 128, SC_SMEM>>>(qh, ql, wh, wlp, kh, kl, ah, al, u, delta);
    fir_gatein_kernel<<<Bb*(Ll/8), 256>>>(hs, v, fsw, flw, delta, shrt, lng, gin);
    split_launch(gin, ginH, ginL, (size_t)BL*GIN);
    hgemm_nt<true><<<dim3(GHID/128, BL/128), 256>>>(ginH, ginL, wtH+WOFF_W1, wtL+WOFF_W1,
                                                    gh, BL, GHID, GIN, b1);
    gate2_wgt<<<BL, 128>>>(gh, w2, b2, lt, wgt);
    combine_kernel<<<BL, 256>>>(shrt, lng, delta, v, wgt, onw, ocomb);
    split_launch(ocomb, ocH, ocL, (size_t)BL*HD);
    hgemm_nt<false><<<dim3(Dd/128, BL/128), 256>>>(ocH, ocL, wtH+WOFF_O, wtL+WOFF_O,
                                                   out, BL, Dd, HD, nullptr);
}

// round 7
// speedup vs baseline: 2.9583x; 1.0064x over previous
#include <cuda_runtime.h>
#include <cuda_bf16.h>
#include <math.h>

#define Bb   2
#define Ll   4096
#define Dd   1024
#define Hh   4
#define CSs  32
#define NCc  128
#define BL   (Bb*Ll)
#define HD   1024
#define GIN  1792
#define GHID 1024
#define CH8  (8*NCc*8192)

// ---------------- scratch ----------------
__device__ float g_xqkv[BL*3072];
__device__ float g_q [BL*HD];
__device__ float g_k [BL*HD];
__device__ float g_v [BL*HD];
__device__ float g_u [CH8];
__device__ float g_delta[BL*HD];
__device__ float g_short[BL*HD];
__device__ float g_long [BL*HD];
__device__ float g_gh [BL*GHID];
__device__ float g_beta[BL*Hh];
__device__ float g_wgt [BL*4];

__device__ __align__(16) __nv_bfloat16 g_hsH[BL*Dd];
__device__ __align__(16) __nv_bfloat16 g_hsL[BL*Dd];
__device__ __align__(16) __nv_bfloat16 g_ginH[BL*GIN];
__device__ __align__(16) __nv_bfloat16 g_ginL[BL*GIN];
__device__ __align__(16) __nv_bfloat16 g_ocH[BL*HD];
__device__ __align__(16) __nv_bfloat16 g_ocL[BL*HD];
#define WOFF_Q  0
#define WOFF_K  (1024*1024)
#define WOFF_V  (2*1024*1024)
#define WOFF_W1 (3*1024*1024)
#define WOFF_O  (3*1024*1024 + 1792*1024)
#define WTOT    (WOFF_O + 1024*1024)
__device__ __align__(16) __nv_bfloat16 g_wtH[WTOT];
__device__ __align__(16) __nv_bfloat16 g_wtL[WTOT];

// scan operand planes
__device__ __align__(16) __nv_bfloat16 g_qh[CH8], g_ql[CH8], g_wh[CH8], g_wl[CH8], g_kh[CH8], g_kl[CH8];
__device__ __align__(16) __nv_bfloat16 g_ah[8*NCc*1024], g_al[8*NCc*1024];

// ---------------- helpers ----------------
__device__ __forceinline__ float siluf(float x){ return x / (1.f + expf(-x)); }
__device__ __forceinline__ float geluf(float x){ return 0.5f * x * (1.f + erff(x * 0.70710678118654752f)); }
__device__ __forceinline__ void ldsm4(unsigned* r, unsigned addr){
    asm volatile("ldmatrix.sync.aligned.m8n8.x4.shared.b16 {%0,%1,%2,%3}, [%4];"
        : "=r"(r[0]),"=r"(r[1]),"=r"(r[2]),"=r"(r[3]) : "r"(addr));
}
__device__ __forceinline__ void ldsm4t(unsigned* r, unsigned addr){
    asm volatile("ldmatrix.sync.aligned.m8n8.x4.trans.shared.b16 {%0,%1,%2,%3}, [%4];"
        : "=r"(r[0]),"=r"(r[1]),"=r"(r[2]),"=r"(r[3]) : "r"(addr));
}
__device__ __forceinline__ void ldsm2(unsigned* r, unsigned addr){
    asm volatile("ldmatrix.sync.aligned.m8n8.x2.shared.b16 {%0,%1}, [%2];"
        : "=r"(r[0]),"=r"(r[1]) : "r"(addr));
}
__device__ __forceinline__ void mma16816(float* c, const unsigned* a, const unsigned* b){
    asm volatile("mma.sync.aligned.m16n8k16.row.col.f32.bf16.bf16.f32 "
        "{%0,%1,%2,%3}, {%4,%5,%6,%7}, {%8,%9}, {%0,%1,%2,%3};"
        : "+f"(c[0]),"+f"(c[1]),"+f"(c[2]),"+f"(c[3])
        : "r"(a[0]),"r"(a[1]),"r"(a[2]),"r"(a[3]), "r"(b[0]),"r"(b[1]));
}
__device__ __forceinline__ void cpa16(unsigned d, const void* s){
    asm volatile("cp.async.cg.shared.global [%0],[%1],16;\n" :: "r"(d), "l"(s));
}
#define CP_COMMIT() asm volatile("cp.async.commit_group;\n")
#define CP_WAIT0()  asm volatile("cp.async.wait_group 0;\n")
__device__ __forceinline__ unsigned pack2(float a, float b){
    __nv_bfloat162 t; t.x=__float2bfloat16(a); t.y=__float2bfloat16(b);
    return *(unsigned*)&t;
}
__device__ __forceinline__ float res1(float v){ return v - __bfloat162float(__float2bfloat16(v)); }
__device__ __forceinline__ void split1(float v, __nv_bfloat16& h, __nv_bfloat16& l){
    h = __float2bfloat16(v); l = __float2bfloat16(v - __bfloat162float(h));
}

// ---------------- fp32 -> (hi,lo) bf16 split ----------------
__global__ void split_kernel(const float4* __restrict__ x, uint2* __restrict__ hi,
                             uint2* __restrict__ lo, int n4)
{
    int i = blockIdx.x*blockDim.x + threadIdx.x;
    if (i >= n4) return;
    float4 v = x[i];
    uint2 ho, loo;
    ho.x = pack2(v.x, v.y);  ho.y = pack2(v.z, v.w);
    loo.x = pack2(res1(v.x), res1(v.y)); loo.y = pack2(res1(v.z), res1(v.w));
    hi[i] = ho; lo[i] = loo;
}

// ---------------- bf16x3 split GEMM, double-buffered ----------
template<bool EPI>
__global__ void __launch_bounds__(256) hgemm_nt(const __nv_bfloat16* __restrict__ Ah,
                                                const __nv_bfloat16* __restrict__ Al,
                                                const __nv_bfloat16* __restrict__ Bh,
                                                const __nv_bfloat16* __restrict__ Bl,
                                                float* __restrict__ C,
                                                int M, int N, int K,
                                                const float* __restrict__ bias)
{
    __shared__ __align__(16) __nv_bfloat16 sm[2][4*128*24];
    const int PL = 128*24;
    const int tid = threadIdx.x;
    const int bm = blockIdx.y*128, bn = blockIdx.x*128;
    const int warp = tid>>5, lane = tid&31;
    const int wm = warp>>2, wn = warp&3;
    float acc[4][4][4];
    #pragma unroll
    for (int i=0;i<4;i++) for(int j=0;j<4;j++) for(int r=0;r<4;r++) acc[i][j][r]=0.f;
    const size_t aoff = (size_t)(bm + (tid>>1))*K + (tid&1)*8;
    const size_t boff = (size_t)(bn + (tid>>1))*K + (tid&1)*8;
    const int sto = (tid>>1)*24 + (tid&1)*8;
    unsigned base = (unsigned)__cvta_generic_to_shared(&sm[0][0]);
    const int arow = wm*64 + (lane&15);
    const int acol = (lane>>4)*8;
    const int brow = wn*32 + ((lane>>4)&1)*8 + (lane&7);
    const int bcol = ((lane>>3)&1)*8;
    const int nk = K >> 4;
    {
        uint4 rAh = *(const uint4*)(Ah + aoff);
        uint4 rAl = *(const uint4*)(Al + aoff);
        uint4 rBh = *(const uint4*)(Bh + boff);
        uint4 rBl = *(const uint4*)(Bl + boff);
        *(uint4*)(&sm[0][0] + sto) = rAh;
        *(uint4*)(&sm[0][0] + PL + sto) = rAl;
        *(uint4*)(&sm[0][0] + 2*PL + sto) = rBh;
        *(uint4*)(&sm[0][0] + 3*PL + sto) = rBl;
    }
    __syncthreads();
    for (int kt = 0; kt < nk; ++kt) {
        const int cur = kt & 1;
        const unsigned sb = base + (unsigned)cur*(8*PL);
        uint4 nAh, nAl, nBh, nBl;
        const bool more = (kt + 1 < nk);
        if (more) {
            const size_t ka = aoff + (size_t)(kt+1)*16;
            const size_t kb = boff + (size_t)(kt+1)*16;
            nAh = *(const uint4*)(Ah + ka); nAl = *(const uint4*)(Al + ka);
            nBh = *(const uint4*)(Bh + kb); nBl = *(const uint4*)(Bl + kb);
        }
        unsigned bh[4][2], bl[4][2];
        #pragma unroll
        for (int ng = 0; ng < 2; ++ng) {
            unsigned r4[4];
            ldsm4(r4, sb + 2u*(2*PL + (brow + ng*16)*24 + bcol));
            bh[2*ng][0]=r4[0]; bh[2*ng][1]=r4[1]; bh[2*ng+1][0]=r4[2]; bh[2*ng+1][1]=r4[3];
            ldsm4(r4, sb + 2u*(3*PL + (brow + ng*16)*24 + bcol));
            bl[2*ng][0]=r4[0]; bl[2*ng][1]=r4[1]; bl[2*ng+1][0]=r4[2]; bl[2*ng+1][1]=r4[3];
        }
        #pragma unroll
        for (int mt = 0; mt < 4; ++mt) {
            unsigned ah[4], al[4];
            ldsm4(ah, sb + 2u*((arow + mt*16)*24 + acol));
            ldsm4(al, sb + 2u*(PL + (arow + mt*16)*24 + acol));
            #pragma unroll
            for (int nt = 0; nt < 4; ++nt) {
                mma16816(acc[mt][nt], ah, bh[nt]);
                mma16816(acc[mt][nt], ah, bl[nt]);
                mma16816(acc[mt][nt], al, bh[nt]);
            }
        }
        if (more) {
            __nv_bfloat16* d = &sm[cur^1][0];
            *(uint4*)(d + sto) = nAh;
            *(uint4*)(d + PL + sto) = nAl;
            *(uint4*)(d + 2*PL + sto) = nBh;
            *(uint4*)(d + 3*PL + sto) = nBl;
            __syncthreads();
        }
    }
    const int g = lane>>2, tig = lane&3;
    #pragma unroll
    for (int mt = 0; mt < 4; ++mt) {
        const int row0 = bm + wm*64 + mt*16 + g;
        #pragma unroll
        for (int nt = 0; nt < 4; ++nt) {
            const int col = bn + wn*32 + nt*8 + tig*2;
            float v0 = acc[mt][nt][0], v1 = acc[mt][nt][1];
            float v2 = acc[mt][nt][2], v3 = acc[mt][nt][3];
            if (EPI) {
                const float bz0 = bias[col], bz1 = bias[col+1];
                v0 = geluf(v0+bz0); v1 = geluf(v1+bz1);
                v2 = geluf(v2+bz0); v3 = geluf(v3+bz1);
            }
            *(float2*)(C + (size_t)row0*N + col)     = make_float2(v0, v1);
            *(float2*)(C + (size_t)(row0+8)*N + col) = make_float2(v2, v3);
        }
    }
}

// ---------------- bf16x3 GEMM variant writing bf16 hi/lo C (for o_proj input path) ----
// (identical mainloop; epilogue writes fp32 to C only) — reuse hgemm_nt for all.

// ---------------- beta ----------------
__global__ void beta_kernel(const float* __restrict__ hs, const float* __restrict__ bw,
                            float* __restrict__ beta)
{
    const int row = blockIdx.x;
    const int warp = threadIdx.x >> 5, lane = threadIdx.x & 31;
    const float* x = hs + (size_t)row * Dd;
    const float* w = bw + warp * Dd;
    float s = 0.f;
    for (int i = lane; i < Dd; i += 32) s += x[i] * w[i];
    #pragma unroll
    for (int o = 16; o; o >>= 1) s += __shfl_xor_sync(0xffffffff, s, o);
    if (lane == 0) beta[row*4 + warp] = 1.f / (1.f + expf(-s));
}

// ---------------- conv + silu + l2norm (reads fused xqkv) ----------------
__global__ void conv_silu_norm(const float* __restrict__ XQKV,
                               const float* __restrict__ WQ, const float* __restrict__ WK,
                               const float* __restrict__ WV,
                               float* __restrict__ Qo, float* __restrict__ Ko,
                               float* __restrict__ Vo)
{
    const int row = blockIdx.x;
    const int b = row >> 12, l = row & (Ll-1);
    const int tid = threadIdx.x;
    const int lane = tid & 31;
    __shared__ float redq[4], redk[4];
    if (tid < 4) { redq[tid] = 0.f; redk[tid] = 0.f; }
    __syncthreads();
    float yq[4], yk[4];
    #pragma unroll
    for (int j = 0; j < 4; ++j) {
        const int c = tid + 256*j;
        float aq=0.f, ak=0.f, av=0.f;
        #pragma unroll
        for (int t = 0; t < 4; ++t) {
            const int ll = l - 3 + t;
            if (ll >= 0) {
                const size_t g3 = ((size_t)(b*Ll + ll))*3072;
                aq += XQKV[g3 + c]*WQ[c*4+t];
                ak += XQKV[g3 + 1024 + c]*WK[c*4+t];
                av += XQKV[g3 + 2048 + c]*WV[c*4+t];
            }
        }
        aq = siluf(aq); ak = siluf(ak); av = siluf(av);
        Vo[(size_t)row*HD + c] = av;
        yq[j] = aq; yk[j] = ak;
        float vq = aq*aq, vk = ak*ak;
        #pragma unroll
        for (int o = 16; o; o >>= 1) {
            vq += __shfl_xor_sync(0xffffffff, vq, o);
            vk += __shfl_xor_sync(0xffffffff, vk, o);
        }
        if (lane == 0) { atomicAdd(&redq[j], vq); atomicAdd(&redk[j], vk); }
    }
    __syncthreads();
    #pragma unroll
    for (int j = 0; j < 4; ++j) {
        const int c = tid + 256*j;
        Qo[(size_t)row*HD + c] = yq[j]*rsqrtf(redq[j] + 1e-12f);
        Ko[(size_t)row*HD + c] = yk[j]*rsqrtf(redk[j] + 1e-12f);
    }
}

// ---------------- precompute (tensor-core) ----------------
#define PPLN 16896
#define OQH 0
#define OQL 16896
#define OKH 33792
#define OKL 50688
#define OVH 67584
#define OVL 84480
#define OBH 101376
#define OBL 118272
#define OTH 135168
#define OTL 137728
#define OAM 140288
#define OTI 144512
#define OSB 148736
#define PRE_SMEM 148992

__global__ void __launch_bounds__(256) precompute_kernel(
    const float* __restrict__ Qn, const float* __restrict__ Kn,
    const float* __restrict__ V,  const float* __restrict__ beta,
    float* __restrict__ U,
    __nv_bfloat16* __restrict__ QH, __nv_bfloat16* __restrict__ QL,
    __nv_bfloat16* __restrict__ WH, __nv_bfloat16* __restrict__ WL,
    __nv_bfloat16* __restrict__ KH, __nv_bfloat16* __restrict__ KL,
    __nv_bfloat16* __restrict__ AH, __nv_bfloat16* __restrict__ AL)
{
    extern __shared__ char smraw[];
    const unsigned smb = (unsigned)__cvta_generic_to_shared(smraw);
    float* Amp = (float*)(smraw + OAM);
    float* Tip = (float*)(smraw + OTI);
    float* sbp = (float*)(smraw + OSB);
    const int idx = blockIdx.x;
    const int bh = idx >> 7, ci = idx & 127;
    const int b = bh >> 2, h = bh & 3;
    const int tid = threadIdx.x, warp = tid>>5, lane = tid&31;
    const int g = lane>>2, qp = (lane&3)*2;
    const size_t cb8 = (size_t)idx*8192;
    const size_t cb1 = (size_t)idx*1024;

    if (tid < 32) sbp[tid] = beta[(size_t)(b*Ll + ci*CSs + tid)*4 + h];
    __syncthreads();

    for (int e = tid; e < 8192; e += 256) {
        const int i = e >> 8, d = e & 255;
        const size_t gg = ((size_t)(b*Ll + ci*CSs + i))*HD + h*256 + d;
        const float qv = Qn[gg], kv = Kn[gg], vv = V[gg];
        const float bi = sbp[i];
        __nv_bfloat16 hh, ll;
        split1(qv, hh, ll);
        *(__nv_bfloat16*)(smraw + OQH + (i*264+d)*2) = hh;
        *(__nv_bfloat16*)(smraw + OQL + (i*264+d)*2) = ll;
        QH[cb8+e] = hh; QL[cb8+e] = ll;
        split1(kv, hh, ll);
        *(__nv_bfloat16*)(smraw + OKH + (i*264+d)*2) = hh;
        *(__nv_bfloat16*)(smraw + OKL + (i*264+d)*2) = ll;
        split1(vv*bi, hh, ll);
        *(__nv_bfloat16*)(smraw + OVH + (i*264+d)*2) = hh;
        *(__nv_bfloat16*)(smraw + OVL + (i*264+d)*2) = ll;
        split1(kv*bi, hh, ll);
        *(__nv_bfloat16*)(smraw + OBH + (i*264+d)*2) = hh;
        *(__nv_bfloat16*)(smraw + OBL + (i*264+d)*2) = ll;
    }
    __syncthreads();

    {
        const int mt = warp>>2, ntw = warp&3;
        float qk[4] = {0,0,0,0}, kk[4] = {0,0,0,0};
        const unsigned arow_off = (mt*16 + (lane&15))*528 + ((lane>>4)*8)*2;
        const unsigned brow_off = (ntw*8 + (lane&7))*528 + (((lane>>3)&1)*8)*2;
        #pragma unroll
        for (int kt = 0; kt < 16; ++kt) {
            const unsigned kb2 = kt*32;
            unsigned aq[4], aql[4], ak4[4], akl[4], b2h[2], b2l[2];
            ldsm4(aq,  smb + OQH + arow_off + kb2);
            ldsm4(aql, smb + OQL + arow_off + kb2);
            ldsm4(ak4, smb + OKH + arow_off + kb2);
            ldsm4(akl, smb + OKL + arow_off + kb2);
            ldsm2(b2h, smb + OKH + brow_off + kb2);
            ldsm2(b2l, smb + OKL + brow_off + kb2);
            mma16816(qk, aq, b2h);  mma16816(qk, aql, b2h); mma16816(qk, aq, b2l);
            mma16816(kk, ak4, b2h); mma16816(kk, akl, b2h); mma16816(kk, ak4, b2l);
        }
        const int i0 = mt*16 + g, j0 = ntw*8 + qp;
        #pragma unroll
        for (int r = 0; r < 4; ++r) {
            const int i = i0 + (r>>1)*8, j = j0 + (r&1);
            Amp[i*33+j] = (i > j) ? sbp[i]*kk[r] : 0.f;
            const float av = (i >= j) ? qk[r] : 0.f;
            __nv_bfloat16 hh, ll;
            split1(av, hh, ll);
            AH[cb1 + i*32 + j] = hh; AL[cb1 + i*32 + j] = ll;
        }
    }
    for (int e = tid; e < 8192; e += 256) {
        const int d = e >> 5, t = e & 31;
        unsigned short hv = *(unsigned short*)(smraw + OKH + (t*264+d)*2) ^ 0x8000u;
        unsigned short lv = *(unsigned short*)(smraw + OKL + (t*264+d)*2) ^ 0x8000u;
        KH[cb8+e] = *(__nv_bfloat16*)&hv;
        KL[cb8+e] = *(__nv_bfloat16*)&lv;
    }
    __syncthreads();

    if (tid < 32) {
        const int j = tid;
        Tip[j] = (j == 0) ? 1.f : 0.f;
        for (int i2 = 1; i2 < 32; ++i2) {
            __syncwarp();
            float s = 0.f;
            for (int m = 0; m < i2; ++m) s += Amp[i2*33+m]*Tip[m*33+j];
            Tip[i2*33+j] = ((i2 == j) ? 1.f : 0.f) - s;
        }
    }
    __syncthreads();
    for (int e = tid; e < 1024; e += 256) {
        const int i = e >> 5, j = e & 31;
        __nv_bfloat16 hh, ll;
        split1(Tip[i*33+j], hh, ll);
        *(__nv_bfloat16*)(smraw + OTH + (i*40+j)*2) = hh;
        *(__nv_bfloat16*)(smraw + OTL + (i*40+j)*2) = ll;
    }
    __syncthreads();

    {
        const int mt = warp>>2;
        unsigned TiH[2][4], TiL[2][4];
        #pragma unroll
        for (int kt = 0; kt < 2; ++kt) {
            const unsigned ao = (mt*16 + (lane&15))*80 + (kt*16 + (lane>>4)*8)*2;
            ldsm4(TiH[kt], smb + OTH + ao);
            ldsm4(TiL[kt], smb + OTL + ao);
        }
        const int i0 = mt*16 + g;
        #pragma unroll
        for (int ng = 0; ng < 4; ++ng) {
            const int n0 = (warp&3)*64 + ng*16;
            float aU[2][4], aW[2][4];
            #pragma unroll
            for (int t2 = 0; t2 < 2; ++t2)
                #pragma unroll
                for (int r = 0; r < 4; ++r) { aU[t2][r]=0.f; aW[t2][r]=0.f; }
            #pragma unroll
            for (int kt = 0; kt < 2; ++kt) {
                const unsigned brow = kt*16 + (lane&7) + ((lane>>3)&1)*8;
                const unsigned bcol = n0 + ((lane>>4)&1)*8;
                const unsigned bo = brow*528 + bcol*2;
                unsigned bvh[4], bvl[4], bbh[4], bbl[4];
                ldsm4t(bvh, smb + OVH + bo);
                ldsm4t(bvl, smb + OVL + bo);
                ldsm4t(bbh, smb + OBH + bo);
                ldsm4t(bbl, smb + OBL + bo);
                #pragma unroll
                for (int nt = 0; nt < 2; ++nt) {
                    mma16816(aU[nt], TiH[kt], bvh+2*nt);
                    mma16816(aU[nt], TiL[kt], bvh+2*nt);
                    mma16816(aU[nt], TiH[kt], bvl+2*nt);
                    mma16816(aW[nt], TiH[kt], bbh+2*nt);
                    mma16816(aW[nt], TiL[kt], bbh+2*nt);
                    mma16816(aW[nt], TiH[kt], bbl+2*nt);
                }
            }
            #pragma unroll
            for (int nt = 0; nt < 2; ++nt)
                #pragma unroll
                for (int r = 0; r < 4; ++r) {
                    const int i = i0 + (r>>1)*8;
                    const int d = n0 + nt*8 + qp + (r&1);
                    U[cb8 + i*256 + d] = aU[nt][r];
                    __nv_bfloat16 hh, ll;
                    split1(aW[nt][r], hh, ll);
                    WH[cb8 + i*256 + d] = hh;
                    WL[cb8 + i*256 + d] = ll;
                }
        }
    }
}

// ---------------- tensor-core delta scan ----------------
#define STGSZ  72704
#define OFF_KT 145408
#define OFF_UB 210944
#define SC_SMEM 227840

__global__ void __launch_bounds__(128) scan_mma(
    const __nv_bfloat16* __restrict__ QHp, const __nv_bfloat16* __restrict__ QLp,
    const __nv_bfloat16* __restrict__ WHp, const __nv_bfloat16* __restrict__ WLp,
    const __nv_bfloat16* __restrict__ KHp, const __nv_bfloat16* __restrict__ KLp,
    const __nv_bfloat16* __restrict__ AHp, const __nv_bfloat16* __restrict__ ALp,
    const float* __restrict__ Ug, float* __restrict__ Out)
{
    extern __shared__ char smraw[];
    const unsigned smb = (unsigned)__cvta_generic_to_shared(smraw);
    float* ub = (float*)(smraw + OFF_UB);
    const int tid = threadIdx.x, warp = tid>>5, lane = tid&31;
    const int bh = blockIdx.x>>4, cb = blockIdx.x&15;
    const int b = bh>>2, h = bh&3;
    const int g = lane>>2, qp = (lane&3)*2;
    const int brow16 = ((lane>>4)&1)*8 + (lane&7);
    const int bcol8 = ((lane>>3)&1)*8;

    float P[8][4];
    #pragma unroll
    for (int i=0;i<8;++i)
        #pragma unroll
        for (int r=0;r<4;++r) P[i][r]=0.f;

    auto issue = [&](int ci, int stg){
        const size_t b8 = (size_t)(bh*NCc + ci)*8192;
        const size_t b1 = (size_t)(bh*NCc + ci)*1024;
        const unsigned sb = smb + stg*STGSZ;
        const __nv_bfloat16* srcs[4] = {QHp+b8, QLp+b8, WHp+b8, WLp+b8};
        #pragma unroll
        for (int pl = 0; pl < 4; ++pl){
            const unsigned dsb = sb + pl*16384;
            for (int e = tid; e < 1024; e += 128){
                int row = e>>5, c = e&31;
                cpa16(dsb + row*512 + ((c^(row&7))<<4), srcs[pl] + row*256 + c*8);
            }
        }
        const unsigned kb2 = smb + OFF_KT + stg*32768;
        for (int e = tid; e < 1024; e += 128){
            int row = e>>2, c = e&3;
            cpa16(kb2 + row*64 + c*16, KHp + b8 + row*32 + c*8);
            cpa16(kb2 + 16384 + row*64 + c*16, KLp + b8 + row*32 + c*8);
        }
        {
            int row = tid>>2, c = tid&3;
            cpa16(sb + 65536 + row*80 + c*16, AHp + b1 + row*32 + c*8);
            cpa16(sb + 68096 + row*80 + c*16, ALp + b1 + row*32 + c*8);
            cpa16(sb + 70656 + row*64 + c*16, Ug + b8 + (size_t)row*256 + cb*16 + c*4);
        }
    };

    issue(0, 0); CP_COMMIT();

    for (int ci = 0; ci < NCc; ++ci) {
        const int stg = ci & 1;
        const unsigned sb = smb + stg*STGSZ;
        const unsigned kb = smb + OFF_KT + stg*32768;
        CP_WAIT0();
        __syncthreads();

        float accW[4][4], accQ[4][4];
        #pragma unroll
        for (int i=0;i<4;++i)
            #pragma unroll
            for (int r=0;r<4;++r){ accW[i][r]=0.f; accQ[i][r]=0.f; }
        #pragma unroll
        for (int kt = 0; kt < 4; ++kt) {
            unsigned Ah[4], Al[4];
            const float* p0 = P[2*kt]; const float* p1 = P[2*kt+1];
            Ah[0]=pack2(p0[0],p0[1]); Ah[1]=pack2(p0[2],p0[3]);
            Ah[2]=pack2(p1[0],p1[1]); Ah[3]=pack2(p1[2],p1[3]);
            Al[0]=pack2(res1(p0[0]),res1(p0[1])); Al[1]=pack2(res1(p0[2]),res1(p0[3]));
            Al[2]=pack2(res1(p1[0]),res1(p1[1])); Al[3]=pack2(res1(p1[2]),res1(p1[3]));
            const int dcol = warp*64 + kt*16 + bcol8;
            unsigned bwh[4][2], bwl[4][2], bqh[4][2], bql[4][2];
            #pragma unroll
            for (int ng = 0; ng < 2; ++ng) {
                const int row = ng*16 + brow16;
                const unsigned off = row*512 + ((((unsigned)(dcol>>3))^(row&7))<<4);
                unsigned r4[4];
                ldsm4(r4, sb + 32768 + off);
                bwh[2*ng][0]=r4[0]; bwh[2*ng][1]=r4[1]; bwh[2*ng+1][0]=r4[2]; bwh[2*ng+1][1]=r4[3];
                ldsm4(r4, sb + 49152 + off);
                bwl[2*ng][0]=r4[0]; bwl[2*ng][1]=r4[1]; bwl[2*ng+1][0]=r4[2]; bwl[2*ng+1][1]=r4[3];
                ldsm4(r4, sb + off);
                bqh[2*ng][0]=r4[0]; bqh[2*ng][1]=r4[1]; bqh[2*ng+1][0]=r4[2]; bqh[2*ng+1][1]=r4[3];
                ldsm4(r4, sb + 16384 + off);
                bql[2*ng][0]=r4[0]; bql[2*ng][1]=r4[1]; bql[2*ng+1][0]=r4[2]; bql[2*ng+1][1]=r4[3];
            }
            #pragma unroll
            for (int nt = 0; nt < 4; ++nt) {
                mma16816(accW[nt], Ah, bwh[nt]);
                mma16816(accW[nt], Al, bwh[nt]);
                mma16816(accW[nt], Ah, bwl[nt]);
                mma16816(accQ[nt], Ah, bqh[nt]);
                mma16816(accQ[nt], Al, bqh[nt]);
                mma16816(accQ[nt], Ah, bql[nt]);
            }
        }
        #pragma unroll
        for (int nt = 0; nt < 4; ++nt)
            #pragma unroll
            for (int r = 0; r < 4; ++r) {
                int c = g + ((r>>1)<<3), t = nt*8 + qp + (r&1);
                ub[(c*4+warp)*66 + t] = accW[nt][r];
                ub[(c*4+warp)*66 + 32 + t] = accQ[nt][r];
            }
        if (ci + 1 < NCc) { issue(ci+1, stg^1); CP_COMMIT(); }
        __syncthreads();

        const float* su = (const float*)(smraw + stg*STGSZ + 70656);
        unsigned UH[2][4], UL[2][4];
        #pragma unroll
        for (int kt = 0; kt < 2; ++kt) {
            float v[8];
            #pragma unroll
            for (int p = 0; p < 8; ++p) {
                const int c = g + (((p>>1)&1)<<3);
                const int t = kt*16 + qp + (p&1) + ((p>>2)<<3);
                const int bi = (c*4)*66 + t;
                v[p] = su[t*16 + c] + ub[bi] + ub[bi+66] + ub[bi+132] + ub[bi+198];
            }
            UH[kt][0]=pack2(v[0],v[1]); UH[kt][1]=pack2(v[2],v[3]);
            UH[kt][2]=pack2(v[4],v[5]); UH[kt][3]=pack2(v[6],v[7]);
            UL[kt][0]=pack2(res1(v[0]),res1(v[1])); UL[kt][1]=pack2(res1(v[2]),res1(v[3]));
            UL[kt][2]=pack2(res1(v[4]),res1(v[5])); UL[kt][3]=pack2(res1(v[6]),res1(v[7]));
        }
        float oc[4];
        const int i0 = warp*8 + qp;
        #pragma unroll
        for (int r = 0; r < 4; ++r) {
            const int c = g + ((r>>1)<<3);
            const int bi = (c*4)*66 + 32 + i0 + (r&1);
            oc[r] = -(ub[bi] + ub[bi+66] + ub[bi+132] + ub[bi+198]);
        }

        #pragma unroll
        for (int kt = 0; kt < 2; ++kt) {
            unsigned bh2[2], bl2[2];
            const unsigned aoff = (warp*8 + (lane&7))*80 + (kt*16 + bcol8)*2;
            ldsm2(bh2, sb + 65536 + aoff);
            ldsm2(bl2, sb + 68096 + aoff);
            mma16816(oc, UH[kt], bh2);
            mma16816(oc, UL[kt], bh2);
            mma16816(oc, UH[kt], bl2);
        }
        {
            const size_t base = ((size_t)(b*Ll + ci*CSs + i0))*HD + h*256 + cb*16;
            Out[base + g]          = oc[0];
            Out[base + HD + g]     = oc[1];
            Out[base + g + 8]      = oc[2];
            Out[base + HD + g + 8] = oc[3];
        }

        #pragma unroll
        for (int kt = 0; kt < 2; ++kt) {
            #pragma unroll
            for (int np = 0; np < 4; ++np) {
                unsigned bh4[4], bl4[4];
                const unsigned off = (warp*64 + np*16 + brow16)*64 + (kt*16 + bcol8)*2;
                ldsm4(bh4, kb + off);
                ldsm4(bl4, kb + 16384 + off);
                mma16816(P[2*np],   UH[kt], bh4);
                mma16816(P[2*np],   UL[kt], bh4);
                mma16816(P[2*np],   UH[kt], bl4);
                mma16816(P[2*np+1], UH[kt], bh4+2);
                mma16816(P[2*np+1], UL[kt], bh4+2);
                mma16816(P[2*np+1], UH[kt], bl4+2);
            }
        }
    }
}

// ---------------- FIR short/long + gate_in (writes bf16 hi/lo gin directly) ----------
__global__ void fir_gatein_kernel(const unsigned* __restrict__ hsHu, const unsigned* __restrict__ hsLu,
                                  const float* __restrict__ V,
                                  const float* __restrict__ ws, const float* __restrict__ wl,
                                  const float* __restrict__ Dl,
                                  float* __restrict__ Sout, float* __restrict__ Lout,
                                  __nv_bfloat16* __restrict__ GinH, __nv_bfloat16* __restrict__ GinL)
{
    const int blk = blockIdx.x;
    const int b = blk / (Ll/8);
    const int l0 = (blk % (Ll/8)) * 8;
    const int tid = threadIdx.x;
    float smean[8], lmean[8], dmean[8];
    #pragma unroll
    for (int r = 0; r < 8; ++r) { smean[r]=0.f; lmean[r]=0.f; dmean[r]=0.f; }
    for (int j = 0; j < 4; ++j) {
        const int ch = tid + 256*j;
        float win[38];
        #pragma unroll
        for (int t = 0; t < 38; ++t) {
            const int l = l0 - 30 + t;
            win[t] = (l >= 0) ? V[((size_t)(b*Ll + l))*HD + ch] : 0.f;
        }
        float wlr[31];
        #pragma unroll
        for (int t = 0; t < 31; ++t) wlr[t] = wl[ch*31 + t];
        const float w0 = ws[ch*3+0], w1 = ws[ch*3+1], w2 = ws[ch*3+2];
        #pragma unroll
        for (int r = 0; r < 8; ++r) {
            float yl = 0.f;
            #pragma unroll
            for (int t = 0; t < 31; ++t) yl += win[r+t]*wlr[t];
            const float ysv = win[r+28]*w0 + win[r+29]*w1 + win[r+30]*w2;
            const size_t row = (size_t)(b*Ll + l0 + r);
            Sout[row*HD + ch] = ysv;
            Lout[row*HD + ch] = yl;
            smean[r] += ysv; lmean[r] += yl;
            dmean[r] += Dl[row*HD + ch];
        }
    }
    for (int r = 0; r < 8; ++r) {
        const size_t row = (size_t)(b*Ll + l0 + r);
        __nv_bfloat16* gH = GinH + row*GIN;
        __nv_bfloat16* gL = GinL + row*GIN;
        // copy hs planes (1024 bf16 = 512 uints, 256 threads x 2)
        #pragma unroll
        for (int j = 0; j < 2; ++j) {
            const int e = tid + 256*j;
            ((unsigned*)gH)[e] = hsHu[row*512 + e];
            ((unsigned*)gL)[e] = hsLu[row*512 + e];
        }
        __nv_bfloat16 hh, ll;
        split1(smean[r]*0.25f, hh, ll);
        gH[1024 + tid] = hh; gL[1024 + tid] = ll;
        split1(lmean[r]*0.25f, hh, ll);
        gH[1280 + tid] = hh; gL[1280 + tid] = ll;
        split1(dmean[r]*0.25f, hh, ll);
        gH[1536 + tid] = hh; gL[1536 + tid] = ll;
    }
}

// ---------------- gate head 2 ----------------
__global__ void gate2_wgt(const float* __restrict__ GH2, const float* __restrict__ W2,
                          const float* __restrict__ b2, const float* __restrict__ ltemp,
                          float* __restrict__ Wgt)
{
    const int row = blockIdx.x;
    const int warp = threadIdx.x >> 5, lane = threadIdx.x & 31;
    __shared__ float lg[4];
    const float* x = GH2 + (size_t)row*GHID;
    const float* w = W2 + warp*GHID;
    float s = 0.f;
    for (int i = lane; i < GHID; i += 32) s += x[i]*w[i];
    #pragma unroll
    for (int o = 16; o; o >>= 1) s += __shfl_xor_sync(0xffffffff, s, o);
    if (lane == 0) lg[warp] = s + b2[warp];
    __syncthreads();
    if (threadIdx.x == 0) {
        const float t = log1pf(expf(ltemp[0])) + 1e-4f;
        float m = fmaxf(fmaxf(lg[0], lg[1]), fmaxf(lg[2], lg[3]));
        float e[4]; float se = 0.f;
        #pragma unroll
        for (int j = 0; j < 4; ++j) { e[j] = expf((lg[j]-m)/t); se += e[j]; }
        #pragma unroll
        for (int j = 0; j < 4; ++j) e[j] /= se;
        const float fl = 0.05f * e[3];
        e[0] = fmaxf(e[0], fl);
        e[1] = fmaxf(e[1], fl);
        const float s2 = e[0]+e[1]+e[2]+e[3];
        #pragma unroll
        for (int j = 0; j < 4; ++j) Wgt[row*4+j] = e[j]/s2;
    }
}

// ---------------- combine + RMSNorm (writes bf16 hi/lo directly) ----------------
__global__ void combine_kernel(const float* __restrict__ Sh, const float* __restrict__ Lg,
                               const float* __restrict__ Dl, const float* __restrict__ V,
                               const float* __restrict__ Wgt, const float* __restrict__ onw,
                               __nv_bfloat16* __restrict__ OH, __nv_bfloat16* __restrict__ OL)
{
    const int row = blockIdx.x;
    const int tid = threadIdx.x, lane = tid & 31;
    __shared__ float red[4];
    if (tid < 4) red[tid] = 0.f;
    __syncthreads();
    const float w0 = Wgt[row*4+0], w1 = Wgt[row*4+1], w2 = Wgt[row*4+2], w3 = Wgt[row*4+3];
    float ov[4];
    #pragma unroll
    for (int j = 0; j < 4; ++j) {
        const size_t g = (size_t)row*HD + tid + 256*j;
        ov[j] = w0*Sh[g] + w1*Lg[g] + w2*Dl[g] + w3*V[g];
        float v = ov[j]*ov[j];
        #pragma unroll
        for (int o = 16; o; o >>= 1) v += __shfl_xor_sync(0xffffffff, v, o);
        if (lane == 0) atomicAdd(&red[j], v);
    }
    __syncthreads();
    #pragma unroll
    for (int j = 0; j < 4; ++j) {
        const float sc = rsqrtf(red[j]*(1.f/256.f) + 1e-5f) * onw[tid];
        __nv_bfloat16 hh, ll;
        split1(ov[j]*sc, hh, ll);
        OH[(size_t)row*HD + tid + 256*j] = hh;
        OL[(size_t)row*HD + tid + 256*j] = ll;
    }
}

// ---------------- launch ----------------
static inline void split_launch(const float* x, __nv_bfloat16* hi, __nv_bfloat16* lo, size_t n)
{
    int n4 = (int)(n >> 2);
    split_kernel<<<(n4 + 255)/256, 256>>>((const float4*)x, (uint2*)hi, (uint2*)lo, n4);
}

extern "C" void kernel_launch(void* const* d_in, const int* in_sizes, int n_in,
                              void* d_out, int out_size)
{
    const float* hs  = (const float*)d_in[0];
    const float* qw  = (const float*)d_in[1];
    const float* kw  = (const float*)d_in[2];
    const float* vw  = (const float*)d_in[3];
    const float* bw  = (const float*)d_in[4];
    const float* qcw = (const float*)d_in[5];
    const float* kcw = (const float*)d_in[6];
    const float* vcw = (const float*)d_in[7];
    const float* fsw = (const float*)d_in[8];
    const float* flw = (const float*)d_in[9];
    const float* w1  = (const float*)d_in[10];
    const float* b1  = (const float*)d_in[11];
    const float* w2  = (const float*)d_in[12];
    const float* b2  = (const float*)d_in[13];
    const float* lt  = (const float*)d_in[14];
    const float* onw = (const float*)d_in[15];
    const float* ow  = (const float*)d_in[16];
    float* out = (float*)d_out;

    float *xqkv,*q,*k,*v,*u,*delta,*shrt,*lng,*gh,*beta,*wgt;
    __nv_bfloat16 *hsH,*hsL,*ginH,*ginL,*ocH,*ocL,*wtH,*wtL;
    __nv_bfloat16 *qh,*ql,*wh,*wlp,*kh,*kl,*ah,*al;
    cudaGetSymbolAddress((void**)&xqkv, g_xqkv);
    cudaGetSymbolAddress((void**)&q,    g_q);
    cudaGetSymbolAddress((void**)&k,    g_k);
    cudaGetSymbolAddress((void**)&v,    g_v);
    cudaGetSymbolAddress((void**)&u,    g_u);
    cudaGetSymbolAddress((void**)&delta,g_delta);
    cudaGetSymbolAddress((void**)&shrt, g_short);
    cudaGetSymbolAddress((void**)&lng,  g_long);
    cudaGetSymbolAddress((void**)&gh,   g_gh);
    cudaGetSymbolAddress((void**)&beta, g_beta);
    cudaGetSymbolAddress((void**)&wgt,  g_wgt);
    cudaGetSymbolAddress((void**)&hsH,  g_hsH);
    cudaGetSymbolAddress((void**)&hsL,  g_hsL);
    cudaGetSymbolAddress((void**)&ginH, g_ginH);
    cudaGetSymbolAddress((void**)&ginL, g_ginL);
    cudaGetSymbolAddress((void**)&ocH,  g_ocH);
    cudaGetSymbolAddress((void**)&ocL,  g_ocL);
    cudaGetSymbolAddress((void**)&wtH,  g_wtH);
    cudaGetSymbolAddress((void**)&wtL,  g_wtL);
    cudaGetSymbolAddress((void**)&qh,   g_qh);
    cudaGetSymbolAddress((void**)&ql,   g_ql);
    cudaGetSymbolAddress((void**)&wh,   g_wh);
    cudaGetSymbolAddress((void**)&wlp,  g_wl);
    cudaGetSymbolAddress((void**)&kh,   g_kh);
    cudaGetSymbolAddress((void**)&kl,   g_kl);
    cudaGetSymbolAddress((void**)&ah,   g_ah);
    cudaGetSymbolAddress((void**)&al,   g_al);

    cudaFuncSetAttribute(precompute_kernel, cudaFuncAttributeMaxDynamicSharedMemorySize, PRE_SMEM);
    cudaFuncSetAttribute(scan_mma, cudaFuncAttributeMaxDynamicSharedMemorySize, SC_SMEM);

    split_launch(hs, hsH, hsL, (size_t)BL*Dd);
    split_launch(qw, wtH + WOFF_Q,  wtL + WOFF_Q,  (size_t)1024*1024);
    split_launch(kw, wtH + WOFF_K,  wtL + WOFF_K,  (size_t)1024*1024);
    split_launch(vw, wtH + WOFF_V,  wtL + WOFF_V,  (size_t)1024*1024);
    split_launch(w1, wtH + WOFF_W1, wtL + WOFF_W1, (size_t)GHID*GIN);
    split_launch(ow, wtH + WOFF_O,  wtL + WOFF_O,  (size_t)Dd*HD);

    // fused q/k/v projection: C[8192,3072]
    hgemm_nt<false><<<dim3(3072/128, BL/128), 256>>>(hsH, hsL, wtH+WOFF_Q, wtL+WOFF_Q,
                                                     xqkv, BL, 3072, Dd, nullptr);
    beta_kernel<<<BL, 128>>>(hs, bw, beta);
    conv_silu_norm<<<BL, 256>>>(xqkv, qcw, kcw, vcw, q, k, v);
    precompute_kernel<<<8*NCc, 256, PRE_SMEM>>>(q, k, v, beta, u,
                                                qh, ql, wh, wlp, kh, kl, ah, al);
    scan_mma<<<128, 128, SC_SMEM>>>(qh, ql, wh, wlp, kh, kl, ah, al, u, delta);
    fir_gatein_kernel<<<Bb*(Ll/8), 256>>>((const unsigned*)hsH, (const unsigned*)hsL,
                                          v, fsw, flw, delta, shrt, lng, ginH, ginL);
    hgemm_nt<true><<<dim3(GHID/128, BL/128), 256>>>(ginH, ginL, wtH+WOFF_W1, wtL+WOFF_W1,
                                                    gh, BL, GHID, GIN, b1);
    gate2_wgt<<<BL, 128>>>(gh, w2, b2, lt, wgt);
    combine_kernel<<<BL, 256>>>(shrt, lng, delta, v, wgt, onw, ocH, ocL);
    hgemm_nt<false><<<dim3(Dd/128, BL/128), 256>>>(ocH, ocL, wtH+WOFF_O, wtL+WOFF_O,
                                                   out, BL, Dd, HD, nullptr);
}

// round 8
// speedup vs baseline: 3.0656x; 1.0362x over previous
#include <cuda_runtime.h>
#include <cuda_bf16.h>
#include <math.h>

#define Bb   2
#define Ll   4096
#define Dd   1024
#define Hh   4
#define CSs  32
#define NCc  128
#define BL   (Bb*Ll)
#define HD   1024
#define GIN  1792
#define GHID 1024
#define CH8  (8*NCc*8192)

// ---------------- scratch ----------------
__device__ float g_xqkv[BL*3072];
__device__ float g_q [BL*HD];
__device__ float g_k [BL*HD];
__device__ float g_v [BL*HD];
__device__ float g_u [CH8];
__device__ float g_delta[BL*HD];
__device__ float g_short[BL*HD];
__device__ float g_long [BL*HD];
__device__ float g_gh [BL*GHID];
__device__ float g_beta[BL*Hh];
__device__ float g_wgt [BL*4];

__device__ __align__(16) __nv_bfloat16 g_hsH[BL*Dd];
__device__ __align__(16) __nv_bfloat16 g_hsL[BL*Dd];
__device__ __align__(16) __nv_bfloat16 g_ginH[BL*GIN];
__device__ __align__(16) __nv_bfloat16 g_ginL[BL*GIN];
__device__ __align__(16) __nv_bfloat16 g_ocH[BL*HD];
__device__ __align__(16) __nv_bfloat16 g_ocL[BL*HD];
#define WOFF_Q  0
#define WOFF_K  (1024*1024)
#define WOFF_V  (2*1024*1024)
#define WOFF_W1 (3*1024*1024)
#define WOFF_O  (3*1024*1024 + 1792*1024)
#define WTOT    (WOFF_O + 1024*1024)
__device__ __align__(16) __nv_bfloat16 g_wtH[WTOT];
__device__ __align__(16) __nv_bfloat16 g_wtL[WTOT];

// scan operand planes
__device__ __align__(16) __nv_bfloat16 g_qh[CH8], g_ql[CH8], g_wh[CH8], g_wl[CH8], g_kh[CH8], g_kl[CH8];
__device__ __align__(16) __nv_bfloat16 g_ah[8*NCc*1024], g_al[8*NCc*1024];

// ---------------- helpers ----------------
__device__ __forceinline__ float siluf(float x){ return x / (1.f + expf(-x)); }
__device__ __forceinline__ float geluf(float x){ return 0.5f * x * (1.f + erff(x * 0.70710678118654752f)); }
__device__ __forceinline__ void ldsm4(unsigned* r, unsigned addr){
    asm volatile("ldmatrix.sync.aligned.m8n8.x4.shared.b16 {%0,%1,%2,%3}, [%4];"
        : "=r"(r[0]),"=r"(r[1]),"=r"(r[2]),"=r"(r[3]) : "r"(addr));
}
__device__ __forceinline__ void ldsm4t(unsigned* r, unsigned addr){
    asm volatile("ldmatrix.sync.aligned.m8n8.x4.trans.shared.b16 {%0,%1,%2,%3}, [%4];"
        : "=r"(r[0]),"=r"(r[1]),"=r"(r[2]),"=r"(r[3]) : "r"(addr));
}
__device__ __forceinline__ void ldsm2(unsigned* r, unsigned addr){
    asm volatile("ldmatrix.sync.aligned.m8n8.x2.shared.b16 {%0,%1}, [%2];"
        : "=r"(r[0]),"=r"(r[1]) : "r"(addr));
}
__device__ __forceinline__ void mma16816(float* c, const unsigned* a, const unsigned* b){
    asm volatile("mma.sync.aligned.m16n8k16.row.col.f32.bf16.bf16.f32 "
        "{%0,%1,%2,%3}, {%4,%5,%6,%7}, {%8,%9}, {%0,%1,%2,%3};"
        : "+f"(c[0]),"+f"(c[1]),"+f"(c[2]),"+f"(c[3])
        : "r"(a[0]),"r"(a[1]),"r"(a[2]),"r"(a[3]), "r"(b[0]),"r"(b[1]));
}
__device__ __forceinline__ void cpa16(unsigned d, const void* s){
    asm volatile("cp.async.cg.shared.global [%0],[%1],16;\n" :: "r"(d), "l"(s));
}
#define CP_COMMIT() asm volatile("cp.async.commit_group;\n")
#define CP_WAIT0()  asm volatile("cp.async.wait_group 0;\n")
__device__ __forceinline__ unsigned pack2(float a, float b){
    __nv_bfloat162 t; t.x=__float2bfloat16(a); t.y=__float2bfloat16(b);
    return *(unsigned*)&t;
}
__device__ __forceinline__ float res1(float v){ return v - __bfloat162float(__float2bfloat16(v)); }
__device__ __forceinline__ void split1(float v, __nv_bfloat16& h, __nv_bfloat16& l){
    h = __float2bfloat16(v); l = __float2bfloat16(v - __bfloat162float(h));
}

// ---------------- fp32 -> (hi,lo) bf16 split ----------------
__global__ void split_kernel(const float4* __restrict__ x, uint2* __restrict__ hi,
                             uint2* __restrict__ lo, int n4)
{
    int i = blockIdx.x*blockDim.x + threadIdx.x;
    if (i >= n4) return;
    float4 v = x[i];
    uint2 ho, loo;
    ho.x = pack2(v.x, v.y);  ho.y = pack2(v.z, v.w);
    loo.x = pack2(res1(v.x), res1(v.y)); loo.y = pack2(res1(v.z), res1(v.w));
    hi[i] = ho; lo[i] = loo;
}

// ---------------- merged weight split (qw,kw,vw,w1,ow -> g_wtH/g_wtL) ----------------
#define W4_Q  262144
#define W4_K  524288
#define W4_V  786432
#define W4_W1 1245184
#define W4_O  1507328
__global__ void wsplit_kernel(const float4* __restrict__ qw, const float4* __restrict__ kw,
                              const float4* __restrict__ vw, const float4* __restrict__ w1,
                              const float4* __restrict__ ow,
                              uint2* __restrict__ hi, uint2* __restrict__ lo)
{
    int i = blockIdx.x*blockDim.x + threadIdx.x;
    if (i >= W4_O) return;
    const float4* src; int local;
    if      (i < W4_Q)  { src = qw; local = i; }
    else if (i < W4_K)  { src = kw; local = i - W4_Q; }
    else if (i < W4_V)  { src = vw; local = i - W4_K; }
    else if (i < W4_W1) { src = w1; local = i - W4_V; }
    else                { src = ow; local = i - W4_W1; }
    float4 v = src[local];
    uint2 ho, loo;
    ho.x = pack2(v.x, v.y);  ho.y = pack2(v.z, v.w);
    loo.x = pack2(res1(v.x), res1(v.y)); loo.y = pack2(res1(v.z), res1(v.w));
    hi[i] = ho; lo[i] = loo;
}

// ---------------- bf16x3 split GEMM, 128x256 tile, 512 threads, double-buffered ----------
// planes per stage (bf16 units): Ah 0, Al 3072, Bh 6144, Bl 12288; stage = 18432
#define G2_STG   18432
#define G2_SMEM  (2*G2_STG*2)   // bytes = 73728
template<bool EPI>
__global__ void __launch_bounds__(512) hgemm_nt(const __nv_bfloat16* __restrict__ Ah,
                                                const __nv_bfloat16* __restrict__ Al,
                                                const __nv_bfloat16* __restrict__ Bh,
                                                const __nv_bfloat16* __restrict__ Bl,
                                                float* __restrict__ C,
                                                int M, int N, int K,
                                                const float* __restrict__ bias)
{
    extern __shared__ __align__(16) __nv_bfloat16 sm[];
    const int tid = threadIdx.x;
    const int bm = blockIdx.y*128, bn = blockIdx.x*256;
    const int warp = tid>>5, lane = tid&31;
    const int wm = warp>>3, wn = warp&7;
    float acc[4][4][4];
    #pragma unroll
    for (int i=0;i<4;i++) for(int j=0;j<4;j++) for(int r=0;r<4;r++) acc[i][j][r]=0.f;

    const bool doA = tid < 256;
    const size_t aoff = (size_t)(bm + ((tid & 255)>>1))*K + (tid&1)*8;
    const size_t boff = (size_t)(bn + (tid>>1))*K + (tid&1)*8;
    const int stoA = ((tid & 255)>>1)*24 + (tid&1)*8;
    const int stoB = 6144 + (tid>>1)*24 + (tid&1)*8;

    unsigned base = (unsigned)__cvta_generic_to_shared(sm);
    const int arow = wm*64 + (lane&15);
    const int acol = (lane>>4)*8;
    const int brow = wn*32 + ((lane>>4)&1)*8 + (lane&7);
    const int bcol = ((lane>>3)&1)*8;
    const int nk = K >> 4;

    {
        uint4 rAh, rAl;
        if (doA) { rAh = *(const uint4*)(Ah + aoff); rAl = *(const uint4*)(Al + aoff); }
        uint4 rBh = *(const uint4*)(Bh + boff);
        uint4 rBl = *(const uint4*)(Bl + boff);
        if (doA) {
            *(uint4*)(sm + stoA) = rAh;
            *(uint4*)(sm + 3072 + stoA) = rAl;
        }
        *(uint4*)(sm + stoB) = rBh;
        *(uint4*)(sm + 6144 + stoB) = rBl;
    }
    __syncthreads();

    for (int kt = 0; kt < nk; ++kt) {
        const int cur = kt & 1;
        const unsigned sb = base + (unsigned)cur*(G2_STG*2);
        uint4 nAh, nAl, nBh, nBl;
        const bool more = (kt + 1 < nk);
        if (more) {
            const size_t kb = boff + (size_t)(kt+1)*16;
            nBh = *(const uint4*)(Bh + kb);
            nBl = *(const uint4*)(Bl + kb);
            if (doA) {
                const size_t ka = aoff + (size_t)(kt+1)*16;
                nAh = *(const uint4*)(Ah + ka);
                nAl = *(const uint4*)(Al + ka);
            }
        }
        unsigned bh[4][2], bl[4][2];
        #pragma unroll
        for (int ng = 0; ng < 2; ++ng) {
            unsigned r4[4];
            ldsm4(r4, sb + 2u*(6144 + (brow + ng*16)*24 + bcol));
            bh[2*ng][0]=r4[0]; bh[2*ng][1]=r4[1]; bh[2*ng+1][0]=r4[2]; bh[2*ng+1][1]=r4[3];
            ldsm4(r4, sb + 2u*(12288 + (brow + ng*16)*24 + bcol));
            bl[2*ng][0]=r4[0]; bl[2*ng][1]=r4[1]; bl[2*ng+1][0]=r4[2]; bl[2*ng+1][1]=r4[3];
        }
        #pragma unroll
        for (int mt = 0; mt < 4; ++mt) {
            unsigned ah[4], al[4];
            ldsm4(ah, sb + 2u*((arow + mt*16)*24 + acol));
            ldsm4(al, sb + 2u*(3072 + (arow + mt*16)*24 + acol));
            #pragma unroll
            for (int nt = 0; nt < 4; ++nt) {
                mma16816(acc[mt][nt], ah, bh[nt]);
                mma16816(acc[mt][nt], ah, bl[nt]);
                mma16816(acc[mt][nt], al, bh[nt]);
            }
        }
        if (more) {
            __nv_bfloat16* d = sm + (cur^1)*G2_STG;
            if (doA) {
                *(uint4*)(d + stoA) = nAh;
                *(uint4*)(d + 3072 + stoA) = nAl;
            }
            *(uint4*)(d + stoB) = nBh;
            *(uint4*)(d + 6144 + stoB) = nBl;
            __syncthreads();
        }
    }
    const int g = lane>>2, tig = lane&3;
    #pragma unroll
    for (int mt = 0; mt < 4; ++mt) {
        const int row0 = bm + wm*64 + mt*16 + g;
        #pragma unroll
        for (int nt = 0; nt < 4; ++nt) {
            const int col = bn + wn*32 + nt*8 + tig*2;
            float v0 = acc[mt][nt][0], v1 = acc[mt][nt][1];
            float v2 = acc[mt][nt][2], v3 = acc[mt][nt][3];
            if (EPI) {
                const float bz0 = bias[col], bz1 = bias[col+1];
                v0 = geluf(v0+bz0); v1 = geluf(v1+bz1);
                v2 = geluf(v2+bz0); v3 = geluf(v3+bz1);
            }
            *(float2*)(C + (size_t)row0*N + col)     = make_float2(v0, v1);
            *(float2*)(C + (size_t)(row0+8)*N + col) = make_float2(v2, v3);
        }
    }
}

// ---------------- beta ----------------
__global__ void beta_kernel(const float* __restrict__ hs, const float* __restrict__ bw,
                            float* __restrict__ beta)
{
    const int row = blockIdx.x;
    const int warp = threadIdx.x >> 5, lane = threadIdx.x & 31;
    const float* x = hs + (size_t)row * Dd;
    const float* w = bw + warp * Dd;
    float s = 0.f;
    for (int i = lane; i < Dd; i += 32) s += x[i] * w[i];
    #pragma unroll
    for (int o = 16; o; o >>= 1) s += __shfl_xor_sync(0xffffffff, s, o);
    if (lane == 0) beta[row*4 + warp] = 1.f / (1.f + expf(-s));
}

// ---------------- conv + silu + l2norm (reads fused xqkv) ----------------
__global__ void conv_silu_norm(const float* __restrict__ XQKV,
                               const float* __restrict__ WQ, const float* __restrict__ WK,
                               const float* __restrict__ WV,
                               float* __restrict__ Qo, float* __restrict__ Ko,
                               float* __restrict__ Vo)
{
    const int row = blockIdx.x;
    const int b = row >> 12, l = row & (Ll-1);
    const int tid = threadIdx.x;
    const int lane = tid & 31;
    __shared__ float redq[4], redk[4];
    if (tid < 4) { redq[tid] = 0.f; redk[tid] = 0.f; }
    __syncthreads();
    float yq[4], yk[4];
    #pragma unroll
    for (int j = 0; j < 4; ++j) {
        const int c = tid + 256*j;
        float aq=0.f, ak=0.f, av=0.f;
        #pragma unroll
        for (int t = 0; t < 4; ++t) {
            const int ll = l - 3 + t;
            if (ll >= 0) {
                const size_t g3 = ((size_t)(b*Ll + ll))*3072;
                aq += XQKV[g3 + c]*WQ[c*4+t];
                ak += XQKV[g3 + 1024 + c]*WK[c*4+t];
                av += XQKV[g3 + 2048 + c]*WV[c*4+t];
            }
        }
        aq = siluf(aq); ak = siluf(ak); av = siluf(av);
        Vo[(size_t)row*HD + c] = av;
        yq[j] = aq; yk[j] = ak;
        float vq = aq*aq, vk = ak*ak;
        #pragma unroll
        for (int o = 16; o; o >>= 1) {
            vq += __shfl_xor_sync(0xffffffff, vq, o);
            vk += __shfl_xor_sync(0xffffffff, vk, o);
        }
        if (lane == 0) { atomicAdd(&redq[j], vq); atomicAdd(&redk[j], vk); }
    }
    __syncthreads();
    #pragma unroll
    for (int j = 0; j < 4; ++j) {
        const int c = tid + 256*j;
        Qo[(size_t)row*HD + c] = yq[j]*rsqrtf(redq[j] + 1e-12f);
        Ko[(size_t)row*HD + c] = yk[j]*rsqrtf(redk[j] + 1e-12f);
    }
}

// ---------------- precompute (tensor-core) ----------------
#define PPLN 16896
#define OQH 0
#define OQL 16896
#define OKH 33792
#define OKL 50688
#define OVH 67584
#define OVL 84480
#define OBH 101376
#define OBL 118272
#define OTH 135168
#define OTL 137728
#define OAM 140288
#define OTI 144512
#define OSB 148736
#define PRE_SMEM 148992

__global__ void __launch_bounds__(256) precompute_kernel(
    const float* __restrict__ Qn, const float* __restrict__ Kn,
    const float* __restrict__ V,  const float* __restrict__ beta,
    float* __restrict__ U,
    __nv_bfloat16* __restrict__ QH, __nv_bfloat16* __restrict__ QL,
    __nv_bfloat16* __restrict__ WH, __nv_bfloat16* __restrict__ WL,
    __nv_bfloat16* __restrict__ KH, __nv_bfloat16* __restrict__ KL,
    __nv_bfloat16* __restrict__ AH, __nv_bfloat16* __restrict__ AL)
{
    extern __shared__ char smraw[];
    const unsigned smb = (unsigned)__cvta_generic_to_shared(smraw);
    float* Amp = (float*)(smraw + OAM);
    float* Tip = (float*)(smraw + OTI);
    float* sbp = (float*)(smraw + OSB);
    const int idx = blockIdx.x;
    const int bh = idx >> 7, ci = idx & 127;
    const int b = bh >> 2, h = bh & 3;
    const int tid = threadIdx.x, warp = tid>>5, lane = tid&31;
    const int g = lane>>2, qp = (lane&3)*2;
    const size_t cb8 = (size_t)idx*8192;
    const size_t cb1 = (size_t)idx*1024;

    if (tid < 32) sbp[tid] = beta[(size_t)(b*Ll + ci*CSs + tid)*4 + h];
    __syncthreads();

    for (int e = tid; e < 8192; e += 256) {
        const int i = e >> 8, d = e & 255;
        const size_t gg = ((size_t)(b*Ll + ci*CSs + i))*HD + h*256 + d;
        const float qv = Qn[gg], kv = Kn[gg], vv = V[gg];
        const float bi = sbp[i];
        __nv_bfloat16 hh, ll;
        split1(qv, hh, ll);
        *(__nv_bfloat16*)(smraw + OQH + (i*264+d)*2) = hh;
        *(__nv_bfloat16*)(smraw + OQL + (i*264+d)*2) = ll;
        QH[cb8+e] = hh; QL[cb8+e] = ll;
        split1(kv, hh, ll);
        *(__nv_bfloat16*)(smraw + OKH + (i*264+d)*2) = hh;
        *(__nv_bfloat16*)(smraw + OKL + (i*264+d)*2) = ll;
        split1(vv*bi, hh, ll);
        *(__nv_bfloat16*)(smraw + OVH + (i*264+d)*2) = hh;
        *(__nv_bfloat16*)(smraw + OVL + (i*264+d)*2) = ll;
        split1(kv*bi, hh, ll);
        *(__nv_bfloat16*)(smraw + OBH + (i*264+d)*2) = hh;
        *(__nv_bfloat16*)(smraw + OBL + (i*264+d)*2) = ll;
    }
    __syncthreads();

    {
        const int mt = warp>>2, ntw = warp&3;
        float qk[4] = {0,0,0,0}, kk[4] = {0,0,0,0};
        const unsigned arow_off = (mt*16 + (lane&15))*528 + ((lane>>4)*8)*2;
        const unsigned brow_off = (ntw*8 + (lane&7))*528 + (((lane>>3)&1)*8)*2;
        #pragma unroll
        for (int kt = 0; kt < 16; ++kt) {
            const unsigned kb2 = kt*32;
            unsigned aq[4], aql[4], ak4[4], akl[4], b2h[2], b2l[2];
            ldsm4(aq,  smb + OQH + arow_off + kb2);
            ldsm4(aql, smb + OQL + arow_off + kb2);
            ldsm4(ak4, smb + OKH + arow_off + kb2);
            ldsm4(akl, smb + OKL + arow_off + kb2);
            ldsm2(b2h, smb + OKH + brow_off + kb2);
            ldsm2(b2l, smb + OKL + brow_off + kb2);
            mma16816(qk, aq, b2h);  mma16816(qk, aql, b2h); mma16816(qk, aq, b2l);
            mma16816(kk, ak4, b2h); mma16816(kk, akl, b2h); mma16816(kk, ak4, b2l);
        }
        const int i0 = mt*16 + g, j0 = ntw*8 + qp;
        #pragma unroll
        for (int r = 0; r < 4; ++r) {
            const int i = i0 + (r>>1)*8, j = j0 + (r&1);
            Amp[i*33+j] = (i > j) ? sbp[i]*kk[r] : 0.f;
            const float av = (i >= j) ? qk[r] : 0.f;
            __nv_bfloat16 hh, ll;
            split1(av, hh, ll);
            AH[cb1 + i*32 + j] = hh; AL[cb1 + i*32 + j] = ll;
        }
    }
    for (int e = tid; e < 8192; e += 256) {
        const int d = e >> 5, t = e & 31;
        unsigned short hv = *(unsigned short*)(smraw + OKH + (t*264+d)*2) ^ 0x8000u;
        unsigned short lv = *(unsigned short*)(smraw + OKL + (t*264+d)*2) ^ 0x8000u;
        KH[cb8+e] = *(__nv_bfloat16*)&hv;
        KL[cb8+e] = *(__nv_bfloat16*)&lv;
    }
    __syncthreads();

    if (tid < 32) {
        const int j = tid;
        Tip[j] = (j == 0) ? 1.f : 0.f;
        for (int i2 = 1; i2 < 32; ++i2) {
            __syncwarp();
            float s = 0.f;
            for (int m = 0; m < i2; ++m) s += Amp[i2*33+m]*Tip[m*33+j];
            Tip[i2*33+j] = ((i2 == j) ? 1.f : 0.f) - s;
        }
    }
    __syncthreads();
    for (int e = tid; e < 1024; e += 256) {
        const int i = e >> 5, j = e & 31;
        __nv_bfloat16 hh, ll;
        split1(Tip[i*33+j], hh, ll);
        *(__nv_bfloat16*)(smraw + OTH + (i*40+j)*2) = hh;
        *(__nv_bfloat16*)(smraw + OTL + (i*40+j)*2) = ll;
    }
    __syncthreads();

    {
        const int mt = warp>>2;
        unsigned TiH[2][4], TiL[2][4];
        #pragma unroll
        for (int kt = 0; kt < 2; ++kt) {
            const unsigned ao = (mt*16 + (lane&15))*80 + (kt*16 + (lane>>4)*8)*2;
            ldsm4(TiH[kt], smb + OTH + ao);
            ldsm4(TiL[kt], smb + OTL + ao);
        }
        const int i0 = mt*16 + g;
        #pragma unroll
        for (int ng = 0; ng < 4; ++ng) {
            const int n0 = (warp&3)*64 + ng*16;
            float aU[2][4], aW[2][4];
            #pragma unroll
            for (int t2 = 0; t2 < 2; ++t2)
                #pragma unroll
                for (int r = 0; r < 4; ++r) { aU[t2][r]=0.f; aW[t2][r]=0.f; }
            #pragma unroll
            for (int kt = 0; kt < 2; ++kt) {
                const unsigned brow = kt*16 + (lane&7) + ((lane>>3)&1)*8;
                const unsigned bcol = n0 + ((lane>>4)&1)*8;
                const unsigned bo = brow*528 + bcol*2;
                unsigned bvh[4], bvl[4], bbh[4], bbl[4];
                ldsm4t(bvh, smb + OVH + bo);
                ldsm4t(bvl, smb + OVL + bo);
                ldsm4t(bbh, smb + OBH + bo);
                ldsm4t(bbl, smb + OBL + bo);
                #pragma unroll
                for (int nt = 0; nt < 2; ++nt) {
                    mma16816(aU[nt], TiH[kt], bvh+2*nt);
                    mma16816(aU[nt], TiL[kt], bvh+2*nt);
                    mma16816(aU[nt], TiH[kt], bvl+2*nt);
                    mma16816(aW[nt], TiH[kt], bbh+2*nt);
                    mma16816(aW[nt], TiL[kt], bbh+2*nt);
                    mma16816(aW[nt], TiH[kt], bbl+2*nt);
                }
            }
            #pragma unroll
            for (int nt = 0; nt < 2; ++nt)
                #pragma unroll
                for (int r = 0; r < 4; ++r) {
                    const int i = i0 + (r>>1)*8;
                    const int d = n0 + nt*8 + qp + (r&1);
                    U[cb8 + i*256 + d] = aU[nt][r];
                    __nv_bfloat16 hh, ll;
                    split1(aW[nt][r], hh, ll);
                    WH[cb8 + i*256 + d] = hh;
                    WL[cb8 + i*256 + d] = ll;
                }
        }
    }
}

// ---------------- tensor-core delta scan ----------------
#define STGSZ  72704
#define OFF_KT 145408
#define OFF_UB 210944
#define SC_SMEM 227840

__global__ void __launch_bounds__(128) scan_mma(
    const __nv_bfloat16* __restrict__ QHp, const __nv_bfloat16* __restrict__ QLp,
    const __nv_bfloat16* __restrict__ WHp, const __nv_bfloat16* __restrict__ WLp,
    const __nv_bfloat16* __restrict__ KHp, const __nv_bfloat16* __restrict__ KLp,
    const __nv_bfloat16* __restrict__ AHp, const __nv_bfloat16* __restrict__ ALp,
    const float* __restrict__ Ug, float* __restrict__ Out)
{
    extern __shared__ char smraw[];
    const unsigned smb = (unsigned)__cvta_generic_to_shared(smraw);
    float* ub = (float*)(smraw + OFF_UB);
    const int tid = threadIdx.x, warp = tid>>5, lane = tid&31;
    const int bh = blockIdx.x>>4, cb = blockIdx.x&15;
    const int b = bh>>2, h = bh&3;
    const int g = lane>>2, qp = (lane&3)*2;
    const int brow16 = ((lane>>4)&1)*8 + (lane&7);
    const int bcol8 = ((lane>>3)&1)*8;

    float P[8][4];
    #pragma unroll
    for (int i=0;i<8;++i)
        #pragma unroll
        for (int r=0;r<4;++r) P[i][r]=0.f;

    auto issue = [&](int ci, int stg){
        const size_t b8 = (size_t)(bh*NCc + ci)*8192;
        const size_t b1 = (size_t)(bh*NCc + ci)*1024;
        const unsigned sb = smb + stg*STGSZ;
        const __nv_bfloat16* srcs[4] = {QHp+b8, QLp+b8, WHp+b8, WLp+b8};
        #pragma unroll
        for (int pl = 0; pl < 4; ++pl){
            const unsigned dsb = sb + pl*16384;
            for (int e = tid; e < 1024; e += 128){
                int row = e>>5, c = e&31;
                cpa16(dsb + row*512 + ((c^(row&7))<<4), srcs[pl] + row*256 + c*8);
            }
        }
        const unsigned kb2 = smb + OFF_KT + stg*32768;
        for (int e = tid; e < 1024; e += 128){
            int row = e>>2, c = e&3;
            cpa16(kb2 + row*64 + c*16, KHp + b8 + row*32 + c*8);
            cpa16(kb2 + 16384 + row*64 + c*16, KLp + b8 + row*32 + c*8);
        }
        {
            int row = tid>>2, c = tid&3;
            cpa16(sb + 65536 + row*80 + c*16, AHp + b1 + row*32 + c*8);
            cpa16(sb + 68096 + row*80 + c*16, ALp + b1 + row*32 + c*8);
            cpa16(sb + 70656 + row*64 + c*16, Ug + b8 + (size_t)row*256 + cb*16 + c*4);
        }
    };

    issue(0, 0); CP_COMMIT();

    for (int ci = 0; ci < NCc; ++ci) {
        const int stg = ci & 1;
        const unsigned sb = smb + stg*STGSZ;
        const unsigned kb = smb + OFF_KT + stg*32768;
        CP_WAIT0();
        __syncthreads();

        float accW[4][4], accQ[4][4];
        #pragma unroll
        for (int i=0;i<4;++i)
            #pragma unroll
            for (int r=0;r<4;++r){ accW[i][r]=0.f; accQ[i][r]=0.f; }
        #pragma unroll
        for (int kt = 0; kt < 4; ++kt) {
            unsigned Ah[4], Al[4];
            const float* p0 = P[2*kt]; const float* p1 = P[2*kt+1];
            Ah[0]=pack2(p0[0],p0[1]); Ah[1]=pack2(p0[2],p0[3]);
            Ah[2]=pack2(p1[0],p1[1]); Ah[3]=pack2(p1[2],p1[3]);
            Al[0]=pack2(res1(p0[0]),res1(p0[1])); Al[1]=pack2(res1(p0[2]),res1(p0[3]));
            Al[2]=pack2(res1(p1[0]),res1(p1[1])); Al[3]=pack2(res1(p1[2]),res1(p1[3]));
            const int dcol = warp*64 + kt*16 + bcol8;
            unsigned bwh[4][2], bwl[4][2], bqh[4][2], bql[4][2];
            #pragma unroll
            for (int ng = 0; ng < 2; ++ng) {
                const int row = ng*16 + brow16;
                const unsigned off = row*512 + ((((unsigned)(dcol>>3))^(row&7))<<4);
                unsigned r4[4];
                ldsm4(r4, sb + 32768 + off);
                bwh[2*ng][0]=r4[0]; bwh[2*ng][1]=r4[1]; bwh[2*ng+1][0]=r4[2]; bwh[2*ng+1][1]=r4[3];
                ldsm4(r4, sb + 49152 + off);
                bwl[2*ng][0]=r4[0]; bwl[2*ng][1]=r4[1]; bwl[2*ng+1][0]=r4[2]; bwl[2*ng+1][1]=r4[3];
                ldsm4(r4, sb + off);
                bqh[2*ng][0]=r4[0]; bqh[2*ng][1]=r4[1]; bqh[2*ng+1][0]=r4[2]; bqh[2*ng+1][1]=r4[3];
                ldsm4(r4, sb + 16384 + off);
                bql[2*ng][0]=r4[0]; bql[2*ng][1]=r4[1]; bql[2*ng+1][0]=r4[2]; bql[2*ng+1][1]=r4[3];
            }
            #pragma unroll
            for (int nt = 0; nt < 4; ++nt) {
                mma16816(accW[nt], Ah, bwh[nt]);
                mma16816(accW[nt], Al, bwh[nt]);
                mma16816(accW[nt], Ah, bwl[nt]);
                mma16816(accQ[nt], Ah, bqh[nt]);
                mma16816(accQ[nt], Al, bqh[nt]);
                mma16816(accQ[nt], Ah, bql[nt]);
            }
        }
        #pragma unroll
        for (int nt = 0; nt < 4; ++nt)
            #pragma unroll
            for (int r = 0; r < 4; ++r) {
                int c = g + ((r>>1)<<3), t = nt*8 + qp + (r&1);
                ub[(c*4+warp)*66 + t] = accW[nt][r];
                ub[(c*4+warp)*66 + 32 + t] = accQ[nt][r];
            }
        if (ci + 1 < NCc) { issue(ci+1, stg^1); CP_COMMIT(); }
        __syncthreads();

        const float* su = (const float*)(smraw + stg*STGSZ + 70656);
        unsigned UH[2][4], UL[2][4];
        #pragma unroll
        for (int kt = 0; kt < 2; ++kt) {
            float v[8];
            #pragma unroll
            for (int p = 0; p < 8; ++p) {
                const int c = g + (((p>>1)&1)<<3);
                const int t = kt*16 + qp + (p&1) + ((p>>2)<<3);
                const int bi = (c*4)*66 + t;
                v[p] = su[t*16 + c] + ub[bi] + ub[bi+66] + ub[bi+132] + ub[bi+198];
            }
            UH[kt][0]=pack2(v[0],v[1]); UH[kt][1]=pack2(v[2],v[3]);
            UH[kt][2]=pack2(v[4],v[5]); UH[kt][3]=pack2(v[6],v[7]);
            UL[kt][0]=pack2(res1(v[0]),res1(v[1])); UL[kt][1]=pack2(res1(v[2]),res1(v[3]));
            UL[kt][2]=pack2(res1(v[4]),res1(v[5])); UL[kt][3]=pack2(res1(v[6]),res1(v[7]));
        }
        float oc[4];
        const int i0 = warp*8 + qp;
        #pragma unroll
        for (int r = 0; r < 4; ++r) {
            const int c = g + ((r>>1)<<3);
            const int bi = (c*4)*66 + 32 + i0 + (r&1);
            oc[r] = -(ub[bi] + ub[bi+66] + ub[bi+132] + ub[bi+198]);
        }

        #pragma unroll
        for (int kt = 0; kt < 2; ++kt) {
            unsigned bh2[2], bl2[2];
            const unsigned aoff = (warp*8 + (lane&7))*80 + (kt*16 + bcol8)*2;
            ldsm2(bh2, sb + 65536 + aoff);
            ldsm2(bl2, sb + 68096 + aoff);
            mma16816(oc, UH[kt], bh2);
            mma16816(oc, UL[kt], bh2);
            mma16816(oc, UH[kt], bl2);
        }
        {
            const size_t base = ((size_t)(b*Ll + ci*CSs + i0))*HD + h*256 + cb*16;
            Out[base + g]          = oc[0];
            Out[base + HD + g]     = oc[1];
            Out[base + g + 8]      = oc[2];
            Out[base + HD + g + 8] = oc[3];
        }

        #pragma unroll
        for (int kt = 0; kt < 2; ++kt) {
            #pragma unroll
            for (int np = 0; np < 4; ++np) {
                unsigned bh4[4], bl4[4];
                const unsigned off = (warp*64 + np*16 + brow16)*64 + (kt*16 + bcol8)*2;
                ldsm4(bh4, kb + off);
                ldsm4(bl4, kb + 16384 + off);
                mma16816(P[2*np],   UH[kt], bh4);
                mma16816(P[2*np],   UL[kt], bh4);
                mma16816(P[2*np],   UH[kt], bl4);
                mma16816(P[2*np+1], UH[kt], bh4+2);
                mma16816(P[2*np+1], UL[kt], bh4+2);
                mma16816(P[2*np+1], UH[kt], bl4+2);
            }
        }
    }
}

// ---------------- FIR short/long + gate_in (writes bf16 hi/lo gin directly) ----------
__global__ void fir_gatein_kernel(const unsigned* __restrict__ hsHu, const unsigned* __restrict__ hsLu,
                                  const float* __restrict__ V,
                                  const float* __restrict__ ws, const float* __restrict__ wl,
                                  const float* __restrict__ Dl,
                                  float* __restrict__ Sout, float* __restrict__ Lout,
                                  __nv_bfloat16* __restrict__ GinH, __nv_bfloat16* __restrict__ GinL)
{
    const int blk = blockIdx.x;
    const int b = blk / (Ll/8);
    const int l0 = (blk % (Ll/8)) * 8;
    const int tid = threadIdx.x;
    float smean[8], lmean[8], dmean[8];
    #pragma unroll
    for (int r = 0; r < 8; ++r) { smean[r]=0.f; lmean[r]=0.f; dmean[r]=0.f; }
    for (int j = 0; j < 4; ++j) {
        const int ch = tid + 256*j;
        float win[38];
        #pragma unroll
        for (int t = 0; t < 38; ++t) {
            const int l = l0 - 30 + t;
            win[t] = (l >= 0) ? V[((size_t)(b*Ll + l))*HD + ch] : 0.f;
        }
        float wlr[31];
        #pragma unroll
        for (int t = 0; t < 31; ++t) wlr[t] = wl[ch*31 + t];
        const float w0 = ws[ch*3+0], w1 = ws[ch*3+1], w2 = ws[ch*3+2];
        #pragma unroll
        for (int r = 0; r < 8; ++r) {
            float yl = 0.f;
            #pragma unroll
            for (int t = 0; t < 31; ++t) yl += win[r+t]*wlr[t];
            const float ysv = win[r+28]*w0 + win[r+29]*w1 + win[r+30]*w2;
            const size_t row = (size_t)(b*Ll + l0 + r);
            Sout[row*HD + ch] = ysv;
            Lout[row*HD + ch] = yl;
            smean[r] += ysv; lmean[r] += yl;
            dmean[r] += Dl[row*HD + ch];
        }
    }
    for (int r = 0; r < 8; ++r) {
        const size_t row = (size_t)(b*Ll + l0 + r);
        __nv_bfloat16* gH = GinH + row*GIN;
        __nv_bfloat16* gL = GinL + row*GIN;
        #pragma unroll
        for (int j = 0; j < 2; ++j) {
            const int e = tid + 256*j;
            ((unsigned*)gH)[e] = hsHu[row*512 + e];
            ((unsigned*)gL)[e] = hsLu[row*512 + e];
        }
        __nv_bfloat16 hh, ll;
        split1(smean[r]*0.25f, hh, ll);
        gH[1024 + tid] = hh; gL[1024 + tid] = ll;
        split1(lmean[r]*0.25f, hh, ll);
        gH[1280 + tid] = hh; gL[1280 + tid] = ll;
        split1(dmean[r]*0.25f, hh, ll);
        gH[1536 + tid] = hh; gL[1536 + tid] = ll;
    }
}

// ---------------- gate head 2 ----------------
__global__ void gate2_wgt(const float* __restrict__ GH2, const float* __restrict__ W2,
                          const float* __restrict__ b2, const float* __restrict__ ltemp,
                          float* __restrict__ Wgt)
{
    const int row = blockIdx.x;
    const int warp = threadIdx.x >> 5, lane = threadIdx.x & 31;
    __shared__ float lg[4];
    const float* x = GH2 + (size_t)row*GHID;
    const float* w = W2 + warp*GHID;
    float s = 0.f;
    for (int i = lane; i < GHID; i += 32) s += x[i]*w[i];
    #pragma unroll
    for (int o = 16; o; o >>= 1) s += __shfl_xor_sync(0xffffffff, s, o);
    if (lane == 0) lg[warp] = s + b2[warp];
    __syncthreads();
    if (threadIdx.x == 0) {
        const float t = log1pf(expf(ltemp[0])) + 1e-4f;
        float m = fmaxf(fmaxf(lg[0], lg[1]), fmaxf(lg[2], lg[3]));
        float e[4]; float se = 0.f;
        #pragma unroll
        for (int j = 0; j < 4; ++j) { e[j] = expf((lg[j]-m)/t); se += e[j]; }
        #pragma unroll
        for (int j = 0; j < 4; ++j) e[j] /= se;
        const float fl = 0.05f * e[3];
        e[0] = fmaxf(e[0], fl);
        e[1] = fmaxf(e[1], fl);
        const float s2 = e[0]+e[1]+e[2]+e[3];
        #pragma unroll
        for (int j = 0; j < 4; ++j) Wgt[row*4+j] = e[j]/s2;
    }
}

// ---------------- combine + RMSNorm (writes bf16 hi/lo directly) ----------------
__global__ void combine_kernel(const float* __restrict__ Sh, const float* __restrict__ Lg,
                               const float* __restrict__ Dl, const float* __restrict__ V,
                               const float* __restrict__ Wgt, const float* __restrict__ onw,
                               __nv_bfloat16* __restrict__ OH, __nv_bfloat16* __restrict__ OL)
{
    const int row = blockIdx.x;
    const int tid = threadIdx.x, lane = tid & 31;
    __shared__ float red[4];
    if (tid < 4) red[tid] = 0.f;
    __syncthreads();
    const float w0 = Wgt[row*4+0], w1 = Wgt[row*4+1], w2 = Wgt[row*4+2], w3 = Wgt[row*4+3];
    float ov[4];
    #pragma unroll
    for (int j = 0; j < 4; ++j) {
        const size_t g = (size_t)row*HD + tid + 256*j;
        ov[j] = w0*Sh[g] + w1*Lg[g] + w2*Dl[g] + w3*V[g];
        float v = ov[j]*ov[j];
        #pragma unroll
        for (int o = 16; o; o >>= 1) v += __shfl_xor_sync(0xffffffff, v, o);
        if (lane == 0) atomicAdd(&red[j], v);
    }
    __syncthreads();
    #pragma unroll
    for (int j = 0; j < 4; ++j) {
        const float sc = rsqrtf(red[j]*(1.f/256.f) + 1e-5f) * onw[tid];
        __nv_bfloat16 hh, ll;
        split1(ov[j]*sc, hh, ll);
        OH[(size_t)row*HD + tid + 256*j] = hh;
        OL[(size_t)row*HD + tid + 256*j] = ll;
    }
}

// ---------------- launch ----------------
extern "C" void kernel_launch(void* const* d_in, const int* in_sizes, int n_in,
                              void* d_out, int out_size)
{
    const float* hs  = (const float*)d_in[0];
    const float* qw  = (const float*)d_in[1];
    const float* kw  = (const float*)d_in[2];
    const float* vw  = (const float*)d_in[3];
    const float* bw  = (const float*)d_in[4];
    const float* qcw = (const float*)d_in[5];
    const float* kcw = (const float*)d_in[6];
    const float* vcw = (const float*)d_in[7];
    const float* fsw = (const float*)d_in[8];
    const float* flw = (const float*)d_in[9];
    const float* w1  = (const float*)d_in[10];
    const float* b1  = (const float*)d_in[11];
    const float* w2  = (const float*)d_in[12];
    const float* b2  = (const float*)d_in[13];
    const float* lt  = (const float*)d_in[14];
    const float* onw = (const float*)d_in[15];
    const float* ow  = (const float*)d_in[16];
    float* out = (float*)d_out;

    float *xqkv,*q,*k,*v,*u,*delta,*shrt,*lng,*gh,*beta,*wgt;
    __nv_bfloat16 *hsH,*hsL,*ginH,*ginL,*ocH,*ocL,*wtH,*wtL;
    __nv_bfloat16 *qh,*ql,*wh,*wlp,*kh,*kl,*ah,*al;
    cudaGetSymbolAddress((void**)&xqkv, g_xqkv);
    cudaGetSymbolAddress((void**)&q,    g_q);
    cudaGetSymbolAddress((void**)&k,    g_k);
    cudaGetSymbolAddress((void**)&v,    g_v);
    cudaGetSymbolAddress((void**)&u,    g_u);
    cudaGetSymbolAddress((void**)&delta,g_delta);
    cudaGetSymbolAddress((void**)&shrt, g_short);
    cudaGetSymbolAddress((void**)&lng,  g_long);
    cudaGetSymbolAddress((void**)&gh,   g_gh);
    cudaGetSymbolAddress((void**)&beta, g_beta);
    cudaGetSymbolAddress((void**)&wgt,  g_wgt);
    cudaGetSymbolAddress((void**)&hsH,  g_hsH);
    cudaGetSymbolAddress((void**)&hsL,  g_hsL);
    cudaGetSymbolAddress((void**)&ginH, g_ginH);
    cudaGetSymbolAddress((void**)&ginL, g_ginL);
    cudaGetSymbolAddress((void**)&ocH,  g_ocH);
    cudaGetSymbolAddress((void**)&ocL,  g_ocL);
    cudaGetSymbolAddress((void**)&wtH,  g_wtH);
    cudaGetSymbolAddress((void**)&wtL,  g_wtL);
    cudaGetSymbolAddress((void**)&qh,   g_qh);
    cudaGetSymbolAddress((void**)&ql,   g_ql);
    cudaGetSymbolAddress((void**)&wh,   g_wh);
    cudaGetSymbolAddress((void**)&wlp,  g_wl);
    cudaGetSymbolAddress((void**)&kh,   g_kh);
    cudaGetSymbolAddress((void**)&kl,   g_kl);
    cudaGetSymbolAddress((void**)&ah,   g_ah);
    cudaGetSymbolAddress((void**)&al,   g_al);

    cudaFuncSetAttribute(precompute_kernel, cudaFuncAttributeMaxDynamicSharedMemorySize, PRE_SMEM);
    cudaFuncSetAttribute(scan_mma, cudaFuncAttributeMaxDynamicSharedMemorySize, SC_SMEM);
    cudaFuncSetAttribute(hgemm_nt<false>, cudaFuncAttributeMaxDynamicSharedMemorySize, G2_SMEM);
    cudaFuncSetAttribute(hgemm_nt<true>,  cudaFuncAttributeMaxDynamicSharedMemorySize, G2_SMEM);

    // hs split + merged weight split
    {
        int n4 = (BL*Dd) >> 2;
        split_kernel<<<(n4 + 255)/256, 256>>>((const float4*)hs, (uint2*)hsH, (uint2*)hsL, n4);
    }
    wsplit_kernel<<<(W4_O + 255)/256, 256>>>((const float4*)qw, (const float4*)kw,
                                             (const float4*)vw, (const float4*)w1,
                                             (const float4*)ow, (uint2*)wtH, (uint2*)wtL);

    // fused q/k/v projection: C[8192,3072]
    hgemm_nt<false><<<dim3(3072/256, BL/128), 512, G2_SMEM>>>(
        hsH, hsL, wtH+WOFF_Q, wtL+WOFF_Q, xqkv, BL, 3072, Dd, nullptr);
    beta_kernel<<<BL, 128>>>(hs, bw, beta);
    conv_silu_norm<<<BL, 256>>>(xqkv, qcw, kcw, vcw, q, k, v);
    precompute_kernel<<<8*NCc, 256, PRE_SMEM>>>(q, k, v, beta, u,
                                                qh, ql, wh, wlp, kh, kl, ah, al);
    scan_mma<<<128, 128, SC_SMEM>>>(qh, ql, wh, wlp, kh, kl, ah, al, u, delta);
    fir_gatein_kernel<<<Bb*(Ll/8), 256>>>((const unsigned*)hsH, (const unsigned*)hsL,
                                          v, fsw, flw, delta, shrt, lng, ginH, ginL);
    hgemm_nt<true><<<dim3(GHID/256, BL/128), 512, G2_SMEM>>>(
        ginH, ginL, wtH+WOFF_W1, wtL+WOFF_W1, gh, BL, GHID, GIN, b1);
    gate2_wgt<<<BL, 128>>>(gh, w2, b2, lt, wgt);
    combine_kernel<<<BL, 256>>>(shrt, lng, delta, v, wgt, onw, ocH, ocL);
    hgemm_nt<false><<<dim3(Dd/256, BL/128), 512, G2_SMEM>>>(
        ocH, ocL, wtH+WOFF_O, wtL+WOFF_O, out, BL, Dd, HD, nullptr);
}

// round 9
// speedup vs baseline: 3.1473x; 1.0266x over previous
#include <cuda_runtime.h>
#include <cuda_bf16.h>
#include <math.h>

#define Bb   2
#define Ll   4096
#define Dd   1024
#define Hh   4
#define CSs  32
#define NCc  128
#define BL   (Bb*Ll)
#define HD   1024
#define GIN  1792
#define GHID 1024
#define CH8  (8*NCc*8192)

// ---------------- scratch ----------------
__device__ float g_xqkv[BL*3072];
__device__ float g_q [BL*HD];
__device__ float g_k [BL*HD];
__device__ float g_v [BL*HD];
__device__ float g_u [CH8];
__device__ float g_delta[BL*HD];
__device__ float g_short[BL*HD];
__device__ float g_long [BL*HD];
__device__ float g_gh [BL*GHID];
__device__ float g_beta[BL*Hh];
__device__ float g_wgt [BL*4];

__device__ __align__(16) __nv_bfloat16 g_hsH[BL*Dd];
__device__ __align__(16) __nv_bfloat16 g_hsL[BL*Dd];
__device__ __align__(16) __nv_bfloat16 g_ginH[BL*GIN];
__device__ __align__(16) __nv_bfloat16 g_ginL[BL*GIN];
__device__ __align__(16) __nv_bfloat16 g_ocH[BL*HD];
__device__ __align__(16) __nv_bfloat16 g_ocL[BL*HD];
#define WOFF_Q  0
#define WOFF_K  (1024*1024)
#define WOFF_V  (2*1024*1024)
#define WOFF_W1 (3*1024*1024)
#define WOFF_O  (3*1024*1024 + 1792*1024)
#define WTOT    (WOFF_O + 1024*1024)
__device__ __align__(16) __nv_bfloat16 g_wtH[WTOT];
__device__ __align__(16) __nv_bfloat16 g_wtL[WTOT];

// scan operand planes
__device__ __align__(16) __nv_bfloat16 g_qh[CH8], g_ql[CH8], g_wh[CH8], g_wl[CH8], g_kh[CH8], g_kl[CH8];
__device__ __align__(16) __nv_bfloat16 g_ah[8*NCc*1024], g_al[8*NCc*1024];

// ---------------- helpers ----------------
__device__ __forceinline__ float siluf(float x){ return x / (1.f + expf(-x)); }
__device__ __forceinline__ float geluf(float x){ return 0.5f * x * (1.f + erff(x * 0.70710678118654752f)); }
__device__ __forceinline__ void ldsm4(unsigned* r, unsigned addr){
    asm volatile("ldmatrix.sync.aligned.m8n8.x4.shared.b16 {%0,%1,%2,%3}, [%4];"
        : "=r"(r[0]),"=r"(r[1]),"=r"(r[2]),"=r"(r[3]) : "r"(addr));
}
__device__ __forceinline__ void ldsm4t(unsigned* r, unsigned addr){
    asm volatile("ldmatrix.sync.aligned.m8n8.x4.trans.shared.b16 {%0,%1,%2,%3}, [%4];"
        : "=r"(r[0]),"=r"(r[1]),"=r"(r[2]),"=r"(r[3]) : "r"(addr));
}
__device__ __forceinline__ void ldsm2(unsigned* r, unsigned addr){
    asm volatile("ldmatrix.sync.aligned.m8n8.x2.shared.b16 {%0,%1}, [%2];"
        : "=r"(r[0]),"=r"(r[1]) : "r"(addr));
}
__device__ __forceinline__ void mma16816(float* c, const unsigned* a, const unsigned* b){
    asm volatile("mma.sync.aligned.m16n8k16.row.col.f32.bf16.bf16.f32 "
        "{%0,%1,%2,%3}, {%4,%5,%6,%7}, {%8,%9}, {%0,%1,%2,%3};"
        : "+f"(c[0]),"+f"(c[1]),"+f"(c[2]),"+f"(c[3])
        : "r"(a[0]),"r"(a[1]),"r"(a[2]),"r"(a[3]), "r"(b[0]),"r"(b[1]));
}
__device__ __forceinline__ void cpa16(unsigned d, const void* s){
    asm volatile("cp.async.cg.shared.global [%0],[%1],16;\n" :: "r"(d), "l"(s));
}
#define CP_COMMIT() asm volatile("cp.async.commit_group;\n")
#define CP_WAIT0()  asm volatile("cp.async.wait_group 0;\n")
__device__ __forceinline__ unsigned pack2(float a, float b){
    __nv_bfloat162 t; t.x=__float2bfloat16(a); t.y=__float2bfloat16(b);
    return *(unsigned*)&t;
}
__device__ __forceinline__ float res1(float v){ return v - __bfloat162float(__float2bfloat16(v)); }
__device__ __forceinline__ void split1(float v, __nv_bfloat16& h, __nv_bfloat16& l){
    h = __float2bfloat16(v); l = __float2bfloat16(v - __bfloat162float(h));
}

// ---------------- fp32 -> (hi,lo) bf16 split ----------------
__global__ void split_kernel(const float4* __restrict__ x, uint2* __restrict__ hi,
                             uint2* __restrict__ lo, int n4)
{
    int i = blockIdx.x*blockDim.x + threadIdx.x;
    if (i >= n4) return;
    float4 v = x[i];
    uint2 ho, loo;
    ho.x = pack2(v.x, v.y);  ho.y = pack2(v.z, v.w);
    loo.x = pack2(res1(v.x), res1(v.y)); loo.y = pack2(res1(v.z), res1(v.w));
    hi[i] = ho; lo[i] = loo;
}

// ---------------- merged weight split ----------------
#define W4_Q  262144
#define W4_K  524288
#define W4_V  786432
#define W4_W1 1245184
#define W4_O  1507328
__global__ void wsplit_kernel(const float4* __restrict__ qw, const float4* __restrict__ kw,
                              const float4* __restrict__ vw, const float4* __restrict__ w1,
                              const float4* __restrict__ ow,
                              uint2* __restrict__ hi, uint2* __restrict__ lo)
{
    int i = blockIdx.x*blockDim.x + threadIdx.x;
    if (i >= W4_O) return;
    const float4* src; int local;
    if      (i < W4_Q)  { src = qw; local = i; }
    else if (i < W4_K)  { src = kw; local = i - W4_Q; }
    else if (i < W4_V)  { src = vw; local = i - W4_K; }
    else if (i < W4_W1) { src = w1; local = i - W4_V; }
    else                { src = ow; local = i - W4_W1; }
    float4 v = src[local];
    uint2 ho, loo;
    ho.x = pack2(v.x, v.y);  ho.y = pack2(v.z, v.w);
    loo.x = pack2(res1(v.x), res1(v.y)); loo.y = pack2(res1(v.z), res1(v.w));
    hi[i] = ho; lo[i] = loo;
}

// ---------------- bf16x3 split GEMM, 128x256 tile, 512 threads ----------
#define G2_STG   18432
#define G2_SMEM  (2*G2_STG*2)
template<bool EPI>
__global__ void __launch_bounds__(512) hgemm_nt(const __nv_bfloat16* __restrict__ Ah,
                                                const __nv_bfloat16* __restrict__ Al,
                                                const __nv_bfloat16* __restrict__ Bh,
                                                const __nv_bfloat16* __restrict__ Bl,
                                                float* __restrict__ C,
                                                int M, int N, int K,
                                                const float* __restrict__ bias)
{
    extern __shared__ __align__(16) __nv_bfloat16 sm[];
    const int tid = threadIdx.x;
    const int bm = blockIdx.y*128, bn = blockIdx.x*256;
    const int warp = tid>>5, lane = tid&31;
    const int wm = warp>>3, wn = warp&7;
    float acc[4][4][4];
    #pragma unroll
    for (int i=0;i<4;i++) for(int j=0;j<4;j++) for(int r=0;r<4;r++) acc[i][j][r]=0.f;

    const bool doA = tid < 256;
    const size_t aoff = (size_t)(bm + ((tid & 255)>>1))*K + (tid&1)*8;
    const size_t boff = (size_t)(bn + (tid>>1))*K + (tid&1)*8;
    const int stoA = ((tid & 255)>>1)*24 + (tid&1)*8;
    const int stoB = 6144 + (tid>>1)*24 + (tid&1)*8;

    unsigned base = (unsigned)__cvta_generic_to_shared(sm);
    const int arow = wm*64 + (lane&15);
    const int acol = (lane>>4)*8;
    const int brow = wn*32 + ((lane>>4)&1)*8 + (lane&7);
    const int bcol = ((lane>>3)&1)*8;
    const int nk = K >> 4;

    {
        uint4 rAh, rAl;
        if (doA) { rAh = *(const uint4*)(Ah + aoff); rAl = *(const uint4*)(Al + aoff); }
        uint4 rBh = *(const uint4*)(Bh + boff);
        uint4 rBl = *(const uint4*)(Bl + boff);
        if (doA) {
            *(uint4*)(sm + stoA) = rAh;
            *(uint4*)(sm + 3072 + stoA) = rAl;
        }
        *(uint4*)(sm + stoB) = rBh;
        *(uint4*)(sm + 6144 + stoB) = rBl;
    }
    __syncthreads();

    for (int kt = 0; kt < nk; ++kt) {
        const int cur = kt & 1;
        const unsigned sb = base + (unsigned)cur*(G2_STG*2);
        uint4 nAh, nAl, nBh, nBl;
        const bool more = (kt + 1 < nk);
        if (more) {
            const size_t kb = boff + (size_t)(kt+1)*16;
            nBh = *(const uint4*)(Bh + kb);
            nBl = *(const uint4*)(Bl + kb);
            if (doA) {
                const size_t ka = aoff + (size_t)(kt+1)*16;
                nAh = *(const uint4*)(Ah + ka);
                nAl = *(const uint4*)(Al + ka);
            }
        }
        unsigned bh[4][2], bl[4][2];
        #pragma unroll
        for (int ng = 0; ng < 2; ++ng) {
            unsigned r4[4];
            ldsm4(r4, sb + 2u*(6144 + (brow + ng*16)*24 + bcol));
            bh[2*ng][0]=r4[0]; bh[2*ng][1]=r4[1]; bh[2*ng+1][0]=r4[2]; bh[2*ng+1][1]=r4[3];
            ldsm4(r4, sb + 2u*(12288 + (brow + ng*16)*24 + bcol));
            bl[2*ng][0]=r4[0]; bl[2*ng][1]=r4[1]; bl[2*ng+1][0]=r4[2]; bl[2*ng+1][1]=r4[3];
        }
        #pragma unroll
        for (int mt = 0; mt < 4; ++mt) {
            unsigned ah[4], al[4];
            ldsm4(ah, sb + 2u*((arow + mt*16)*24 + acol));
            ldsm4(al, sb + 2u*(3072 + (arow + mt*16)*24 + acol));
            #pragma unroll
            for (int nt = 0; nt < 4; ++nt) {
                mma16816(acc[mt][nt], ah, bh[nt]);
                mma16816(acc[mt][nt], ah, bl[nt]);
                mma16816(acc[mt][nt], al, bh[nt]);
            }
        }
        if (more) {
            __nv_bfloat16* d = sm + (cur^1)*G2_STG;
            if (doA) {
                *(uint4*)(d + stoA) = nAh;
                *(uint4*)(d + 3072 + stoA) = nAl;
            }
            *(uint4*)(d + stoB) = nBh;
            *(uint4*)(d + 6144 + stoB) = nBl;
            __syncthreads();
        }
    }
    const int g = lane>>2, tig = lane&3;
    #pragma unroll
    for (int mt = 0; mt < 4; ++mt) {
        const int row0 = bm + wm*64 + mt*16 + g;
        #pragma unroll
        for (int nt = 0; nt < 4; ++nt) {
            const int col = bn + wn*32 + nt*8 + tig*2;
            float v0 = acc[mt][nt][0], v1 = acc[mt][nt][1];
            float v2 = acc[mt][nt][2], v3 = acc[mt][nt][3];
            if (EPI) {
                const float bz0 = bias[col], bz1 = bias[col+1];
                v0 = geluf(v0+bz0); v1 = geluf(v1+bz1);
                v2 = geluf(v2+bz0); v3 = geluf(v3+bz1);
            }
            *(float2*)(C + (size_t)row0*N + col)     = make_float2(v0, v1);
            *(float2*)(C + (size_t)(row0+8)*N + col) = make_float2(v2, v3);
        }
    }
}

// ---------------- beta ----------------
__global__ void beta_kernel(const float* __restrict__ hs, const float* __restrict__ bw,
                            float* __restrict__ beta)
{
    const int row = blockIdx.x;
    const int warp = threadIdx.x >> 5, lane = threadIdx.x & 31;
    const float* x = hs + (size_t)row * Dd;
    const float* w = bw + warp * Dd;
    float s = 0.f;
    for (int i = lane; i < Dd; i += 32) s += x[i] * w[i];
    #pragma unroll
    for (int o = 16; o; o >>= 1) s += __shfl_xor_sync(0xffffffff, s, o);
    if (lane == 0) beta[row*4 + warp] = 1.f / (1.f + expf(-s));
}

// ---------------- conv + silu + l2norm, 8 rows/block, register windows ----------------
#define CV_SMEM ((16384 + 64)*4)
__global__ void __launch_bounds__(256) conv_silu_norm(const float* __restrict__ XQKV,
                               const float* __restrict__ WQ, const float* __restrict__ WK,
                               const float* __restrict__ WV,
                               float* __restrict__ Qo, float* __restrict__ Ko,
                               float* __restrict__ Vo)
{
    extern __shared__ float cs[];
    float* sq = cs;            // [8][1024]
    float* sk = cs + 8192;
    float* red = cs + 16384;   // redq[32], redk[32]
    const int blk = blockIdx.x;
    const int b = blk / (Ll/8);
    const int l0 = (blk % (Ll/8)) * 8;
    const int tid = threadIdx.x;
    const int warp = tid>>5, lane = tid&31;
    if (tid < 64) red[tid] = 0.f;
    __syncthreads();

    #pragma unroll
    for (int j = 0; j < 4; ++j) {
        const int c = tid + 256*j;
        float win[11];
        // --- q stream ---
        #pragma unroll
        for (int t = 0; t < 11; ++t) {
            const int l = l0 - 3 + t;
            win[t] = (l >= 0) ? XQKV[((size_t)(b*Ll + l))*3072 + c] : 0.f;
        }
        {
            const float w0 = WQ[c*4+0], w1 = WQ[c*4+1], w2 = WQ[c*4+2], w3 = WQ[c*4+3];
            #pragma unroll
            for (int r = 0; r < 8; ++r)
                sq[r*1024 + c] = siluf(win[r]*w0 + win[r+1]*w1 + win[r+2]*w2 + win[r+3]*w3);
        }
        // --- k stream ---
        #pragma unroll
        for (int t = 0; t < 11; ++t) {
            const int l = l0 - 3 + t;
            win[t] = (l >= 0) ? XQKV[((size_t)(b*Ll + l))*3072 + 1024 + c] : 0.f;
        }
        {
            const float w0 = WK[c*4+0], w1 = WK[c*4+1], w2 = WK[c*4+2], w3 = WK[c*4+3];
            #pragma unroll
            for (int r = 0; r < 8; ++r)
                sk[r*1024 + c] = siluf(win[r]*w0 + win[r+1]*w1 + win[r+2]*w2 + win[r+3]*w3);
        }
        // --- v stream (direct write) ---
        #pragma unroll
        for (int t = 0; t < 11; ++t) {
            const int l = l0 - 3 + t;
            win[t] = (l >= 0) ? XQKV[((size_t)(b*Ll + l))*3072 + 2048 + c] : 0.f;
        }
        {
            const float w0 = WV[c*4+0], w1 = WV[c*4+1], w2 = WV[c*4+2], w3 = WV[c*4+3];
            #pragma unroll
            for (int r = 0; r < 8; ++r)
                Vo[((size_t)(b*Ll + l0 + r))*HD + c] =
                    siluf(win[r]*w0 + win[r+1]*w1 + win[r+2]*w2 + win[r+3]*w3);
        }
    }
    __syncthreads();

    // reduction: 32 (row,head) groups x2 (q,k); warp handles 8 groups
    #pragma unroll
    for (int gi = 0; gi < 4; ++gi) {
        const int group = warp*4 + gi;          // 0..31
        const int r = group >> 2, h = group & 3;
        float sQ = 0.f, sK = 0.f;
        #pragma unroll
        for (int i = 0; i < 8; ++i) {
            const float vq = sq[r*1024 + h*256 + lane + 32*i];
            const float vk = sk[r*1024 + h*256 + lane + 32*i];
            sQ += vq*vq; sK += vk*vk;
        }
        #pragma unroll
        for (int o = 16; o; o >>= 1) {
            sQ += __shfl_xor_sync(0xffffffff, sQ, o);
            sK += __shfl_xor_sync(0xffffffff, sK, o);
        }
        if (lane == 0) { red[group] = rsqrtf(sQ + 1e-12f); red[32+group] = rsqrtf(sK + 1e-12f); }
    }
    __syncthreads();

    #pragma unroll
    for (int j = 0; j < 4; ++j) {
        const int c = tid + 256*j;
        #pragma unroll
        for (int r = 0; r < 8; ++r) {
            const size_t go = ((size_t)(b*Ll + l0 + r))*HD + c;
            Qo[go] = sq[r*1024 + c] * red[r*4 + j];
            Ko[go] = sk[r*1024 + c] * red[32 + r*4 + j];
        }
    }
}

// ---------------- precompute (tensor-core) ----------------
#define PPLN 16896
#define OQH 0
#define OQL 16896
#define OKH 33792
#define OKL 50688
#define OVH 67584
#define OVL 84480
#define OBH 101376
#define OBL 118272
#define OTH 135168
#define OTL 137728
#define OAM 140288
#define OTI 144512
#define OSB 148736
#define PRE_SMEM 148992

__global__ void __launch_bounds__(256) precompute_kernel(
    const float* __restrict__ Qn, const float* __restrict__ Kn,
    const float* __restrict__ V,  const float* __restrict__ beta,
    float* __restrict__ U,
    __nv_bfloat16* __restrict__ QH, __nv_bfloat16* __restrict__ QL,
    __nv_bfloat16* __restrict__ WH, __nv_bfloat16* __restrict__ WL,
    __nv_bfloat16* __restrict__ KH, __nv_bfloat16* __restrict__ KL,
    __nv_bfloat16* __restrict__ AH, __nv_bfloat16* __restrict__ AL)
{
    extern __shared__ char smraw[];
    const unsigned smb = (unsigned)__cvta_generic_to_shared(smraw);
    float* Amp = (float*)(smraw + OAM);
    float* Tip = (float*)(smraw + OTI);
    float* sbp = (float*)(smraw + OSB);
    const int idx = blockIdx.x;
    const int bh = idx >> 7, ci = idx & 127;
    const int b = bh >> 2, h = bh & 3;
    const int tid = threadIdx.x, warp = tid>>5, lane = tid&31;
    const int g = lane>>2, qp = (lane&3)*2;
    const size_t cb8 = (size_t)idx*8192;
    const size_t cb1 = (size_t)idx*1024;

    if (tid < 32) sbp[tid] = beta[(size_t)(b*Ll + ci*CSs + tid)*4 + h];
    __syncthreads();

    for (int e = tid; e < 8192; e += 256) {
        const int i = e >> 8, d = e & 255;
        const size_t gg = ((size_t)(b*Ll + ci*CSs + i))*HD + h*256 + d;
        const float qv = Qn[gg], kv = Kn[gg], vv = V[gg];
        const float bi = sbp[i];
        __nv_bfloat16 hh, ll;
        split1(qv, hh, ll);
        *(__nv_bfloat16*)(smraw + OQH + (i*264+d)*2) = hh;
        *(__nv_bfloat16*)(smraw + OQL + (i*264+d)*2) = ll;
        QH[cb8+e] = hh; QL[cb8+e] = ll;
        split1(kv, hh, ll);
        *(__nv_bfloat16*)(smraw + OKH + (i*264+d)*2) = hh;
        *(__nv_bfloat16*)(smraw + OKL + (i*264+d)*2) = ll;
        split1(vv*bi, hh, ll);
        *(__nv_bfloat16*)(smraw + OVH + (i*264+d)*2) = hh;
        *(__nv_bfloat16*)(smraw + OVL + (i*264+d)*2) = ll;
        split1(kv*bi, hh, ll);
        *(__nv_bfloat16*)(smraw + OBH + (i*264+d)*2) = hh;
        *(__nv_bfloat16*)(smraw + OBL + (i*264+d)*2) = ll;
    }
    __syncthreads();

    {
        const int mt = warp>>2, ntw = warp&3;
        float qk[4] = {0,0,0,0}, kk[4] = {0,0,0,0};
        const unsigned arow_off = (mt*16 + (lane&15))*528 + ((lane>>4)*8)*2;
        const unsigned brow_off = (ntw*8 + (lane&7))*528 + (((lane>>3)&1)*8)*2;
        #pragma unroll
        for (int kt = 0; kt < 16; ++kt) {
            const unsigned kb2 = kt*32;
            unsigned aq[4], aql[4], ak4[4], akl[4], b2h[2], b2l[2];
            ldsm4(aq,  smb + OQH + arow_off + kb2);
            ldsm4(aql, smb + OQL + arow_off + kb2);
            ldsm4(ak4, smb + OKH + arow_off + kb2);
            ldsm4(akl, smb + OKL + arow_off + kb2);
            ldsm2(b2h, smb + OKH + brow_off + kb2);
            ldsm2(b2l, smb + OKL + brow_off + kb2);
            mma16816(qk, aq, b2h);  mma16816(qk, aql, b2h); mma16816(qk, aq, b2l);
            mma16816(kk, ak4, b2h); mma16816(kk, akl, b2h); mma16816(kk, ak4, b2l);
        }
        const int i0 = mt*16 + g, j0 = ntw*8 + qp;
        #pragma unroll
        for (int r = 0; r < 4; ++r) {
            const int i = i0 + (r>>1)*8, j = j0 + (r&1);
            Amp[i*33+j] = (i > j) ? sbp[i]*kk[r] : 0.f;
            const float av = (i >= j) ? qk[r] : 0.f;
            __nv_bfloat16 hh, ll;
            split1(av, hh, ll);
            AH[cb1 + i*32 + j] = hh; AL[cb1 + i*32 + j] = ll;
        }
    }
    for (int e = tid; e < 8192; e += 256) {
        const int d = e >> 5, t = e & 31;
        unsigned short hv = *(unsigned short*)(smraw + OKH + (t*264+d)*2) ^ 0x8000u;
        unsigned short lv = *(unsigned short*)(smraw + OKL + (t*264+d)*2) ^ 0x8000u;
        KH[cb8+e] = *(__nv_bfloat16*)&hv;
        KL[cb8+e] = *(__nv_bfloat16*)&lv;
    }
    __syncthreads();

    if (tid < 32) {
        const int j = tid;
        Tip[j] = (j == 0) ? 1.f : 0.f;
        for (int i2 = 1; i2 < 32; ++i2) {
            __syncwarp();
            float s = 0.f;
            for (int m = 0; m < i2; ++m) s += Amp[i2*33+m]*Tip[m*33+j];
            Tip[i2*33+j] = ((i2 == j) ? 1.f : 0.f) - s;
        }
    }
    __syncthreads();
    for (int e = tid; e < 1024; e += 256) {
        const int i = e >> 5, j = e & 31;
        __nv_bfloat16 hh, ll;
        split1(Tip[i*33+j], hh, ll);
        *(__nv_bfloat16*)(smraw + OTH + (i*40+j)*2) = hh;
        *(__nv_bfloat16*)(smraw + OTL + (i*40+j)*2) = ll;
    }
    __syncthreads();

    {
        const int mt = warp>>2;
        unsigned TiH[2][4], TiL[2][4];
        #pragma unroll
        for (int kt = 0; kt < 2; ++kt) {
            const unsigned ao = (mt*16 + (lane&15))*80 + (kt*16 + (lane>>4)*8)*2;
            ldsm4(TiH[kt], smb + OTH + ao);
            ldsm4(TiL[kt], smb + OTL + ao);
        }
        const int i0 = mt*16 + g;
        #pragma unroll
        for (int ng = 0; ng < 4; ++ng) {
            const int n0 = (warp&3)*64 + ng*16;
            float aU[2][4], aW[2][4];
            #pragma unroll
            for (int t2 = 0; t2 < 2; ++t2)
                #pragma unroll
                for (int r = 0; r < 4; ++r) { aU[t2][r]=0.f; aW[t2][r]=0.f; }
            #pragma unroll
            for (int kt = 0; kt < 2; ++kt) {
                const unsigned brow = kt*16 + (lane&7) + ((lane>>3)&1)*8;
                const unsigned bcol = n0 + ((lane>>4)&1)*8;
                const unsigned bo = brow*528 + bcol*2;
                unsigned bvh[4], bvl[4], bbh[4], bbl[4];
                ldsm4t(bvh, smb + OVH + bo);
                ldsm4t(bvl, smb + OVL + bo);
                ldsm4t(bbh, smb + OBH + bo);
                ldsm4t(bbl, smb + OBL + bo);
                #pragma unroll
                for (int nt = 0; nt < 2; ++nt) {
                    mma16816(aU[nt], TiH[kt], bvh+2*nt);
                    mma16816(aU[nt], TiL[kt], bvh+2*nt);
                    mma16816(aU[nt], TiH[kt], bvl+2*nt);
                    mma16816(aW[nt], TiH[kt], bbh+2*nt);
                    mma16816(aW[nt], TiL[kt], bbh+2*nt);
                    mma16816(aW[nt], TiH[kt], bbl+2*nt);
                }
            }
            #pragma unroll
            for (int nt = 0; nt < 2; ++nt)
                #pragma unroll
                for (int r = 0; r < 4; ++r) {
                    const int i = i0 + (r>>1)*8;
                    const int d = n0 + nt*8 + qp + (r&1);
                    U[cb8 + i*256 + d] = aU[nt][r];
                    __nv_bfloat16 hh, ll;
                    split1(aW[nt][r], hh, ll);
                    WH[cb8 + i*256 + d] = hh;
                    WL[cb8 + i*256 + d] = ll;
                }
        }
    }
}

// ---------------- tensor-core delta scan ----------------
#define STGSZ  72704
#define OFF_KT 145408
#define OFF_UB 210944
#define SC_SMEM 227840

__global__ void __launch_bounds__(128) scan_mma(
    const __nv_bfloat16* __restrict__ QHp, const __nv_bfloat16* __restrict__ QLp,
    const __nv_bfloat16* __restrict__ WHp, const __nv_bfloat16* __restrict__ WLp,
    const __nv_bfloat16* __restrict__ KHp, const __nv_bfloat16* __restrict__ KLp,
    const __nv_bfloat16* __restrict__ AHp, const __nv_bfloat16* __restrict__ ALp,
    const float* __restrict__ Ug, float* __restrict__ Out)
{
    extern __shared__ char smraw[];
    const unsigned smb = (unsigned)__cvta_generic_to_shared(smraw);
    float* ub = (float*)(smraw + OFF_UB);
    const int tid = threadIdx.x, warp = tid>>5, lane = tid&31;
    const int bh = blockIdx.x>>4, cb = blockIdx.x&15;
    const int b = bh>>2, h = bh&3;
    const int g = lane>>2, qp = (lane&3)*2;
    const int brow16 = ((lane>>4)&1)*8 + (lane&7);
    const int bcol8 = ((lane>>3)&1)*8;

    float P[8][4];
    #pragma unroll
    for (int i=0;i<8;++i)
        #pragma unroll
        for (int r=0;r<4;++r) P[i][r]=0.f;

    auto issue = [&](int ci, int stg){
        const size_t b8 = (size_t)(bh*NCc + ci)*8192;
        const size_t b1 = (size_t)(bh*NCc + ci)*1024;
        const unsigned sb = smb + stg*STGSZ;
        const __nv_bfloat16* srcs[4] = {QHp+b8, QLp+b8, WHp+b8, WLp+b8};
        #pragma unroll
        for (int pl = 0; pl < 4; ++pl){
            const unsigned dsb = sb + pl*16384;
            for (int e = tid; e < 1024; e += 128){
                int row = e>>5, c = e&31;
                cpa16(dsb + row*512 + ((c^(row&7))<<4), srcs[pl] + row*256 + c*8);
            }
        }
        const unsigned kb2 = smb + OFF_KT + stg*32768;
        for (int e = tid; e < 1024; e += 128){
            int row = e>>2, c = e&3;
            cpa16(kb2 + row*64 + c*16, KHp + b8 + row*32 + c*8);
            cpa16(kb2 + 16384 + row*64 + c*16, KLp + b8 + row*32 + c*8);
        }
        {
            int row = tid>>2, c = tid&3;
            cpa16(sb + 65536 + row*80 + c*16, AHp + b1 + row*32 + c*8);
            cpa16(sb + 68096 + row*80 + c*16, ALp + b1 + row*32 + c*8);
            cpa16(sb + 70656 + row*64 + c*16, Ug + b8 + (size_t)row*256 + cb*16 + c*4);
        }
    };

    issue(0, 0); CP_COMMIT();

    for (int ci = 0; ci < NCc; ++ci) {
        const int stg = ci & 1;
        const unsigned sb = smb + stg*STGSZ;
        const unsigned kb = smb + OFF_KT + stg*32768;
        CP_WAIT0();
        __syncthreads();

        float accW[4][4], accQ[4][4];
        #pragma unroll
        for (int i=0;i<4;++i)
            #pragma unroll
            for (int r=0;r<4;++r){ accW[i][r]=0.f; accQ[i][r]=0.f; }
        #pragma unroll
        for (int kt = 0; kt < 4; ++kt) {
            unsigned Ah[4], Al[4];
            const float* p0 = P[2*kt]; const float* p1 = P[2*kt+1];
            Ah[0]=pack2(p0[0],p0[1]); Ah[1]=pack2(p0[2],p0[3]);
            Ah[2]=pack2(p1[0],p1[1]); Ah[3]=pack2(p1[2],p1[3]);
            Al[0]=pack2(res1(p0[0]),res1(p0[1])); Al[1]=pack2(res1(p0[2]),res1(p0[3]));
            Al[2]=pack2(res1(p1[0]),res1(p1[1])); Al[3]=pack2(res1(p1[2]),res1(p1[3]));
            const int dcol = warp*64 + kt*16 + bcol8;
            unsigned bwh[4][2], bwl[4][2], bqh[4][2], bql[4][2];
            #pragma unroll
            for (int ng = 0; ng < 2; ++ng) {
                const int row = ng*16 + brow16;
                const unsigned off = row*512 + ((((unsigned)(dcol>>3))^(row&7))<<4);
                unsigned r4[4];
                ldsm4(r4, sb + 32768 + off);
                bwh[2*ng][0]=r4[0]; bwh[2*ng][1]=r4[1]; bwh[2*ng+1][0]=r4[2]; bwh[2*ng+1][1]=r4[3];
                ldsm4(r4, sb + 49152 + off);
                bwl[2*ng][0]=r4[0]; bwl[2*ng][1]=r4[1]; bwl[2*ng+1][0]=r4[2]; bwl[2*ng+1][1]=r4[3];
                ldsm4(r4, sb + off);
                bqh[2*ng][0]=r4[0]; bqh[2*ng][1]=r4[1]; bqh[2*ng+1][0]=r4[2]; bqh[2*ng+1][1]=r4[3];
                ldsm4(r4, sb + 16384 + off);
                bql[2*ng][0]=r4[0]; bql[2*ng][1]=r4[1]; bql[2*ng+1][0]=r4[2]; bql[2*ng+1][1]=r4[3];
            }
            #pragma unroll
            for (int nt = 0; nt < 4; ++nt) {
                mma16816(accW[nt], Ah, bwh[nt]);
                mma16816(accW[nt], Al, bwh[nt]);
                mma16816(accW[nt], Ah, bwl[nt]);
                mma16816(accQ[nt], Ah, bqh[nt]);
                mma16816(accQ[nt], Al, bqh[nt]);
                mma16816(accQ[nt], Ah, bql[nt]);
            }
        }
        #pragma unroll
        for (int nt = 0; nt < 4; ++nt)
            #pragma unroll
            for (int r = 0; r < 4; ++r) {
                int c = g + ((r>>1)<<3), t = nt*8 + qp + (r&1);
                ub[(c*4+warp)*66 + t] = accW[nt][r];
                ub[(c*4+warp)*66 + 32 + t] = accQ[nt][r];
            }
        if (ci + 1 < NCc) { issue(ci+1, stg^1); CP_COMMIT(); }
        __syncthreads();

        const float* su = (const float*)(smraw + stg*STGSZ + 70656);
        unsigned UH[2][4], UL[2][4];
        #pragma unroll
        for (int kt = 0; kt < 2; ++kt) {
            float v[8];
            #pragma unroll
            for (int p = 0; p < 8; ++p) {
                const int c = g + (((p>>1)&1)<<3);
                const int t = kt*16 + qp + (p&1) + ((p>>2)<<3);
                const int bi = (c*4)*66 + t;
                v[p] = su[t*16 + c] + ub[bi] + ub[bi+66] + ub[bi+132] + ub[bi+198];
            }
            UH[kt][0]=pack2(v[0],v[1]); UH[kt][1]=pack2(v[2],v[3]);
            UH[kt][2]=pack2(v[4],v[5]); UH[kt][3]=pack2(v[6],v[7]);
            UL[kt][0]=pack2(res1(v[0]),res1(v[1])); UL[kt][1]=pack2(res1(v[2]),res1(v[3]));
            UL[kt][2]=pack2(res1(v[4]),res1(v[5])); UL[kt][3]=pack2(res1(v[6]),res1(v[7]));
        }
        float oc[4];
        const int i0 = warp*8 + qp;
        #pragma unroll
        for (int r = 0; r < 4; ++r) {
            const int c = g + ((r>>1)<<3);
            const int bi = (c*4)*66 + 32 + i0 + (r&1);
            oc[r] = -(ub[bi] + ub[bi+66] + ub[bi+132] + ub[bi+198]);
        }

        #pragma unroll
        for (int kt = 0; kt < 2; ++kt) {
            unsigned bh2[2], bl2[2];
            const unsigned aoff = (warp*8 + (lane&7))*80 + (kt*16 + bcol8)*2;
            ldsm2(bh2, sb + 65536 + aoff);
            ldsm2(bl2, sb + 68096 + aoff);
            mma16816(oc, UH[kt], bh2);
            mma16816(oc, UL[kt], bh2);
            mma16816(oc, UH[kt], bl2);
        }
        {
            const size_t base = ((size_t)(b*Ll + ci*CSs + i0))*HD + h*256 + cb*16;
            Out[base + g]          = oc[0];
            Out[base + HD + g]     = oc[1];
            Out[base + g + 8]      = oc[2];
            Out[base + HD + g + 8] = oc[3];
        }

        #pragma unroll
        for (int kt = 0; kt < 2; ++kt) {
            #pragma unroll
            for (int np = 0; np < 4; ++np) {
                unsigned bh4[4], bl4[4];
                const unsigned off = (warp*64 + np*16 + brow16)*64 + (kt*16 + bcol8)*2;
                ldsm4(bh4, kb + off);
                ldsm4(bl4, kb + 16384 + off);
                mma16816(P[2*np],   UH[kt], bh4);
                mma16816(P[2*np],   UL[kt], bh4);
                mma16816(P[2*np],   UH[kt], bl4);
                mma16816(P[2*np+1], UH[kt], bh4+2);
                mma16816(P[2*np+1], UL[kt], bh4+2);
                mma16816(P[2*np+1], UH[kt], bl4+2);
            }
        }
    }
}

// ---------------- FIR short/long + gate_in, 16 rows/block ----------
__global__ void __launch_bounds__(256) fir_gatein_kernel(
                                  const unsigned* __restrict__ hsHu, const unsigned* __restrict__ hsLu,
                                  const float* __restrict__ V,
                                  const float* __restrict__ ws, const float* __restrict__ wl,
                                  const float* __restrict__ Dl,
                                  float* __restrict__ Sout, float* __restrict__ Lout,
                                  __nv_bfloat16* __restrict__ GinH, __nv_bfloat16* __restrict__ GinL)
{
    const int blk = blockIdx.x;
    const int b = blk / (Ll/16);
    const int l0 = (blk % (Ll/16)) * 16;
    const int tid = threadIdx.x;
    float smean[16], lmean[16], dmean[16];
    #pragma unroll
    for (int r = 0; r < 16; ++r) { smean[r]=0.f; lmean[r]=0.f; dmean[r]=0.f; }
    for (int j = 0; j < 4; ++j) {
        const int ch = tid + 256*j;
        float win[46];
        #pragma unroll
        for (int t = 0; t < 46; ++t) {
            const int l = l0 - 30 + t;
            win[t] = (l >= 0) ? V[((size_t)(b*Ll + l))*HD + ch] : 0.f;
        }
        float wlr[31];
        #pragma unroll
        for (int t = 0; t < 31; ++t) wlr[t] = wl[ch*31 + t];
        const float w0 = ws[ch*3+0], w1 = ws[ch*3+1], w2 = ws[ch*3+2];
        #pragma unroll
        for (int r = 0; r < 16; ++r) {
            float yl = 0.f;
            #pragma unroll
            for (int t = 0; t < 31; ++t) yl += win[r+t]*wlr[t];
            const float ysv = win[r+28]*w0 + win[r+29]*w1 + win[r+30]*w2;
            const size_t row = (size_t)(b*Ll + l0 + r);
            Sout[row*HD + ch] = ysv;
            Lout[row*HD + ch] = yl;
            smean[r] += ysv; lmean[r] += yl;
            dmean[r] += Dl[row*HD + ch];
        }
    }
    for (int r = 0; r < 16; ++r) {
        const size_t row = (size_t)(b*Ll + l0 + r);
        __nv_bfloat16* gH = GinH + row*GIN;
        __nv_bfloat16* gL = GinL + row*GIN;
        #pragma unroll
        for (int j = 0; j < 2; ++j) {
            const int e = tid + 256*j;
            ((unsigned*)gH)[e] = hsHu[row*512 + e];
            ((unsigned*)gL)[e] = hsLu[row*512 + e];
        }
        __nv_bfloat16 hh, ll;
        split1(smean[r]*0.25f, hh, ll);
        gH[1024 + tid] = hh; gL[1024 + tid] = ll;
        split1(lmean[r]*0.25f, hh, ll);
        gH[1280 + tid] = hh; gL[1280 + tid] = ll;
        split1(dmean[r]*0.25f, hh, ll);
        gH[1536 + tid] = hh; gL[1536 + tid] = ll;
    }
}

// ---------------- gate head 2 ----------------
__global__ void gate2_wgt(const float* __restrict__ GH2, const float* __restrict__ W2,
                          const float* __restrict__ b2, const float* __restrict__ ltemp,
                          float* __restrict__ Wgt)
{
    const int row = blockIdx.x;
    const int warp = threadIdx.x >> 5, lane = threadIdx.x & 31;
    __shared__ float lg[4];
    const float* x = GH2 + (size_t)row*GHID;
    const float* w = W2 + warp*GHID;
    float s = 0.f;
    for (int i = lane; i < GHID; i += 32) s += x[i]*w[i];
    #pragma unroll
    for (int o = 16; o; o >>= 1) s += __shfl_xor_sync(0xffffffff, s, o);
    if (lane == 0) lg[warp] = s + b2[warp];
    __syncthreads();
    if (threadIdx.x == 0) {
        const float t = log1pf(expf(ltemp[0])) + 1e-4f;
        float m = fmaxf(fmaxf(lg[0], lg[1]), fmaxf(lg[2], lg[3]));
        float e[4]; float se = 0.f;
        #pragma unroll
        for (int j = 0; j < 4; ++j) { e[j] = expf((lg[j]-m)/t); se += e[j]; }
        #pragma unroll
        for (int j = 0; j < 4; ++j) e[j] /= se;
        const float fl = 0.05f * e[3];
        e[0] = fmaxf(e[0], fl);
        e[1] = fmaxf(e[1], fl);
        const float s2 = e[0]+e[1]+e[2]+e[3];
        #pragma unroll
        for (int j = 0; j < 4; ++j) Wgt[row*4+j] = e[j]/s2;
    }
}

// ---------------- combine + RMSNorm (writes bf16 hi/lo directly) ----------------
__global__ void combine_kernel(const float* __restrict__ Sh, const float* __restrict__ Lg,
                               const float* __restrict__ Dl, const float* __restrict__ V,
                               const float* __restrict__ Wgt, const float* __restrict__ onw,
                               __nv_bfloat16* __restrict__ OH, __nv_bfloat16* __restrict__ OL)
{
    const int row = blockIdx.x;
    const int tid = threadIdx.x, lane = tid & 31;
    __shared__ float red[4];
    if (tid < 4) red[tid] = 0.f;
    __syncthreads();
    const float w0 = Wgt[row*4+0], w1 = Wgt[row*4+1], w2 = Wgt[row*4+2], w3 = Wgt[row*4+3];
    float ov[4];
    #pragma unroll
    for (int j = 0; j < 4; ++j) {
        const size_t g = (size_t)row*HD + tid + 256*j;
        ov[j] = w0*Sh[g] + w1*Lg[g] + w2*Dl[g] + w3*V[g];
        float v = ov[j]*ov[j];
        #pragma unroll
        for (int o = 16; o; o >>= 1) v += __shfl_xor_sync(0xffffffff, v, o);
        if (lane == 0) atomicAdd(&red[j], v);
    }
    __syncthreads();
    #pragma unroll
    for (int j = 0; j < 4; ++j) {
        const float sc = rsqrtf(red[j]*(1.f/256.f) + 1e-5f) * onw[tid];
        __nv_bfloat16 hh, ll;
        split1(ov[j]*sc, hh, ll);
        OH[(size_t)row*HD + tid + 256*j] = hh;
        OL[(size_t)row*HD + tid + 256*j] = ll;
    }
}

// ---------------- launch ----------------
extern "C" void kernel_launch(void* const* d_in, const int* in_sizes, int n_in,
                              void* d_out, int out_size)
{
    const float* hs  = (const float*)d_in[0];
    const float* qw  = (const float*)d_in[1];
    const float* kw  = (const float*)d_in[2];
    const float* vw  = (const float*)d_in[3];
    const float* bw  = (const float*)d_in[4];
    const float* qcw = (const float*)d_in[5];
    const float* kcw = (const float*)d_in[6];
    const float* vcw = (const float*)d_in[7];
    const float* fsw = (const float*)d_in[8];
    const float* flw = (const float*)d_in[9];
    const float* w1  = (const float*)d_in[10];
    const float* b1  = (const float*)d_in[11];
    const float* w2  = (const float*)d_in[12];
    const float* b2  = (const float*)d_in[13];
    const float* lt  = (const float*)d_in[14];
    const float* onw = (const float*)d_in[15];
    const float* ow  = (const float*)d_in[16];
    float* out = (float*)d_out;

    float *xqkv,*q,*k,*v,*u,*delta,*shrt,*lng,*gh,*beta,*wgt;
    __nv_bfloat16 *hsH,*hsL,*ginH,*ginL,*ocH,*ocL,*wtH,*wtL;
    __nv_bfloat16 *qh,*ql,*wh,*wlp,*kh,*kl,*ah,*al;
    cudaGetSymbolAddress((void**)&xqkv, g_xqkv);
    cudaGetSymbolAddress((void**)&q,    g_q);
    cudaGetSymbolAddress((void**)&k,    g_k);
    cudaGetSymbolAddress((void**)&v,    g_v);
    cudaGetSymbolAddress((void**)&u,    g_u);
    cudaGetSymbolAddress((void**)&delta,g_delta);
    cudaGetSymbolAddress((void**)&shrt, g_short);
    cudaGetSymbolAddress((void**)&lng,  g_long);
    cudaGetSymbolAddress((void**)&gh,   g_gh);
    cudaGetSymbolAddress((void**)&beta, g_beta);
    cudaGetSymbolAddress((void**)&wgt,  g_wgt);
    cudaGetSymbolAddress((void**)&hsH,  g_hsH);
    cudaGetSymbolAddress((void**)&hsL,  g_hsL);
    cudaGetSymbolAddress((void**)&ginH, g_ginH);
    cudaGetSymbolAddress((void**)&ginL, g_ginL);
    cudaGetSymbolAddress((void**)&ocH,  g_ocH);
    cudaGetSymbolAddress((void**)&ocL,  g_ocL);
    cudaGetSymbolAddress((void**)&wtH,  g_wtH);
    cudaGetSymbolAddress((void**)&wtL,  g_wtL);
    cudaGetSymbolAddress((void**)&qh,   g_qh);
    cudaGetSymbolAddress((void**)&ql,   g_ql);
    cudaGetSymbolAddress((void**)&wh,   g_wh);
    cudaGetSymbolAddress((void**)&wlp,  g_wl);
    cudaGetSymbolAddress((void**)&kh,   g_kh);
    cudaGetSymbolAddress((void**)&kl,   g_kl);
    cudaGetSymbolAddress((void**)&ah,   g_ah);
    cudaGetSymbolAddress((void**)&al,   g_al);

    cudaFuncSetAttribute(precompute_kernel, cudaFuncAttributeMaxDynamicSharedMemorySize, PRE_SMEM);
    cudaFuncSetAttribute(scan_mma, cudaFuncAttributeMaxDynamicSharedMemorySize, SC_SMEM);
    cudaFuncSetAttribute(hgemm_nt<false>, cudaFuncAttributeMaxDynamicSharedMemorySize, G2_SMEM);
    cudaFuncSetAttribute(hgemm_nt<true>,  cudaFuncAttributeMaxDynamicSharedMemorySize, G2_SMEM);
    cudaFuncSetAttribute(conv_silu_norm,  cudaFuncAttributeMaxDynamicSharedMemorySize, CV_SMEM);

    {
        int n4 = (BL*Dd) >> 2;
        split_kernel<<<(n4 + 255)/256, 256>>>((const float4*)hs, (uint2*)hsH, (uint2*)hsL, n4);
    }
    wsplit_kernel<<<(W4_O + 255)/256, 256>>>((const float4*)qw, (const float4*)kw,
                                             (const float4*)vw, (const float4*)w1,
                                             (const float4*)ow, (uint2*)wtH, (uint2*)wtL);

    hgemm_nt<false><<<dim3(3072/256, BL/128), 512, G2_SMEM>>>(
        hsH, hsL, wtH+WOFF_Q, wtL+WOFF_Q, xqkv, BL, 3072, Dd, nullptr);
    beta_kernel<<<BL, 128>>>(hs, bw, beta);
    conv_silu_norm<<<BL/8, 256, CV_SMEM>>>(xqkv, qcw, kcw, vcw, q, k, v);
    precompute_kernel<<<8*NCc, 256, PRE_SMEM>>>(q, k, v, beta, u,
                                                qh, ql, wh, wlp, kh, kl, ah, al);
    scan_mma<<<128, 128, SC_SMEM>>>(qh, ql, wh, wlp, kh, kl, ah, al, u, delta);
    fir_gatein_kernel<<<Bb*(Ll/16), 256>>>((const unsigned*)hsH, (const unsigned*)hsL,
                                           v, fsw, flw, delta, shrt, lng, ginH, ginL);
    hgemm_nt<true><<<dim3(GHID/256, BL/128), 512, G2_SMEM>>>(
        ginH, ginL, wtH+WOFF_W1, wtL+WOFF_W1, gh, BL, GHID, GIN, b1);
    gate2_wgt<<<BL, 128>>>(gh, w2, b2, lt, wgt);
    combine_kernel<<<BL, 256>>>(shrt, lng, delta, v, wgt, onw, ocH, ocL);
    hgemm_nt<false><<<dim3(Dd/256, BL/128), 512, G2_SMEM>>>(
        ocH, ocL, wtH+WOFF_O, wtL+WOFF_O, out, BL, Dd, HD, nullptr);
}